// round 1
// baseline (speedup 1.0000x reference)
#include <cuda_runtime.h>
#include <math.h>

#define E_CONST 320000
#define N_CONST 10000

// ---------------- scratch (no allocations allowed) ----------------
static __device__ float    g_vff [(size_t)E_CONST * 64];   // [sin_cos(48) | raw dist(16)]
static __device__ float    g_hE  [(size_t)E_CONST * 256];
static __device__ float    g_bufA[(size_t)E_CONST * 128];
static __device__ float    g_bufB[(size_t)E_CONST * 128];
static __device__ float    g_logit[(size_t)E_CONST * 4];   // logits, then exp()
static __device__ unsigned g_max [N_CONST * 4];
static __device__ float    g_sum [N_CONST * 4];
static __device__ float    g_hagg[N_CONST * 128];
static __device__ double   g_bnacc[32];                    // [sum(16) | sumsq(16)]
static __device__ float    g_bnst[32];                     // [scale(16) | shift(16)]

// monotonic float<->uint encoding for atomicMax on signed floats
__device__ __forceinline__ unsigned fenc(float f) {
    unsigned u = __float_as_uint(f);
    return (u & 0x80000000u) ? ~u : (u | 0x80000000u);
}
__device__ __forceinline__ float fdec(unsigned u) {
    return (u & 0x80000000u) ? __uint_as_float(u & 0x7FFFFFFFu) : __uint_as_float(~u);
}

// ---------------- init ----------------
__global__ void init_kernel(unsigned* gmax, float* gsum, float* hagg, double* bnacc, int N)
{
    int i = blockIdx.x * 256 + threadIdx.x;
    if (i < N * 128) hagg[i] = 0.f;
    if (i < N * 4) { gmax[i] = 0x007FFFFFu; /* enc(-inf) */ gsum[i] = 0.f; }
    if (i < 32) bnacc[i] = 0.0;
}

// ---------------- geometry + BN statistics ----------------
__global__ __launch_bounds__(256)
void geom_kernel(const int* __restrict__ eidx, const float* __restrict__ hvv,
                 const float* __restrict__ frame, const float* __restrict__ Wvec,
                 float* __restrict__ vff, double* __restrict__ bnacc, int E)
{
    __shared__ float Ws[512];
    __shared__ float bsum[16], bsq[16];
    int tid = threadIdx.x;
    for (int i = tid; i < 512; i += 256) Ws[i] = Wvec[i];
    if (tid < 16) { bsum[tid] = 0.f; bsq[tid] = 0.f; }
    __syncthreads();

    int e = blockIdx.x * 256 + tid;
    float dloc[16];
#pragma unroll
    for (int o = 0; o < 16; o++) dloc[o] = 0.f;

    if (e < E) {
        int c = eidx[e];
        int d = eidx[E + e];
        float F[9];
#pragma unroll
        for (int i = 0; i < 9; i++) F[i] = frame[e * 9 + i];
        float vdt[48], vsrc[48];
#pragma unroll
        for (int v = 0; v < 16; v++) {
            float x = hvv[d * 48 + v * 3 + 0];
            float y = hvv[d * 48 + v * 3 + 1];
            float z = hvv[d * 48 + v * 3 + 2];
            vdt[v * 3 + 0] = F[0] * x + F[1] * y + F[2] * z;
            vdt[v * 3 + 1] = F[3] * x + F[4] * y + F[5] * z;
            vdt[v * 3 + 2] = F[6] * x + F[7] * y + F[8] * z;
        }
#pragma unroll
        for (int i = 0; i < 48; i++) vsrc[i] = hvv[c * 48 + i];

#pragma unroll
        for (int o = 0; o < 16; o++) {
            float v0 = vdt[o * 3 + 0], v1 = vdt[o * 3 + 1], v2 = vdt[o * 3 + 2];
#pragma unroll
            for (int v = 0; v < 16; v++) {
                float wa = Ws[o * 32 + v], wb = Ws[o * 32 + 16 + v];
                v0 += wa * vdt[v * 3 + 0] + wb * vsrc[v * 3 + 0];
                v1 += wa * vdt[v * 3 + 1] + wb * vsrc[v * 3 + 1];
                v2 += wa * vdt[v * 3 + 2] + wb * vsrc[v * 3 + 2];
            }
            float dist = sqrtf(v0 * v0 + v1 * v1 + v2 * v2) + 1e-6f;
            float inv = 1.f / dist;
            vff[e * 64 + o * 3 + 0] = v0 * inv;
            vff[e * 64 + o * 3 + 1] = v1 * inv;
            vff[e * 64 + o * 3 + 2] = v2 * inv;
            vff[e * 64 + 48 + o] = dist;   // raw dist; BN affine applied in GEMM A-loader
            dloc[o] = dist;
        }
    }

    // per-channel warp reduce -> shared -> one double atomic per channel per block
#pragma unroll
    for (int o = 0; o < 16; o++) {
        float v = dloc[o], v2 = v * v;
#pragma unroll
        for (int off = 16; off; off >>= 1) {
            v  += __shfl_down_sync(0xffffffffu, v, off);
            v2 += __shfl_down_sync(0xffffffffu, v2, off);
        }
        if ((tid & 31) == 0) { atomicAdd(&bsum[o], v); atomicAdd(&bsq[o], v2); }
    }
    __syncthreads();
    if (tid < 16) {
        atomicAdd(&bnacc[tid], (double)bsum[tid]);
        atomicAdd(&bnacc[16 + tid], (double)bsq[tid]);
    }
}

__global__ void bn_finalize(const double* __restrict__ acc, const float* __restrict__ g,
                            const float* __restrict__ b, float* __restrict__ st, int E)
{
    int i = threadIdx.x;
    if (i >= 16) return;
    double mean = acc[i] / (double)E;
    double var  = acc[16 + i] / (double)E - mean * mean;
    float s = (float)((double)g[i] / sqrt(var + 1e-5));
    st[i] = s;
    st[16 + i] = b[i] - (float)mean * s;
}

// ---------------- generic tiled SGEMM with fused A-builders & activations ----------------
// MODE 0: A = A0 [M,K] plain
// MODE 1: A = [ vff(48 sin_cos | 16 dist*bn_s+bn_t) | A1 = h_E(256) ], K=320
// MODE 2: A = [ A0[gidx[row]] (128) | A1 = hE(256) ], K=384
// ACT: 0 none, 1 relu, 2 exact gelu
template<int MODE, int ACT>
__global__ __launch_bounds__(256)
void gemm_kernel(const float* __restrict__ A0, const float* __restrict__ A1,
                 const int* __restrict__ gidx, const float* __restrict__ B,
                 const float* __restrict__ bias, const float* __restrict__ bn_st,
                 float* __restrict__ C, int M, int Nt, int K)
{
    __shared__ float As[8][128];
    __shared__ float Bs[8][128];
    const int tid = threadIdx.x;
    const int row0 = blockIdx.y * 128;
    const int col0 = blockIdx.x * 128;
    const int ty = tid >> 4, tx = tid & 15;

    float acc[8][8];
#pragma unroll
    for (int i = 0; i < 8; i++)
#pragma unroll
        for (int j = 0; j < 8; j++) acc[i][j] = 0.f;

    for (int k0 = 0; k0 < K; k0 += 8) {
#pragma unroll
        for (int l = 0; l < 4; l++) {
            int idx = tid + l * 256;
            int m = idx >> 3, kk = idx & 7;
            int row = row0 + m, k = k0 + kk;
            float a = 0.f;
            if (row < M) {
                if (MODE == 0) {
                    a = A0[row * K + k];
                } else if (MODE == 1) {
                    if (k < 64) {
                        a = A0[row * 64 + k];
                        if (k >= 48) a = fmaf(a, bn_st[k - 48], bn_st[k - 32]);
                    } else {
                        a = A1[row * 256 + (k - 64)];
                    }
                } else {
                    if (k < 128) a = A0[gidx[row] * 128 + k];
                    else         a = A1[row * 256 + (k - 128)];
                }
            }
            As[kk][m] = a;
        }
#pragma unroll
        for (int l = 0; l < 4; l++) {
            int idx = tid + l * 256;
            int kk = idx >> 7, n = idx & 127;
            Bs[kk][n] = B[(k0 + kk) * Nt + col0 + n];
        }
        __syncthreads();
#pragma unroll
        for (int kk = 0; kk < 8; kk++) {
            float4 a0 = *(const float4*)&As[kk][ty * 8];
            float4 a1 = *(const float4*)&As[kk][ty * 8 + 4];
            float4 b0 = *(const float4*)&Bs[kk][tx * 8];
            float4 b1 = *(const float4*)&Bs[kk][tx * 8 + 4];
            float ra[8] = {a0.x, a0.y, a0.z, a0.w, a1.x, a1.y, a1.z, a1.w};
            float rb[8] = {b0.x, b0.y, b0.z, b0.w, b1.x, b1.y, b1.z, b1.w};
#pragma unroll
            for (int i = 0; i < 8; i++)
#pragma unroll
                for (int j = 0; j < 8; j++)
                    acc[i][j] = fmaf(ra[i], rb[j], acc[i][j]);
        }
        __syncthreads();
    }

#pragma unroll
    for (int i = 0; i < 8; i++) {
        int row = row0 + ty * 8 + i;
        if (row >= M) continue;
#pragma unroll
        for (int j = 0; j < 8; j++) {
            int col = col0 + tx * 8 + j;
            float c = acc[i][j];
            if (bias) c += bias[col];
            if (ACT == 1) c = fmaxf(c, 0.f);
            if (ACT == 2) c = 0.5f * c * (1.f + erff(c * 0.70710678118654752f));
            C[row * Nt + col] = c;
        }
    }
}

// ---------------- logits (only 4 needed heads) + segment max ----------------
__global__ __launch_bounds__(256)
void logits_kernel(const float* __restrict__ x2, const float* __restrict__ Wb3,
                   const float* __restrict__ bb3, const int* __restrict__ center,
                   float* __restrict__ logit, unsigned* __restrict__ gmax, int E)
{
    int gtid = blockIdx.x * 256 + threadIdx.x;
    int e = gtid >> 5;
    int lane = gtid & 31;
    if (e >= E) return;
    const float* xr = x2 + e * 128;
    float p0 = 0.f, p1 = 0.f, p2 = 0.f, p3 = 0.f;
#pragma unroll
    for (int kk = 0; kk < 4; kk++) {
        int k = lane + kk * 32;
        float x = xr[k];
        p0 += x * Wb3[k * 8 + 0];
        p1 += x * Wb3[k * 8 + 1];
        p2 += x * Wb3[k * 8 + 2];
        p3 += x * Wb3[k * 8 + 3];
    }
#pragma unroll
    for (int off = 16; off; off >>= 1) {
        p0 += __shfl_xor_sync(0xffffffffu, p0, off);
        p1 += __shfl_xor_sync(0xffffffffu, p1, off);
        p2 += __shfl_xor_sync(0xffffffffu, p2, off);
        p3 += __shfl_xor_sync(0xffffffffu, p3, off);
    }
    if (lane < 4) {
        float p = (lane == 0) ? p0 : (lane == 1) ? p1 : (lane == 2) ? p2 : p3;
        float l = (p + bb3[lane]) * 0.17677669529663687f;  // 1/sqrt(32)
        logit[e * 4 + lane] = l;
        atomicMax(&gmax[center[e] * 4 + lane], fenc(l));
    }
}

// ---------------- exp + segment sum ----------------
__global__ void expsum_kernel(float* __restrict__ logit, const int* __restrict__ center,
                              const unsigned* __restrict__ gmax, float* __restrict__ gsum, int E)
{
    int idx = blockIdx.x * 256 + threadIdx.x;
    if (idx >= E * 4) return;
    int e = idx >> 2, h = idx & 3;
    int c = center[e];
    float m = fdec(gmax[c * 4 + h]);
    float ex = expf(logit[idx] - m);
    logit[idx] = ex;
    atomicAdd(&gsum[c * 4 + h], ex);
}

// ---------------- weighted segment aggregation ----------------
__global__ void agg_kernel(const float* __restrict__ gexp, const float* __restrict__ gsum,
                           const float* __restrict__ V, const int* __restrict__ center,
                           float* __restrict__ hagg, int E)
{
    int idx = blockIdx.x * 256 + threadIdx.x;
    if (idx >= E * 128) return;
    int e = idx >> 7, t = idx & 127, h = t >> 5;
    int c = center[e];
    float att = gexp[e * 4 + h] / gsum[c * 4 + h];
    atomicAdd(&hagg[c * 128 + t], att * V[idx]);
}

// ---------------- host launch ----------------
extern "C" void kernel_launch(void* const* d_in, const int* in_sizes, int n_in,
                              void* d_out, int out_size)
{
    const float* h_V   = (const float*)d_in[0];
    const float* h_E   = (const float*)d_in[1];
    const int*   eidx  = (const int*)  d_in[2];
    const float* hvv   = (const float*)d_in[3];
    const float* frame = (const float*)d_in[4];
    const float* W_vec = (const float*)d_in[5];
    const float* W_red = (const float*)d_in[6];
    const float* Wb1   = (const float*)d_in[7];
    const float* bb1   = (const float*)d_in[8];
    const float* Wb2   = (const float*)d_in[9];
    const float* bb2   = (const float*)d_in[10];
    const float* Wb3   = (const float*)d_in[11];
    const float* bb3   = (const float*)d_in[12];
    const float* Wv1   = (const float*)d_in[13];
    const float* bv1   = (const float*)d_in[14];
    const float* Wv2   = (const float*)d_in[15];
    const float* bv2   = (const float*)d_in[16];
    const float* Wv3   = (const float*)d_in[17];
    const float* bv3   = (const float*)d_in[18];
    const float* W_O   = (const float*)d_in[19];
    const float* bn_g  = (const float*)d_in[20];
    const float* bn_b  = (const float*)d_in[21];

    int E = in_sizes[2] / 2;
    int N = in_sizes[0] / 128;
    float* out = (float*)d_out;

    float *vff, *hE, *bufA, *bufB, *logit, *gsum, *hagg, *bnst;
    unsigned* gmax;
    double* bnacc;
    cudaGetSymbolAddress((void**)&vff,   g_vff);
    cudaGetSymbolAddress((void**)&hE,    g_hE);
    cudaGetSymbolAddress((void**)&bufA,  g_bufA);
    cudaGetSymbolAddress((void**)&bufB,  g_bufB);
    cudaGetSymbolAddress((void**)&logit, g_logit);
    cudaGetSymbolAddress((void**)&gmax,  g_max);
    cudaGetSymbolAddress((void**)&gsum,  g_sum);
    cudaGetSymbolAddress((void**)&hagg,  g_hagg);
    cudaGetSymbolAddress((void**)&bnacc, g_bnacc);
    cudaGetSymbolAddress((void**)&bnst,  g_bnst);

    dim3 thr(256);
    int My = (E + 127) / 128;

    init_kernel<<<(N * 128 + 255) / 256, 256>>>(gmax, gsum, hagg, bnacc, N);
    geom_kernel<<<(E + 255) / 256, 256>>>(eidx, hvv, frame, W_vec, vff, bnacc, E);
    bn_finalize<<<1, 32>>>(bnacc, bn_g, bn_b, bnst, E);

    // hE = [vff_bn | h_E] @ W_red
    gemm_kernel<1, 0><<<dim3(2, My), thr>>>(vff, h_E, nullptr, W_red, nullptr, bnst, hE, E, 256, 320);
    // x1 = relu([h_V[center] | hE] @ Wb1 + bb1)
    gemm_kernel<2, 1><<<dim3(1, My), thr>>>(h_V, hE, eidx, Wb1, bb1, nullptr, bufA, E, 128, 384);
    // x2 = relu(x1 @ Wb2 + bb2)
    gemm_kernel<0, 1><<<dim3(1, My), thr>>>(bufA, nullptr, nullptr, Wb2, bb2, nullptr, bufB, E, 128, 128);
    // logits (4 heads) + segment max
    logits_kernel<<<(E * 32 + 255) / 256, 256>>>(bufB, Wb3, bb3, eidx, logit, gmax, E);
    // v1 = gelu(hE @ Wv1 + bv1)   (bufA: x1 dead)
    gemm_kernel<0, 2><<<dim3(1, My), thr>>>(hE, nullptr, nullptr, Wv1, bv1, nullptr, bufA, E, 128, 256);
    // exp + segment sum
    expsum_kernel<<<(E * 4 + 255) / 256, 256>>>(logit, eidx, gmax, gsum, E);
    // v2 = gelu(v1 @ Wv2 + bv2)   (bufB: x2 dead after logits)
    gemm_kernel<0, 2><<<dim3(1, My), thr>>>(bufA, nullptr, nullptr, Wv2, bv2, nullptr, bufB, E, 128, 128);
    // V = v2 @ Wv3 + bv3          (bufA: v1 dead)
    gemm_kernel<0, 0><<<dim3(1, My), thr>>>(bufB, nullptr, nullptr, Wv3, bv3, nullptr, bufA, E, 128, 128);
    // h_agg = segment_sum(att * V)
    agg_kernel<<<(E * 128 + 255) / 256, 256>>>(logit, gsum, bufA, eidx, hagg, E);
    // out = h_agg @ W_O
    gemm_kernel<0, 0><<<dim3(1, (N + 127) / 128), thr>>>(hagg, nullptr, nullptr, W_O, nullptr, nullptr, out, N, 128, 128);
}

// round 3
// speedup vs baseline: 2.1623x; 2.1623x over previous
#include <cuda_runtime.h>
#include <cuda_bf16.h>
#include <math.h>
#include <stdint.h>

#define E_CONST 320000
#define N_CONST 10000
typedef __nv_bfloat16 bf16;

// ---------------- scratch (no allocations allowed) ----------------
static __device__ float    g_vff [(size_t)E_CONST * 64];       // fp32 [sincos48|dist16]
static __device__ bf16     g_vffh[(size_t)E_CONST * 64];
static __device__ bf16     g_vffl[(size_t)E_CONST * 64];
static __device__ bf16     g_hEh [(size_t)E_CONST * 256];      // input h_E planes
static __device__ bf16     g_hEl [(size_t)E_CONST * 256];
static __device__ bf16     g_eh  [(size_t)E_CONST * 256];      // hE (W_red out) planes
static __device__ bf16     g_el  [(size_t)E_CONST * 256];
static __device__ bf16     g_pAh [(size_t)E_CONST * 128];      // x1 then v1
static __device__ bf16     g_pAl [(size_t)E_CONST * 128];
static __device__ bf16     g_pBh [(size_t)E_CONST * 128];      // v2
static __device__ bf16     g_pBl [(size_t)E_CONST * 128];
static __device__ float    g_f32 [(size_t)E_CONST * 128];      // x2 then V
static __device__ bf16     g_hVh [N_CONST * 128];
static __device__ bf16     g_hVl [N_CONST * 128];
static __device__ bf16     g_hgh [N_CONST * 128];
static __device__ bf16     g_hgl [N_CONST * 128];
static __device__ bf16     g_wh  [262144];                     // all weights, [n][k]
static __device__ bf16     g_wl  [262144];
static __device__ float    g_logit[(size_t)E_CONST * 4];
static __device__ unsigned g_max [N_CONST * 4];
static __device__ float    g_sum [N_CONST * 4];
static __device__ float    g_hagg[N_CONST * 128];
static __device__ double   g_bnacc[32];
static __device__ float    g_bnst[32];

// weight plane offsets (elements)
#define OW_RED 0        // 256 x 320
#define OW_B1  81920    // 128 x 384
#define OW_B2  131072   // 128 x 128
#define OW_V1  147456   // 128 x 256
#define OW_V2  180224   // 128 x 128
#define OW_V3  196608   // 128 x 128
#define OW_O   212992   // 128 x 128

// ---------------- helpers ----------------
__device__ __forceinline__ uint32_t smem_u32(const void* p) {
    uint32_t a;
    asm("{ .reg .u64 t; cvta.to.shared.u64 t, %1; cvt.u32.u64 %0, t; }" : "=r"(a) : "l"(p));
    return a;
}
__device__ __forceinline__ void cp16(uint32_t dst, const void* src) {
    asm volatile("cp.async.cg.shared.global [%0], [%1], 16;"
        :: "r"(dst), "l"(__cvta_generic_to_global(src)) : "memory");
}
#define CP_COMMIT() asm volatile("cp.async.commit_group;" ::: "memory")
#define CP_WAIT(n)  asm volatile("cp.async.wait_group %0;" :: "n"(n) : "memory")

__device__ __forceinline__ void ldsm4(uint32_t* r, uint32_t addr) {
    asm volatile("ldmatrix.sync.aligned.m8n8.x4.shared.b16 {%0,%1,%2,%3}, [%4];"
        : "=r"(r[0]), "=r"(r[1]), "=r"(r[2]), "=r"(r[3]) : "r"(addr));
}
__device__ __forceinline__ void mma16816(float* d, const uint32_t* a, const uint32_t* b) {
    asm volatile(
        "mma.sync.aligned.m16n8k16.row.col.f32.bf16.bf16.f32 "
        "{%0,%1,%2,%3}, {%4,%5,%6,%7}, {%8,%9}, {%0,%1,%2,%3};"
        : "+f"(d[0]), "+f"(d[1]), "+f"(d[2]), "+f"(d[3])
        : "r"(a[0]), "r"(a[1]), "r"(a[2]), "r"(a[3]), "r"(b[0]), "r"(b[1]));
}
__device__ __forceinline__ unsigned fenc(float f) {
    unsigned u = __float_as_uint(f);
    return (u & 0x80000000u) ? ~u : (u | 0x80000000u);
}
__device__ __forceinline__ float fdec(unsigned u) {
    return (u & 0x80000000u) ? __uint_as_float(u & 0x7FFFFFFFu) : __uint_as_float(~u);
}

// ---------------- init ----------------
__global__ void init_kernel(unsigned* gmax, float* gsum, float* hagg, double* bnacc, int N)
{
    int i = blockIdx.x * 256 + threadIdx.x;
    if (i < N * 128) hagg[i] = 0.f;
    if (i < N * 4) { gmax[i] = 0x007FFFFFu; gsum[i] = 0.f; }
    if (i < 32) bnacc[i] = 0.0;
}

// ---------------- geometry + BN stats ----------------
__global__ __launch_bounds__(256)
void geom_kernel(const int* __restrict__ eidx, const float* __restrict__ hvv,
                 const float* __restrict__ frame, const float* __restrict__ Wvec,
                 float* __restrict__ vff, double* __restrict__ bnacc, int E)
{
    __shared__ float Ws[512];
    __shared__ float bsum[16], bsq[16];
    int tid = threadIdx.x;
    for (int i = tid; i < 512; i += 256) Ws[i] = Wvec[i];
    if (tid < 16) { bsum[tid] = 0.f; bsq[tid] = 0.f; }
    __syncthreads();

    int e = blockIdx.x * 256 + tid;
    float dloc[16];
#pragma unroll
    for (int o = 0; o < 16; o++) dloc[o] = 0.f;

    if (e < E) {
        int c = eidx[e];
        int d = eidx[E + e];
        float F[9];
#pragma unroll
        for (int i = 0; i < 9; i++) F[i] = frame[e * 9 + i];
        float vdt[48], vsrc[48];
#pragma unroll
        for (int v = 0; v < 16; v++) {
            float x = hvv[d * 48 + v * 3 + 0];
            float y = hvv[d * 48 + v * 3 + 1];
            float z = hvv[d * 48 + v * 3 + 2];
            vdt[v * 3 + 0] = F[0] * x + F[1] * y + F[2] * z;
            vdt[v * 3 + 1] = F[3] * x + F[4] * y + F[5] * z;
            vdt[v * 3 + 2] = F[6] * x + F[7] * y + F[8] * z;
        }
#pragma unroll
        for (int i = 0; i < 48; i++) vsrc[i] = hvv[c * 48 + i];

#pragma unroll
        for (int o = 0; o < 16; o++) {
            float v0 = vdt[o * 3 + 0], v1 = vdt[o * 3 + 1], v2 = vdt[o * 3 + 2];
#pragma unroll
            for (int v = 0; v < 16; v++) {
                float wa = Ws[o * 32 + v], wb = Ws[o * 32 + 16 + v];
                v0 += wa * vdt[v * 3 + 0] + wb * vsrc[v * 3 + 0];
                v1 += wa * vdt[v * 3 + 1] + wb * vsrc[v * 3 + 1];
                v2 += wa * vdt[v * 3 + 2] + wb * vsrc[v * 3 + 2];
            }
            float dist = sqrtf(v0 * v0 + v1 * v1 + v2 * v2) + 1e-6f;
            float inv = 1.f / dist;
            vff[e * 64 + o * 3 + 0] = v0 * inv;
            vff[e * 64 + o * 3 + 1] = v1 * inv;
            vff[e * 64 + o * 3 + 2] = v2 * inv;
            vff[e * 64 + 48 + o] = dist;
            dloc[o] = dist;
        }
    }

#pragma unroll
    for (int o = 0; o < 16; o++) {
        float v = dloc[o], v2 = v * v;
#pragma unroll
        for (int off = 16; off; off >>= 1) {
            v  += __shfl_down_sync(0xffffffffu, v, off);
            v2 += __shfl_down_sync(0xffffffffu, v2, off);
        }
        if ((tid & 31) == 0) { atomicAdd(&bsum[o], v); atomicAdd(&bsq[o], v2); }
    }
    __syncthreads();
    if (tid < 16) {
        atomicAdd(&bnacc[tid], (double)bsum[tid]);
        atomicAdd(&bnacc[16 + tid], (double)bsq[tid]);
    }
}

__global__ void bn_finalize(const double* __restrict__ acc, const float* __restrict__ g,
                            const float* __restrict__ b, float* __restrict__ st, int E)
{
    int i = threadIdx.x;
    if (i >= 16) return;
    double mean = acc[i] / (double)E;
    double var  = acc[16 + i] / (double)E - mean * mean;
    float s = (float)((double)g[i] / sqrt(var + 1e-5));
    st[i] = s;
    st[16 + i] = b[i] - (float)mean * s;
}

// ---------------- conversion passes ----------------
__global__ void wprep(const float* __restrict__ W, bf16* __restrict__ hi, bf16* __restrict__ lo,
                      int K, int NT)
{
    int idx = blockIdx.x * 256 + threadIdx.x;
    if (idx >= K * NT) return;
    int k = idx / NT, n = idx % NT;
    float v = W[idx];
    bf16 h = __float2bfloat16_rn(v);
    hi[(size_t)n * K + k] = h;
    lo[(size_t)n * K + k] = __float2bfloat16_rn(v - __bfloat162float(h));
}

__global__ void c2planes(const float* __restrict__ x, bf16* __restrict__ hi,
                         bf16* __restrict__ lo, size_t n)
{
    size_t i = (size_t)blockIdx.x * 256 + threadIdx.x;
    if (i >= n) return;
    float v = x[i];
    bf16 h = __float2bfloat16_rn(v);
    hi[i] = h;
    lo[i] = __float2bfloat16_rn(v - __bfloat162float(h));
}

__global__ void vffprep(const float* __restrict__ vff, const float* __restrict__ st,
                        bf16* __restrict__ hi, bf16* __restrict__ lo, int E)
{
    size_t i = (size_t)blockIdx.x * 256 + threadIdx.x;
    if (i >= (size_t)E * 64) return;
    int col = (int)(i & 63);
    float v = vff[i];
    if (col >= 48) v = fmaf(v, st[col - 48], st[col - 32]);
    bf16 h = __float2bfloat16_rn(v);
    hi[i] = h;
    lo[i] = __float2bfloat16_rn(v - __bfloat162float(h));
}

// ---------------- HMMA bf16x3 GEMM ----------------
// C[M,NTC] = A[M,K] @ W[K,NTC]; A,W given as bf16 hi/lo planes (W as [n][k]).
// MODE 0: A = (Ahi,Alo) stride K
// MODE 1: chunk k0==0 -> vff planes (stride 64); else A2 planes stride 256 at k0-64
// MODE 2: k0<128 -> gathered (Ahi,Alo)[gidx[row]] stride 128; else A2 planes stride 256 at k0-128
// ACT: 0 none, 1 relu, 2 gelu ; OUTF: 1 fp32 C, 2 bf16 hi/lo planes
template<int MODE, int ACT, int OUTF, int NTC>
__global__ __launch_bounds__(256, 1)
void hmma_gemm(const bf16* __restrict__ Ahi, const bf16* __restrict__ Alo,
               const bf16* __restrict__ A2hi, const bf16* __restrict__ A2lo,
               const int* __restrict__ gidx,
               const bf16* __restrict__ Bhi, const bf16* __restrict__ Blo,
               const float* __restrict__ bias,
               float* __restrict__ Cf, bf16* __restrict__ Chi, bf16* __restrict__ Clo,
               int M, int K)
{
    extern __shared__ char smem[];
    // stage = 4 planes (Ahi,Alo,Bhi,Blo) each 128 rows x 128B = 16KB -> 64KB/stage, x2
    const uint32_t sb = smem_u32(smem);
    const int tid = threadIdx.x;
    const int wid = tid >> 5;
    const int lane = tid & 31;
    const int row0 = blockIdx.y * 128;
    const int col0 = blockIdx.x * 128;

    // ---- loader mapping: thread -> (row lr, 4 of 8 16B-units) ----
    const int lr = tid >> 1;
    const int u0 = (tid & 1) * 4;
    const int arow = (row0 + lr < M) ? (row0 + lr) : (M - 1);
    int gr = 0;
    if (MODE == 2) gr = gidx[arow];
    const int brow = col0 + lr;  // weight plane row (always valid)

    const int nk = K >> 6;

    auto issue = [&](int kc, int st) {
        const int k0 = kc << 6;
        const bf16 *pah, *pal;
        if (MODE == 0) {
            pah = Ahi + (size_t)arow * K + k0;
            pal = Alo + (size_t)arow * K + k0;
        } else if (MODE == 1) {
            if (k0 == 0) { pah = Ahi + (size_t)arow * 64; pal = Alo + (size_t)arow * 64; }
            else { pah = A2hi + (size_t)arow * 256 + (k0 - 64); pal = A2lo + (size_t)arow * 256 + (k0 - 64); }
        } else {
            if (k0 < 128) { pah = Ahi + (size_t)gr * 128 + k0; pal = Alo + (size_t)gr * 128 + k0; }
            else { pah = A2hi + (size_t)arow * 256 + (k0 - 128); pal = A2lo + (size_t)arow * 256 + (k0 - 128); }
        }
        const bf16* pbh = Bhi + (size_t)brow * K + k0;
        const bf16* pbl = Blo + (size_t)brow * K + k0;

        const uint32_t stbase = sb + st * 65536;
        const uint32_t rowoff = lr * 128;
        const int sw = lr & 7;
#pragma unroll
        for (int i = 0; i < 4; i++) {
            const int u = u0 + i;
            const uint32_t d = rowoff + (uint32_t)((u ^ sw) << 4);
            cp16(stbase +         d, (const char*)pah + u * 16);
            cp16(stbase + 16384 + d, (const char*)pal + u * 16);
            cp16(stbase + 32768 + d, (const char*)pbh + u * 16);
            cp16(stbase + 49152 + d, (const char*)pbl + u * 16);
        }
        CP_COMMIT();
    };

    // ---- compute mapping: 8 warps = 4(m) x 2(n) ----
    const int wm = wid >> 1;
    const int wn = wid & 1;

    float acc[2][8][4];
#pragma unroll
    for (int i = 0; i < 2; i++)
#pragma unroll
        for (int j = 0; j < 8; j++)
#pragma unroll
            for (int q = 0; q < 4; q++) acc[i][j][q] = 0.f;

    // precompute ldmatrix lane offsets (row, unit-bit) independent of kstep
    const int a_row = wm * 32 + (lane & 7) + ((lane & 8) ? 8 : 0); // + mt*16
    const int a_ub  = (lane & 16) ? 1 : 0;
    const int b_rowb = wn * 64 + (lane & 7) + ((lane & 16) ? 8 : 0); // + g*16
    const int b_ub  = (lane & 8) ? 1 : 0;

    issue(0, 0);
    for (int kc = 0; kc < nk; kc++) {
        if (kc + 1 < nk) { issue(kc + 1, (kc + 1) & 1); CP_WAIT(1); }
        else             { CP_WAIT(0); }
        __syncthreads();

        const uint32_t stbase = sb + (kc & 1) * 65536;
#pragma unroll
        for (int ks = 0; ks < 4; ks++) {
            uint32_t ahi[2][4], alo[2][4];
#pragma unroll
            for (int mt = 0; mt < 2; mt++) {
                const int r = a_row + mt * 16;
                const int u = ks * 2 + a_ub;
                const uint32_t off = r * 128 + (uint32_t)(((u ^ (r & 7))) << 4);
                ldsm4(ahi[mt], stbase + off);
                ldsm4(alo[mt], stbase + 16384 + off);
            }
            uint32_t bhi[4][4], blo[4][4];
#pragma unroll
            for (int g = 0; g < 4; g++) {
                const int n = b_rowb + g * 16;
                const int u = ks * 2 + b_ub;
                const uint32_t off = n * 128 + (uint32_t)(((u ^ (n & 7))) << 4);
                ldsm4(bhi[g], stbase + 32768 + off);
                ldsm4(blo[g], stbase + 49152 + off);
            }
#pragma unroll
            for (int mt = 0; mt < 2; mt++)
#pragma unroll
                for (int nt = 0; nt < 8; nt++) {
                    float* a_ = acc[mt][nt];
                    const uint32_t* bh = &bhi[nt >> 1][(nt & 1) * 2];
                    const uint32_t* bl = &blo[nt >> 1][(nt & 1) * 2];
                    mma16816(a_, ahi[mt], bh);
                    mma16816(a_, ahi[mt], bl);
                    mma16816(a_, alo[mt], bh);
                }
        }
        __syncthreads();
    }

    // ---- epilogue ----
#pragma unroll
    for (int mt = 0; mt < 2; mt++) {
        const int r = row0 + wm * 32 + mt * 16 + (lane >> 2);
#pragma unroll
        for (int nt = 0; nt < 8; nt++) {
            const int c = col0 + wn * 64 + nt * 8 + (lane & 3) * 2;
            float d[4];
#pragma unroll
            for (int q = 0; q < 4; q++) d[q] = acc[mt][nt][q];
            if (bias) {
                float b0 = bias[c], b1 = bias[c + 1];
                d[0] += b0; d[1] += b1; d[2] += b0; d[3] += b1;
            }
#pragma unroll
            for (int q = 0; q < 4; q++) {
                if (ACT == 1) d[q] = fmaxf(d[q], 0.f);
                if (ACT == 2) d[q] = 0.5f * d[q] * (1.f + erff(d[q] * 0.70710678118654752f));
            }
#pragma unroll
            for (int half = 0; half < 2; half++) {
                const int rr = r + half * 8;
                if (rr >= M) continue;
                const float e0 = d[half * 2], e1 = d[half * 2 + 1];
                if (OUTF == 1) {
                    *(float2*)(Cf + (size_t)rr * NTC + c) = make_float2(e0, e1);
                } else {
                    bf16 h0 = __float2bfloat16_rn(e0);
                    bf16 h1 = __float2bfloat16_rn(e1);
                    __nv_bfloat162 hp; hp.x = h0; hp.y = h1;
                    __nv_bfloat162 lp;
                    lp.x = __float2bfloat16_rn(e0 - __bfloat162float(h0));
                    lp.y = __float2bfloat16_rn(e1 - __bfloat162float(h1));
                    *(__nv_bfloat162*)(Chi + (size_t)rr * NTC + c) = hp;
                    *(__nv_bfloat162*)(Clo + (size_t)rr * NTC + c) = lp;
                }
            }
        }
    }
}

// ---------------- logits (4 needed heads) + segment max ----------------
__global__ __launch_bounds__(256)
void logits_kernel(const float* __restrict__ x2, const float* __restrict__ Wb3,
                   const float* __restrict__ bb3, const int* __restrict__ center,
                   float* __restrict__ logit, unsigned* __restrict__ gmax, int E)
{
    int gtid = blockIdx.x * 256 + threadIdx.x;
    int e = gtid >> 5;
    int lane = gtid & 31;
    if (e >= E) return;
    const float* xr = x2 + (size_t)e * 128;
    float p0 = 0.f, p1 = 0.f, p2 = 0.f, p3 = 0.f;
#pragma unroll
    for (int kk = 0; kk < 4; kk++) {
        int k = lane + kk * 32;
        float x = xr[k];
        p0 += x * Wb3[k * 8 + 0];
        p1 += x * Wb3[k * 8 + 1];
        p2 += x * Wb3[k * 8 + 2];
        p3 += x * Wb3[k * 8 + 3];
    }
#pragma unroll
    for (int off = 16; off; off >>= 1) {
        p0 += __shfl_xor_sync(0xffffffffu, p0, off);
        p1 += __shfl_xor_sync(0xffffffffu, p1, off);
        p2 += __shfl_xor_sync(0xffffffffu, p2, off);
        p3 += __shfl_xor_sync(0xffffffffu, p3, off);
    }
    if (lane < 4) {
        float p = (lane == 0) ? p0 : (lane == 1) ? p1 : (lane == 2) ? p2 : p3;
        float l = (p + bb3[lane]) * 0.17677669529663687f;
        logit[e * 4 + lane] = l;
        atomicMax(&gmax[center[e] * 4 + lane], fenc(l));
    }
}

__global__ void expsum_kernel(float* __restrict__ logit, const int* __restrict__ center,
                              const unsigned* __restrict__ gmax, float* __restrict__ gsum, int E)
{
    int idx = blockIdx.x * 256 + threadIdx.x;
    if (idx >= E * 4) return;
    int e = idx >> 2, h = idx & 3;
    int c = center[e];
    float m = fdec(gmax[c * 4 + h]);
    float ex = expf(logit[idx] - m);
    logit[idx] = ex;
    atomicAdd(&gsum[c * 4 + h], ex);
}

__global__ void agg_kernel(const float* __restrict__ gexp, const float* __restrict__ gsum,
                           const float* __restrict__ V, const int* __restrict__ center,
                           float* __restrict__ hagg, int E)
{
    int idx = blockIdx.x * 256 + threadIdx.x;
    if (idx >= E * 128) return;
    int e = idx >> 7, t = idx & 127, h = t >> 5;
    int c = center[e];
    float att = gexp[e * 4 + h] / gsum[c * 4 + h];
    atomicAdd(&hagg[c * 128 + t], att * V[idx]);
}

// ---------------- host launch ----------------
extern "C" void kernel_launch(void* const* d_in, const int* in_sizes, int n_in,
                              void* d_out, int out_size)
{
    const float* h_V   = (const float*)d_in[0];
    const float* h_E   = (const float*)d_in[1];
    const int*   eidx  = (const int*)  d_in[2];
    const float* hvv   = (const float*)d_in[3];
    const float* frame = (const float*)d_in[4];
    const float* W_vec = (const float*)d_in[5];
    const float* W_red = (const float*)d_in[6];
    const float* Wb1   = (const float*)d_in[7];
    const float* bb1   = (const float*)d_in[8];
    const float* Wb2   = (const float*)d_in[9];
    const float* bb2   = (const float*)d_in[10];
    const float* Wb3   = (const float*)d_in[11];
    const float* bb3   = (const float*)d_in[12];
    const float* Wv1   = (const float*)d_in[13];
    const float* bv1   = (const float*)d_in[14];
    const float* Wv2   = (const float*)d_in[15];
    const float* bv2   = (const float*)d_in[16];
    const float* Wv3   = (const float*)d_in[17];
    const float* bv3   = (const float*)d_in[18];
    const float* W_O   = (const float*)d_in[19];
    const float* bn_g  = (const float*)d_in[20];
    const float* bn_b  = (const float*)d_in[21];

    int E = in_sizes[2] / 2;
    int N = in_sizes[0] / 128;
    float* out = (float*)d_out;

    float *vff, *f32, *logit, *gsum, *hagg, *bnst;
    bf16 *vffh, *vffl, *hEh, *hEl, *eh, *el, *pAh, *pAl, *pBh, *pBl, *hVh, *hVl, *hgh, *hgl, *wh, *wl;
    unsigned* gmax;
    double* bnacc;
    cudaGetSymbolAddress((void**)&vff,   g_vff);
    cudaGetSymbolAddress((void**)&vffh,  g_vffh);
    cudaGetSymbolAddress((void**)&vffl,  g_vffl);
    cudaGetSymbolAddress((void**)&hEh,   g_hEh);
    cudaGetSymbolAddress((void**)&hEl,   g_hEl);
    cudaGetSymbolAddress((void**)&eh,    g_eh);
    cudaGetSymbolAddress((void**)&el,    g_el);
    cudaGetSymbolAddress((void**)&pAh,   g_pAh);
    cudaGetSymbolAddress((void**)&pAl,   g_pAl);
    cudaGetSymbolAddress((void**)&pBh,   g_pBh);
    cudaGetSymbolAddress((void**)&pBl,   g_pBl);
    cudaGetSymbolAddress((void**)&f32,   g_f32);
    cudaGetSymbolAddress((void**)&hVh,   g_hVh);
    cudaGetSymbolAddress((void**)&hVl,   g_hVl);
    cudaGetSymbolAddress((void**)&hgh,   g_hgh);
    cudaGetSymbolAddress((void**)&hgl,   g_hgl);
    cudaGetSymbolAddress((void**)&wh,    g_wh);
    cudaGetSymbolAddress((void**)&wl,    g_wl);
    cudaGetSymbolAddress((void**)&logit, g_logit);
    cudaGetSymbolAddress((void**)&gmax,  g_max);
    cudaGetSymbolAddress((void**)&gsum,  g_sum);
    cudaGetSymbolAddress((void**)&hagg,  g_hagg);
    cudaGetSymbolAddress((void**)&bnacc, g_bnacc);
    cudaGetSymbolAddress((void**)&bnst,  g_bnst);

    const int SMEM = 131072;
    cudaFuncSetAttribute(hmma_gemm<1, 0, 2, 256>, cudaFuncAttributeMaxDynamicSharedMemorySize, SMEM);
    cudaFuncSetAttribute(hmma_gemm<2, 1, 2, 128>, cudaFuncAttributeMaxDynamicSharedMemorySize, SMEM);
    cudaFuncSetAttribute(hmma_gemm<0, 1, 1, 128>, cudaFuncAttributeMaxDynamicSharedMemorySize, SMEM);
    cudaFuncSetAttribute(hmma_gemm<0, 2, 2, 128>, cudaFuncAttributeMaxDynamicSharedMemorySize, SMEM);
    cudaFuncSetAttribute(hmma_gemm<0, 0, 1, 128>, cudaFuncAttributeMaxDynamicSharedMemorySize, SMEM);

    int Mt = (E + 127) / 128;
    int Mo = (N + 127) / 128;

    init_kernel<<<(N * 128 + 255) / 256, 256>>>(gmax, gsum, hagg, bnacc, N);
    geom_kernel<<<(E + 255) / 256, 256>>>(eidx, hvv, frame, W_vec, vff, bnacc, E);
    bn_finalize<<<1, 32>>>(bnacc, bn_g, bn_b, bnst, E);

    // conversions
    wprep<<<(320 * 256 + 255) / 256, 256>>>(W_red, wh + OW_RED, wl + OW_RED, 320, 256);
    wprep<<<(384 * 128 + 255) / 256, 256>>>(Wb1,   wh + OW_B1,  wl + OW_B1,  384, 128);
    wprep<<<(128 * 128 + 255) / 256, 256>>>(Wb2,   wh + OW_B2,  wl + OW_B2,  128, 128);
    wprep<<<(256 * 128 + 255) / 256, 256>>>(Wv1,   wh + OW_V1,  wl + OW_V1,  256, 128);
    wprep<<<(128 * 128 + 255) / 256, 256>>>(Wv2,   wh + OW_V2,  wl + OW_V2,  128, 128);
    wprep<<<(128 * 128 + 255) / 256, 256>>>(Wv3,   wh + OW_V3,  wl + OW_V3,  128, 128);
    wprep<<<(128 * 128 + 255) / 256, 256>>>(W_O,   wh + OW_O,   wl + OW_O,   128, 128);
    c2planes<<<(int)(((size_t)E * 256 + 255) / 256), 256>>>(h_E, hEh, hEl, (size_t)E * 256);
    c2planes<<<(N * 128 + 255) / 256, 256>>>(h_V, hVh, hVl, (size_t)N * 128);
    vffprep<<<(int)(((size_t)E * 64 + 255) / 256), 256>>>(vff, bnst, vffh, vffl, E);

    // hE = [vff_bn | h_E] @ W_red  -> planes
    hmma_gemm<1, 0, 2, 256><<<dim3(2, Mt), 256, SMEM>>>(
        vffh, vffl, hEh, hEl, nullptr, wh + OW_RED, wl + OW_RED, nullptr,
        nullptr, eh, el, E, 320);
    // x1 = relu([h_V[center] | hE] @ Wb1 + bb1) -> planes
    hmma_gemm<2, 1, 2, 128><<<dim3(1, Mt), 256, SMEM>>>(
        hVh, hVl, eh, el, eidx, wh + OW_B1, wl + OW_B1, bb1,
        nullptr, pAh, pAl, E, 384);
    // x2 = relu(x1 @ Wb2 + bb2) -> fp32
    hmma_gemm<0, 1, 1, 128><<<dim3(1, Mt), 256, SMEM>>>(
        pAh, pAl, nullptr, nullptr, nullptr, wh + OW_B2, wl + OW_B2, bb2,
        f32, nullptr, nullptr, E, 128);
    // logits + segment max
    logits_kernel<<<(E * 32 + 255) / 256, 256>>>(f32, Wb3, bb3, eidx, logit, gmax, E);
    // v1 = gelu(hE @ Wv1 + bv1) -> planes (pA reusable after x2)
    hmma_gemm<0, 2, 2, 128><<<dim3(1, Mt), 256, SMEM>>>(
        eh, el, nullptr, nullptr, nullptr, wh + OW_V1, wl + OW_V1, bv1,
        nullptr, pAh, pAl, E, 256);
    // exp + segment sum
    expsum_kernel<<<(E * 4 + 255) / 256, 256>>>(logit, eidx, gmax, gsum, E);
    // v2 = gelu(v1 @ Wv2 + bv2) -> planes
    hmma_gemm<0, 2, 2, 128><<<dim3(1, Mt), 256, SMEM>>>(
        pAh, pAl, nullptr, nullptr, nullptr, wh + OW_V2, wl + OW_V2, bv2,
        nullptr, pBh, pBl, E, 128);
    // V = v2 @ Wv3 + bv3 -> fp32 (x2 dead after logits)
    hmma_gemm<0, 0, 1, 128><<<dim3(1, Mt), 256, SMEM>>>(
        pBh, pBl, nullptr, nullptr, nullptr, wh + OW_V3, wl + OW_V3, bv3,
        f32, nullptr, nullptr, E, 128);
    // h_agg = segment_sum(att * V)
    agg_kernel<<<(E * 128 + 255) / 256, 256>>>(logit, gsum, f32, eidx, hagg, E);
    // hagg -> planes, then out = hagg @ W_O
    c2planes<<<(N * 128 + 255) / 256, 256>>>(hagg, hgh, hgl, (size_t)N * 128);
    hmma_gemm<0, 0, 1, 128><<<dim3(1, Mo), 256, SMEM>>>(
        hgh, hgl, nullptr, nullptr, nullptr, wh + OW_O, wl + OW_O, nullptr,
        out, nullptr, nullptr, N, 128);
}

// round 4
// speedup vs baseline: 2.6013x; 1.2030x over previous
#include <cuda_runtime.h>
#include <cuda_bf16.h>
#include <math.h>
#include <stdint.h>

#define E_CONST 320000
#define N_CONST 10000
typedef __nv_bfloat16 bf16;

// ---------------- scratch (no allocations allowed) ----------------
static __device__ float    g_vff [(size_t)E_CONST * 64];       // fp32 [sincos48|dist16]
static __device__ bf16     g_vffh[(size_t)E_CONST * 64];
static __device__ bf16     g_vffl[(size_t)E_CONST * 64];
static __device__ bf16     g_hEh [(size_t)E_CONST * 256];      // input h_E planes
static __device__ bf16     g_hEl [(size_t)E_CONST * 256];
static __device__ bf16     g_eh  [(size_t)E_CONST * 256];      // hE (W_red out) planes
static __device__ bf16     g_el  [(size_t)E_CONST * 256];
static __device__ bf16     g_hVh [N_CONST * 128];
static __device__ bf16     g_hVl [N_CONST * 128];
static __device__ bf16     g_hgh [N_CONST * 128];
static __device__ bf16     g_hgl [N_CONST * 128];
static __device__ bf16     g_wh  [262144];                     // all weights, [n][k]
static __device__ bf16     g_wl  [262144];
static __device__ float    g_logit[(size_t)E_CONST * 4];
static __device__ unsigned g_max [N_CONST * 4];
static __device__ float    g_sum [N_CONST * 4];
static __device__ float    g_hagg[N_CONST * 128];
static __device__ double   g_bnacc[32];
static __device__ float    g_bnst[32];

// weight plane offsets (elements)
#define OW_RED 0        // 256 x 320
#define OW_B1  81920    // 128 x 384
#define OW_B2  131072   // 128 x 128
#define OW_V1  147456   // 128 x 256
#define OW_V2  180224   // 128 x 128
#define OW_V3  196608   // 128 x 128
#define OW_O   212992   // 128 x 128
#define W_TOTAL 229376

// ---------------- helpers ----------------
__device__ __forceinline__ uint32_t smem_u32(const void* p) {
    uint32_t a;
    asm("{ .reg .u64 t; cvta.to.shared.u64 t, %1; cvt.u32.u64 %0, t; }" : "=r"(a) : "l"(p));
    return a;
}
__device__ __forceinline__ void cp16(uint32_t dst, const void* src) {
    asm volatile("cp.async.cg.shared.global [%0], [%1], 16;"
        :: "r"(dst), "l"(__cvta_generic_to_global(src)) : "memory");
}
#define CP_COMMIT() asm volatile("cp.async.commit_group;" ::: "memory")
#define CP_WAIT(n)  asm volatile("cp.async.wait_group %0;" :: "n"(n) : "memory")

__device__ __forceinline__ void ldsm4(uint32_t* r, uint32_t addr) {
    asm volatile("ldmatrix.sync.aligned.m8n8.x4.shared.b16 {%0,%1,%2,%3}, [%4];"
        : "=r"(r[0]), "=r"(r[1]), "=r"(r[2]), "=r"(r[3]) : "r"(addr));
}
__device__ __forceinline__ void mma16816(float* d, const uint32_t* a, const uint32_t* b) {
    asm volatile(
        "mma.sync.aligned.m16n8k16.row.col.f32.bf16.bf16.f32 "
        "{%0,%1,%2,%3}, {%4,%5,%6,%7}, {%8,%9}, {%0,%1,%2,%3};"
        : "+f"(d[0]), "+f"(d[1]), "+f"(d[2]), "+f"(d[3])
        : "r"(a[0]), "r"(a[1]), "r"(a[2]), "r"(a[3]), "r"(b[0]), "r"(b[1]));
}
__device__ __forceinline__ unsigned fenc(float f) {
    unsigned u = __float_as_uint(f);
    return (u & 0x80000000u) ? ~u : (u | 0x80000000u);
}
__device__ __forceinline__ float fdec(unsigned u) {
    return (u & 0x80000000u) ? __uint_as_float(u & 0x7FFFFFFFu) : __uint_as_float(~u);
}
__device__ __forceinline__ float gelu_f(float x) {
    return 0.5f * x * (1.f + erff(x * 0.70710678118654752f));
}

// ---------------- init ----------------
__global__ void init_kernel(unsigned* gmax, float* gsum, float* hagg, double* bnacc, int N)
{
    int i = blockIdx.x * 256 + threadIdx.x;
    if (i < N * 128) hagg[i] = 0.f;
    if (i < N * 4) { gmax[i] = 0x007FFFFFu; gsum[i] = 0.f; }
    if (i < 32) bnacc[i] = 0.0;
}

// ---------------- geometry + BN stats ----------------
__global__ __launch_bounds__(256)
void geom_kernel(const int* __restrict__ eidx, const float* __restrict__ hvv,
                 const float* __restrict__ frame, const float* __restrict__ Wvec,
                 float* __restrict__ vff, double* __restrict__ bnacc, int E)
{
    __shared__ float Ws[512];
    __shared__ float bsum[16], bsq[16];
    int tid = threadIdx.x;
    for (int i = tid; i < 512; i += 256) Ws[i] = Wvec[i];
    if (tid < 16) { bsum[tid] = 0.f; bsq[tid] = 0.f; }
    __syncthreads();

    int e = blockIdx.x * 256 + tid;
    float dloc[16];
#pragma unroll
    for (int o = 0; o < 16; o++) dloc[o] = 0.f;

    if (e < E) {
        int c = eidx[e];
        int d = eidx[E + e];
        float F[9];
#pragma unroll
        for (int i = 0; i < 9; i++) F[i] = frame[e * 9 + i];
        float vdt[48], vsrc[48];
#pragma unroll
        for (int v = 0; v < 16; v++) {
            float x = hvv[d * 48 + v * 3 + 0];
            float y = hvv[d * 48 + v * 3 + 1];
            float z = hvv[d * 48 + v * 3 + 2];
            vdt[v * 3 + 0] = F[0] * x + F[1] * y + F[2] * z;
            vdt[v * 3 + 1] = F[3] * x + F[4] * y + F[5] * z;
            vdt[v * 3 + 2] = F[6] * x + F[7] * y + F[8] * z;
        }
#pragma unroll
        for (int i = 0; i < 48; i++) vsrc[i] = hvv[c * 48 + i];

#pragma unroll
        for (int o = 0; o < 16; o++) {
            float v0 = vdt[o * 3 + 0], v1 = vdt[o * 3 + 1], v2 = vdt[o * 3 + 2];
#pragma unroll
            for (int v = 0; v < 16; v++) {
                float wa = Ws[o * 32 + v], wb = Ws[o * 32 + 16 + v];
                v0 += wa * vdt[v * 3 + 0] + wb * vsrc[v * 3 + 0];
                v1 += wa * vdt[v * 3 + 1] + wb * vsrc[v * 3 + 1];
                v2 += wa * vdt[v * 3 + 2] + wb * vsrc[v * 3 + 2];
            }
            float dist = sqrtf(v0 * v0 + v1 * v1 + v2 * v2) + 1e-6f;
            float inv = 1.f / dist;
            vff[e * 64 + o * 3 + 0] = v0 * inv;
            vff[e * 64 + o * 3 + 1] = v1 * inv;
            vff[e * 64 + o * 3 + 2] = v2 * inv;
            vff[e * 64 + 48 + o] = dist;
            dloc[o] = dist;
        }
    }

#pragma unroll
    for (int o = 0; o < 16; o++) {
        float v = dloc[o], v2 = v * v;
#pragma unroll
        for (int off = 16; off; off >>= 1) {
            v  += __shfl_down_sync(0xffffffffu, v, off);
            v2 += __shfl_down_sync(0xffffffffu, v2, off);
        }
        if ((tid & 31) == 0) { atomicAdd(&bsum[o], v); atomicAdd(&bsq[o], v2); }
    }
    __syncthreads();
    if (tid < 16) {
        atomicAdd(&bnacc[tid], (double)bsum[tid]);
        atomicAdd(&bnacc[16 + tid], (double)bsq[tid]);
    }
}

__global__ void bn_finalize(const double* __restrict__ acc, const float* __restrict__ g,
                            const float* __restrict__ b, float* __restrict__ st, int E)
{
    int i = threadIdx.x;
    if (i >= 16) return;
    double mean = acc[i] / (double)E;
    double var  = acc[16 + i] / (double)E - mean * mean;
    float s = (float)((double)g[i] / sqrt(var + 1e-5));
    st[i] = s;
    st[16 + i] = b[i] - (float)mean * s;
}

// ---------------- conversion passes ----------------
__global__ void wprep_all(const float* __restrict__ W0, const float* __restrict__ W1,
                          const float* __restrict__ W2, const float* __restrict__ W3,
                          const float* __restrict__ W4, const float* __restrict__ W5,
                          const float* __restrict__ W6,
                          bf16* __restrict__ hi, bf16* __restrict__ lo)
{
    int idx = blockIdx.x * 256 + threadIdx.x;
    if (idx >= W_TOTAL) return;
    const float* src; int K, NT, start;
    if      (idx < OW_B1)  { src = W0; K = 320; NT = 256; start = OW_RED; }
    else if (idx < OW_B2)  { src = W1; K = 384; NT = 128; start = OW_B1; }
    else if (idx < OW_V1)  { src = W2; K = 128; NT = 128; start = OW_B2; }
    else if (idx < OW_V2)  { src = W3; K = 256; NT = 128; start = OW_V1; }
    else if (idx < OW_V3)  { src = W4; K = 128; NT = 128; start = OW_V2; }
    else if (idx < OW_O)   { src = W5; K = 128; NT = 128; start = OW_V3; }
    else                   { src = W6; K = 128; NT = 128; start = OW_O; }
    int local = idx - start;
    int k = local / NT, n = local % NT;
    float v = src[local];
    bf16 h = __float2bfloat16_rn(v);
    hi[start + (size_t)n * K + k] = h;
    lo[start + (size_t)n * K + k] = __float2bfloat16_rn(v - __bfloat162float(h));
}

__global__ void c2planes(const float* __restrict__ x, bf16* __restrict__ hi,
                         bf16* __restrict__ lo, size_t n)
{
    size_t i = (size_t)blockIdx.x * 256 + threadIdx.x;
    if (i >= n) return;
    float v = x[i];
    bf16 h = __float2bfloat16_rn(v);
    hi[i] = h;
    lo[i] = __float2bfloat16_rn(v - __bfloat162float(h));
}

__global__ void vffprep(const float* __restrict__ vff, const float* __restrict__ st,
                        bf16* __restrict__ hi, bf16* __restrict__ lo, int E)
{
    size_t i = (size_t)blockIdx.x * 256 + threadIdx.x;
    if (i >= (size_t)E * 64) return;
    int col = (int)(i & 63);
    float v = vff[i];
    if (col >= 48) v = fmaf(v, st[col - 48], st[col - 32]);
    bf16 h = __float2bfloat16_rn(v);
    hi[i] = h;
    lo[i] = __float2bfloat16_rn(v - __bfloat162float(h));
}

// ================= GEMM building blocks =================
// Global-pipelined GEMM producing per-warp acc[2][8][4], 128x128 tile, 8 warps (4m x 2n).
// MODE 0: A = (Ahi,Alo) stride K
// MODE 1: chunk k0==0 -> vff planes (stride 64); else A2 planes stride 256 at k0-64
// MODE 2: k0<128 -> gathered (Ahi,Alo)[gidx[row]] stride 128; else A2 planes stride 256 at k0-128
template<int MODE>
__device__ __forceinline__ void gemm_pipeline(
    float acc[2][8][4], uint32_t sb,
    const bf16* __restrict__ Ahi, const bf16* __restrict__ Alo,
    const bf16* __restrict__ A2hi, const bf16* __restrict__ A2lo,
    const int* __restrict__ gidx,
    const bf16* __restrict__ Bhi, const bf16* __restrict__ Blo,
    int row0, int col0, int M, int K, int tid)
{
    const int lane = tid & 31;
    const int wid = tid >> 5;

    const int lr = tid >> 1;
    const int u0 = (tid & 1) * 4;
    const int arow = (row0 + lr < M) ? (row0 + lr) : (M - 1);
    int gr = 0;
    if (MODE == 2) gr = gidx[arow];
    const int brow = col0 + lr;

    const int nk = K >> 6;

    auto issue = [&](int kc, int st) {
        const int k0 = kc << 6;
        const bf16 *pah, *pal;
        if (MODE == 0) {
            pah = Ahi + (size_t)arow * K + k0;
            pal = Alo + (size_t)arow * K + k0;
        } else if (MODE == 1) {
            if (k0 == 0) { pah = Ahi + (size_t)arow * 64; pal = Alo + (size_t)arow * 64; }
            else { pah = A2hi + (size_t)arow * 256 + (k0 - 64); pal = A2lo + (size_t)arow * 256 + (k0 - 64); }
        } else {
            if (k0 < 128) { pah = Ahi + (size_t)gr * 128 + k0; pal = Alo + (size_t)gr * 128 + k0; }
            else { pah = A2hi + (size_t)arow * 256 + (k0 - 128); pal = A2lo + (size_t)arow * 256 + (k0 - 128); }
        }
        const bf16* pbh = Bhi + (size_t)brow * K + k0;
        const bf16* pbl = Blo + (size_t)brow * K + k0;

        const uint32_t stbase = sb + st * 65536;
        const uint32_t rowoff = lr * 128;
        const int sw = lr & 7;
#pragma unroll
        for (int i = 0; i < 4; i++) {
            const int u = u0 + i;
            const uint32_t d = rowoff + (uint32_t)((u ^ sw) << 4);
            cp16(stbase +         d, (const char*)pah + u * 16);
            cp16(stbase + 16384 + d, (const char*)pal + u * 16);
            cp16(stbase + 32768 + d, (const char*)pbh + u * 16);
            cp16(stbase + 49152 + d, (const char*)pbl + u * 16);
        }
        CP_COMMIT();
    };

    const int wm = wid >> 1;
    const int wn = wid & 1;
    const int a_row = wm * 32 + (lane & 7) + ((lane & 8) ? 8 : 0);
    const int a_ub  = (lane & 16) ? 1 : 0;
    const int b_rowb = wn * 64 + (lane & 7) + ((lane & 16) ? 8 : 0);
    const int b_ub  = (lane & 8) ? 1 : 0;

    issue(0, 0);
    for (int kc = 0; kc < nk; kc++) {
        if (kc + 1 < nk) { issue(kc + 1, (kc + 1) & 1); CP_WAIT(1); }
        else             { CP_WAIT(0); }
        __syncthreads();

        const uint32_t stbase = sb + (kc & 1) * 65536;
#pragma unroll
        for (int ks = 0; ks < 4; ks++) {
            uint32_t ahi[2][4], alo[2][4];
#pragma unroll
            for (int mt = 0; mt < 2; mt++) {
                const int r = a_row + mt * 16;
                const int u = ks * 2 + a_ub;
                const uint32_t off = r * 128 + (uint32_t)(((u ^ (r & 7))) << 4);
                ldsm4(ahi[mt], stbase + off);
                ldsm4(alo[mt], stbase + 16384 + off);
            }
            uint32_t bhi[4][4], blo[4][4];
#pragma unroll
            for (int g = 0; g < 4; g++) {
                const int n = b_rowb + g * 16;
                const int u = ks * 2 + b_ub;
                const uint32_t off = n * 128 + (uint32_t)(((u ^ (n & 7))) << 4);
                ldsm4(bhi[g], stbase + 32768 + off);
                ldsm4(blo[g], stbase + 49152 + off);
            }
#pragma unroll
            for (int mt = 0; mt < 2; mt++)
#pragma unroll
                for (int nt = 0; nt < 8; nt++) {
                    float* a_ = acc[mt][nt];
                    const uint32_t* bh = &bhi[nt >> 1][(nt & 1) * 2];
                    const uint32_t* bl = &blo[nt >> 1][(nt & 1) * 2];
                    mma16816(a_, ahi[mt], bh);
                    mma16816(a_, ahi[mt], bl);
                    mma16816(a_, alo[mt], bh);
                }
        }
        __syncthreads();
    }
}

// smem-resident GEMM: A planes at aB, B planes at bB (layout: hi c0|hi c1 (16KB ea), lo at +32768)
__device__ __forceinline__ void gemm_smem2(float acc[2][8][4], uint32_t aB, uint32_t bB, int tid)
{
    const int wid = tid >> 5, lane = tid & 31;
    const int wm = wid >> 1, wn = wid & 1;
    const int a_row = wm * 32 + (lane & 7) + ((lane & 8) ? 8 : 0);
    const int a_ub  = (lane & 16) ? 1 : 0;
    const int b_rowb = wn * 64 + (lane & 7) + ((lane & 16) ? 8 : 0);
    const int b_ub  = (lane & 8) ? 1 : 0;
#pragma unroll
    for (int kc = 0; kc < 2; kc++) {
#pragma unroll
        for (int ks = 0; ks < 4; ks++) {
            uint32_t ahi[2][4], alo[2][4];
#pragma unroll
            for (int mt = 0; mt < 2; mt++) {
                const int r = a_row + mt * 16;
                const int u = ks * 2 + a_ub;
                const uint32_t off = kc * 16384 + r * 128 + (uint32_t)(((u ^ (r & 7))) << 4);
                ldsm4(ahi[mt], aB + off);
                ldsm4(alo[mt], aB + 32768 + off);
            }
            uint32_t bhi[4][4], blo[4][4];
#pragma unroll
            for (int g = 0; g < 4; g++) {
                const int n = b_rowb + g * 16;
                const int u = ks * 2 + b_ub;
                const uint32_t off = kc * 16384 + n * 128 + (uint32_t)(((u ^ (n & 7))) << 4);
                ldsm4(bhi[g], bB + off);
                ldsm4(blo[g], bB + 32768 + off);
            }
#pragma unroll
            for (int mt = 0; mt < 2; mt++)
#pragma unroll
                for (int nt = 0; nt < 8; nt++) {
                    float* a_ = acc[mt][nt];
                    const uint32_t* bh = &bhi[nt >> 1][(nt & 1) * 2];
                    const uint32_t* bl = &blo[nt >> 1][(nt & 1) * 2];
                    mma16816(a_, ahi[mt], bh);
                    mma16816(a_, ahi[mt], bl);
                    mma16816(a_, alo[mt], bh);
                }
        }
    }
}

// load 128x128 weight planes into smem chunk layout (hi c0|hi c1|lo c0|lo c1)
__device__ __forceinline__ void load_wplanes(uint32_t dst, const bf16* __restrict__ Whi,
                                             const bf16* __restrict__ Wlo, int tid)
{
    for (int i = tid; i < 2048; i += 256) {
        const int kc = i >> 10;
        const int rem = i & 1023;
        const int row = rem >> 3, u = rem & 7;
        const uint32_t d = kc * 16384 + row * 128 + (uint32_t)(((u ^ (row & 7))) << 4);
        cp16(dst +         d, (const char*)(Whi + (size_t)row * 128 + kc * 64) + u * 16);
        cp16(dst + 32768 + d, (const char*)(Wlo + (size_t)row * 128 + kc * 64) + u * 16);
    }
    CP_COMMIT();
    CP_WAIT(0);
}

// store fragments -> smem bf16 hi/lo planes (with bias + activation)
template<int ACT>
__device__ __forceinline__ void store_planes(const float acc[2][8][4], char* smemp, uint32_t base,
                                             const float* __restrict__ bias, int tid)
{
    const int wid = tid >> 5, lane = tid & 31;
    const int wm = wid >> 1, wn = wid & 1;
#pragma unroll
    for (int mt = 0; mt < 2; mt++)
#pragma unroll
        for (int nt = 0; nt < 8; nt++) {
            const int c = wn * 64 + nt * 8 + (lane & 3) * 2;
            const int kc = c >> 6, kk = c & 63, u = kk >> 3;
            const float b0 = bias[c], b1 = bias[c + 1];
#pragma unroll
            for (int half = 0; half < 2; half++) {
                const int r = wm * 32 + mt * 16 + (lane >> 2) + half * 8;
                float e0 = acc[mt][nt][half * 2] + b0;
                float e1 = acc[mt][nt][half * 2 + 1] + b1;
                if (ACT == 1) { e0 = fmaxf(e0, 0.f); e1 = fmaxf(e1, 0.f); }
                if (ACT == 2) { e0 = gelu_f(e0); e1 = gelu_f(e1); }
                bf16 h0 = __float2bfloat16_rn(e0);
                bf16 h1 = __float2bfloat16_rn(e1);
                __nv_bfloat162 hp; hp.x = h0; hp.y = h1;
                __nv_bfloat162 lp;
                lp.x = __float2bfloat16_rn(e0 - __bfloat162float(h0));
                lp.y = __float2bfloat16_rn(e1 - __bfloat162float(h1));
                const uint32_t ad = base + kc * 16384 + r * 128 +
                                    (uint32_t)(((u ^ (r & 7))) << 4) + (kk & 7) * 2;
                *(__nv_bfloat162*)(smemp + ad) = hp;
                *(__nv_bfloat162*)(smemp + 32768 + ad) = lp;
            }
        }
}

// ---------------- standalone GEMM (W_red, W_O) ----------------
template<int MODE, int OUTF, int NTC>
__global__ __launch_bounds__(256, 1)
void hmma_gemm(const bf16* __restrict__ Ahi, const bf16* __restrict__ Alo,
               const bf16* __restrict__ A2hi, const bf16* __restrict__ A2lo,
               const int* __restrict__ gidx,
               const bf16* __restrict__ Bhi, const bf16* __restrict__ Blo,
               float* __restrict__ Cf, bf16* __restrict__ Chi, bf16* __restrict__ Clo,
               int M, int K)
{
    extern __shared__ char smem[];
    const uint32_t sb = smem_u32(smem);
    const int tid = threadIdx.x;
    const int wid = tid >> 5, lane = tid & 31;
    const int row0 = blockIdx.y * 128;
    const int col0 = blockIdx.x * 128;

    float acc[2][8][4];
#pragma unroll
    for (int i = 0; i < 2; i++)
#pragma unroll
        for (int j = 0; j < 8; j++)
#pragma unroll
            for (int q = 0; q < 4; q++) acc[i][j][q] = 0.f;

    gemm_pipeline<MODE>(acc, sb, Ahi, Alo, A2hi, A2lo, gidx, Bhi, Blo, row0, col0, M, K, tid);

    const int wm = wid >> 1, wn = wid & 1;
#pragma unroll
    for (int mt = 0; mt < 2; mt++) {
        const int r = row0 + wm * 32 + mt * 16 + (lane >> 2);
#pragma unroll
        for (int nt = 0; nt < 8; nt++) {
            const int c = col0 + wn * 64 + nt * 8 + (lane & 3) * 2;
#pragma unroll
            for (int half = 0; half < 2; half++) {
                const int rr = r + half * 8;
                if (rr >= M) continue;
                const float e0 = acc[mt][nt][half * 2];
                const float e1 = acc[mt][nt][half * 2 + 1];
                if (OUTF == 1) {
                    *(float2*)(Cf + (size_t)rr * NTC + c) = make_float2(e0, e1);
                } else {
                    bf16 h0 = __float2bfloat16_rn(e0);
                    bf16 h1 = __float2bfloat16_rn(e1);
                    __nv_bfloat162 hp; hp.x = h0; hp.y = h1;
                    __nv_bfloat162 lp;
                    lp.x = __float2bfloat16_rn(e0 - __bfloat162float(h0));
                    lp.y = __float2bfloat16_rn(e1 - __bfloat162float(h1));
                    *(__nv_bfloat162*)(Chi + (size_t)rr * NTC + c) = hp;
                    *(__nv_bfloat162*)(Clo + (size_t)rr * NTC + c) = lp;
                }
            }
        }
    }
}

// ---------------- fused A: x1 -> x2 -> logits(+segmax) ----------------
__global__ __launch_bounds__(256, 1)
void fusedA_kernel(const bf16* __restrict__ hVh, const bf16* __restrict__ hVl,
                   const bf16* __restrict__ eh, const bf16* __restrict__ el,
                   const int* __restrict__ eidx,
                   const bf16* __restrict__ wb1h, const bf16* __restrict__ wb1l,
                   const float* __restrict__ bb1,
                   const bf16* __restrict__ wb2h, const bf16* __restrict__ wb2l,
                   const float* __restrict__ bb2,
                   const float* __restrict__ Wb3, const float* __restrict__ bb3,
                   float* __restrict__ logit, unsigned* __restrict__ gmax, int M)
{
    extern __shared__ char smem[];
    const uint32_t sb = smem_u32(smem);
    const int tid = threadIdx.x;
    const int row0 = blockIdx.x * 128;

    // Wb3 (4 heads) transposed into smem tail: wb3s[h*128 + k]
    float* wb3s = (float*)(smem + 131072);
    if (tid < 128) {
#pragma unroll
        for (int h = 0; h < 4; h++) wb3s[h * 128 + tid] = Wb3[tid * 8 + h];
    }

    float acc[2][8][4];
#pragma unroll
    for (int i = 0; i < 2; i++)
#pragma unroll
        for (int j = 0; j < 8; j++)
#pragma unroll
            for (int q = 0; q < 4; q++) acc[i][j][q] = 0.f;

    // x1 = relu([hV[center] | hE] @ Wb1 + bb1), K=384
    gemm_pipeline<2>(acc, sb, hVh, hVl, eh, el, eidx, wb1h, wb1l, row0, 0, M, 384, tid);

    // x1 planes -> [0,64K); Wb2 planes -> [64K,128K)
    store_planes<1>(acc, smem, 0, bb1, tid);
    load_wplanes(sb + 65536, wb2h, wb2l, tid);
    __syncthreads();

    // x2 = relu(x1 @ Wb2 + bb2)
    float acc2[2][8][4];
#pragma unroll
    for (int i = 0; i < 2; i++)
#pragma unroll
        for (int j = 0; j < 8; j++)
#pragma unroll
            for (int q = 0; q < 4; q++) acc2[i][j][q] = 0.f;
    gemm_smem2(acc2, sb, sb + 65536, tid);
    __syncthreads();

    // x2 fp32 -> [0,64K)
    {
        const int wid = tid >> 5, lane = tid & 31;
        const int wm = wid >> 1, wn = wid & 1;
#pragma unroll
        for (int mt = 0; mt < 2; mt++)
#pragma unroll
            for (int nt = 0; nt < 8; nt++) {
                const int c = wn * 64 + nt * 8 + (lane & 3) * 2;
                const float b0 = bb2[c], b1 = bb2[c + 1];
#pragma unroll
                for (int half = 0; half < 2; half++) {
                    const int r = wm * 32 + mt * 16 + (lane >> 2) + half * 8;
                    float e0 = fmaxf(acc2[mt][nt][half * 2] + b0, 0.f);
                    float e1 = fmaxf(acc2[mt][nt][half * 2 + 1] + b1, 0.f);
                    *(float2*)(smem + ((size_t)r * 128 + c) * 4) = make_float2(e0, e1);
                }
            }
    }
    __syncthreads();

    // logits (4 heads) + segment max
    {
        const int wid = tid >> 5, lane = tid & 31;
        const float* x2s = (const float*)smem;
        for (int rr = wid * 16; rr < wid * 16 + 16; rr++) {
            const int e = row0 + rr;
            if (e >= M) break;
            float p0 = 0.f, p1 = 0.f, p2 = 0.f, p3 = 0.f;
#pragma unroll
            for (int j = 0; j < 4; j++) {
                const int c = lane + j * 32;
                const float x = x2s[rr * 128 + c];
                p0 += x * wb3s[c];
                p1 += x * wb3s[128 + c];
                p2 += x * wb3s[256 + c];
                p3 += x * wb3s[384 + c];
            }
#pragma unroll
            for (int off = 16; off; off >>= 1) {
                p0 += __shfl_xor_sync(0xffffffffu, p0, off);
                p1 += __shfl_xor_sync(0xffffffffu, p1, off);
                p2 += __shfl_xor_sync(0xffffffffu, p2, off);
                p3 += __shfl_xor_sync(0xffffffffu, p3, off);
            }
            if (lane < 4) {
                const float p = (lane == 0) ? p0 : (lane == 1) ? p1 : (lane == 2) ? p2 : p3;
                const float l = (p + bb3[lane]) * 0.17677669529663687f;
                logit[(size_t)e * 4 + lane] = l;
                atomicMax(&gmax[eidx[e] * 4 + lane], fenc(l));
            }
        }
    }
}

// ---------------- fused B: v1 -> v2 -> V -> weighted aggregate ----------------
__global__ __launch_bounds__(256, 1)
void fusedB_kernel(const bf16* __restrict__ eh, const bf16* __restrict__ el,
                   const bf16* __restrict__ wv1h, const bf16* __restrict__ wv1l,
                   const float* __restrict__ bv1,
                   const bf16* __restrict__ wv2h, const bf16* __restrict__ wv2l,
                   const float* __restrict__ bv2,
                   const bf16* __restrict__ wv3h, const bf16* __restrict__ wv3l,
                   const float* __restrict__ bv3,
                   const int* __restrict__ eidx,
                   const float* __restrict__ gexp, const float* __restrict__ gsum,
                   float* __restrict__ hagg, int M)
{
    extern __shared__ char smem[];
    const uint32_t sb = smem_u32(smem);
    const int tid = threadIdx.x;
    const int row0 = blockIdx.x * 128;

    float* atts = (float*)(smem + 131072);
    int*   cens = (int*)(smem + 131072 + 2048);
    if (tid < 128) {
        const int e = row0 + tid;
        if (e < M) {
            const int c = eidx[e];
            cens[tid] = c;
#pragma unroll
            for (int h = 0; h < 4; h++)
                atts[tid * 4 + h] = gexp[(size_t)e * 4 + h] / gsum[c * 4 + h];
        }
    }

    float acc[2][8][4];
#pragma unroll
    for (int i = 0; i < 2; i++)
#pragma unroll
        for (int j = 0; j < 8; j++)
#pragma unroll
            for (int q = 0; q < 4; q++) acc[i][j][q] = 0.f;

    // v1 = gelu(hE @ Wv1 + bv1), K=256
    gemm_pipeline<0>(acc, sb, eh, el, nullptr, nullptr, nullptr, wv1h, wv1l, row0, 0, M, 256, tid);

    store_planes<2>(acc, smem, 0, bv1, tid);
    load_wplanes(sb + 65536, wv2h, wv2l, tid);
    __syncthreads();

    // v2 = gelu(v1 @ Wv2 + bv2)
    float acc2[2][8][4];
#pragma unroll
    for (int i = 0; i < 2; i++)
#pragma unroll
        for (int j = 0; j < 8; j++)
#pragma unroll
            for (int q = 0; q < 4; q++) acc2[i][j][q] = 0.f;
    gemm_smem2(acc2, sb, sb + 65536, tid);
    __syncthreads();

    // v2 planes -> [0,64K); Wv3 planes -> [64K,128K)
    store_planes<2>(acc2, smem, 0, bv2, tid);
    load_wplanes(sb + 65536, wv3h, wv3l, tid);
    __syncthreads();

    // V = v2 @ Wv3 (+bv3 applied below)
    float acc3[2][8][4];
#pragma unroll
    for (int i = 0; i < 2; i++)
#pragma unroll
        for (int j = 0; j < 8; j++)
#pragma unroll
            for (int q = 0; q < 4; q++) acc3[i][j][q] = 0.f;
    gemm_smem2(acc3, sb, sb + 65536, tid);

    // weighted aggregate: hagg[center] += att * (V + bv3)
    {
        const int wid = tid >> 5, lane = tid & 31;
        const int wm = wid >> 1, wn = wid & 1;
#pragma unroll
        for (int mt = 0; mt < 2; mt++)
#pragma unroll
            for (int nt = 0; nt < 8; nt++) {
                const int c = wn * 64 + nt * 8 + (lane & 3) * 2;
                const int h = c >> 5;
                const float b0 = bv3[c], b1 = bv3[c + 1];
#pragma unroll
                for (int half = 0; half < 2; half++) {
                    const int rr = wm * 32 + mt * 16 + (lane >> 2) + half * 8;
                    if (row0 + rr < M) {
                        const float a = atts[rr * 4 + h];
                        float* dst = hagg + (size_t)cens[rr] * 128 + c;
                        atomicAdd(dst,     (acc3[mt][nt][half * 2] + b0) * a);
                        atomicAdd(dst + 1, (acc3[mt][nt][half * 2 + 1] + b1) * a);
                    }
                }
            }
    }
}

// ---------------- exp + segment sum ----------------
__global__ void expsum_kernel(float* __restrict__ logit, const int* __restrict__ center,
                              const unsigned* __restrict__ gmax, float* __restrict__ gsum, int E)
{
    int idx = blockIdx.x * 256 + threadIdx.x;
    if (idx >= E * 4) return;
    int e = idx >> 2, h = idx & 3;
    int c = center[e];
    float m = fdec(gmax[c * 4 + h]);
    float ex = expf(logit[idx] - m);
    logit[idx] = ex;
    atomicAdd(&gsum[c * 4 + h], ex);
}

// ---------------- host launch ----------------
extern "C" void kernel_launch(void* const* d_in, const int* in_sizes, int n_in,
                              void* d_out, int out_size)
{
    const float* h_V   = (const float*)d_in[0];
    const float* h_E   = (const float*)d_in[1];
    const int*   eidx  = (const int*)  d_in[2];
    const float* hvv   = (const float*)d_in[3];
    const float* frame = (const float*)d_in[4];
    const float* W_vec = (const float*)d_in[5];
    const float* W_red = (const float*)d_in[6];
    const float* Wb1   = (const float*)d_in[7];
    const float* bb1   = (const float*)d_in[8];
    const float* Wb2   = (const float*)d_in[9];
    const float* bb2   = (const float*)d_in[10];
    const float* Wb3   = (const float*)d_in[11];
    const float* bb3   = (const float*)d_in[12];
    const float* Wv1   = (const float*)d_in[13];
    const float* bv1   = (const float*)d_in[14];
    const float* Wv2   = (const float*)d_in[15];
    const float* bv2   = (const float*)d_in[16];
    const float* Wv3   = (const float*)d_in[17];
    const float* bv3   = (const float*)d_in[18];
    const float* W_O   = (const float*)d_in[19];
    const float* bn_g  = (const float*)d_in[20];
    const float* bn_b  = (const float*)d_in[21];

    int E = in_sizes[2] / 2;
    int N = in_sizes[0] / 128;
    float* out = (float*)d_out;

    float *vff, *logit, *gsum, *hagg, *bnst;
    bf16 *vffh, *vffl, *hEh, *hEl, *eh, *el, *hVh, *hVl, *hgh, *hgl, *wh, *wl;
    unsigned* gmax;
    double* bnacc;
    cudaGetSymbolAddress((void**)&vff,   g_vff);
    cudaGetSymbolAddress((void**)&vffh,  g_vffh);
    cudaGetSymbolAddress((void**)&vffl,  g_vffl);
    cudaGetSymbolAddress((void**)&hEh,   g_hEh);
    cudaGetSymbolAddress((void**)&hEl,   g_hEl);
    cudaGetSymbolAddress((void**)&eh,    g_eh);
    cudaGetSymbolAddress((void**)&el,    g_el);
    cudaGetSymbolAddress((void**)&hVh,   g_hVh);
    cudaGetSymbolAddress((void**)&hVl,   g_hVl);
    cudaGetSymbolAddress((void**)&hgh,   g_hgh);
    cudaGetSymbolAddress((void**)&hgl,   g_hgl);
    cudaGetSymbolAddress((void**)&wh,    g_wh);
    cudaGetSymbolAddress((void**)&wl,    g_wl);
    cudaGetSymbolAddress((void**)&logit, g_logit);
    cudaGetSymbolAddress((void**)&gmax,  g_max);
    cudaGetSymbolAddress((void**)&gsum,  g_sum);
    cudaGetSymbolAddress((void**)&hagg,  g_hagg);
    cudaGetSymbolAddress((void**)&bnacc, g_bnacc);
    cudaGetSymbolAddress((void**)&bnst,  g_bnst);

    const int SMEM   = 131072;
    const int SMEM_A = 131072 + 2048;
    const int SMEM_B = 131072 + 2048 + 512;
    cudaFuncSetAttribute(hmma_gemm<1, 2, 256>, cudaFuncAttributeMaxDynamicSharedMemorySize, SMEM);
    cudaFuncSetAttribute(hmma_gemm<0, 1, 128>, cudaFuncAttributeMaxDynamicSharedMemorySize, SMEM);
    cudaFuncSetAttribute(fusedA_kernel, cudaFuncAttributeMaxDynamicSharedMemorySize, SMEM_A);
    cudaFuncSetAttribute(fusedB_kernel, cudaFuncAttributeMaxDynamicSharedMemorySize, SMEM_B);

    int Mt = (E + 127) / 128;
    int Mo = (N + 127) / 128;

    init_kernel<<<(N * 128 + 255) / 256, 256>>>(gmax, gsum, hagg, bnacc, N);
    geom_kernel<<<(E + 255) / 256, 256>>>(eidx, hvv, frame, W_vec, vff, bnacc, E);
    bn_finalize<<<1, 32>>>(bnacc, bn_g, bn_b, bnst, E);

    // conversions
    wprep_all<<<(W_TOTAL + 255) / 256, 256>>>(W_red, Wb1, Wb2, Wv1, Wv2, Wv3, W_O, wh, wl);
    c2planes<<<(int)(((size_t)E * 256 + 255) / 256), 256>>>(h_E, hEh, hEl, (size_t)E * 256);
    c2planes<<<(N * 128 + 255) / 256, 256>>>(h_V, hVh, hVl, (size_t)N * 128);
    vffprep<<<(int)(((size_t)E * 64 + 255) / 256), 256>>>(vff, bnst, vffh, vffl, E);

    // hE = [vff_bn | h_E] @ W_red  -> planes
    hmma_gemm<1, 2, 256><<<dim3(2, Mt), 256, SMEM>>>(
        vffh, vffl, hEh, hEl, nullptr, wh + OW_RED, wl + OW_RED,
        nullptr, eh, el, E, 320);
    // fused A: x1 -> x2 -> logits + segment max
    fusedA_kernel<<<Mt, 256, SMEM_A>>>(
        hVh, hVl, eh, el, eidx,
        wh + OW_B1, wl + OW_B1, bb1,
        wh + OW_B2, wl + OW_B2, bb2,
        Wb3, bb3, logit, gmax, E);
    // exp + segment sum
    expsum_kernel<<<(E * 4 + 255) / 256, 256>>>(logit, eidx, gmax, gsum, E);
    // fused B: v1 -> v2 -> V -> weighted aggregate
    fusedB_kernel<<<Mt, 256, SMEM_B>>>(
        eh, el,
        wh + OW_V1, wl + OW_V1, bv1,
        wh + OW_V2, wl + OW_V2, bv2,
        wh + OW_V3, wl + OW_V3, bv3,
        eidx, logit, gsum, hagg, E);
    // hagg -> planes, then out = hagg @ W_O
    c2planes<<<(N * 128 + 255) / 256, 256>>>(hagg, hgh, hgl, (size_t)N * 128);
    hmma_gemm<0, 1, 128><<<dim3(1, Mo), 256, SMEM>>>(
        hgh, hgl, nullptr, nullptr, nullptr, wh + OW_O, wl + OW_O,
        out, nullptr, nullptr, N, 128);
}

// round 5
// speedup vs baseline: 2.7369x; 1.0521x over previous
#include <cuda_runtime.h>
#include <cuda_bf16.h>
#include <math.h>
#include <stdint.h>

#define E_CONST 320000
#define N_CONST 10000
typedef __nv_bfloat16 bf16;

// ---------------- scratch (no allocations allowed) ----------------
static __device__ float    g_vff [(size_t)E_CONST * 64];       // fp32 [sincos48|dist16]
static __device__ bf16     g_eh  [(size_t)E_CONST * 256];      // hE (W_red out) planes
static __device__ bf16     g_el  [(size_t)E_CONST * 256];
static __device__ bf16     g_hVh [N_CONST * 128];
static __device__ bf16     g_hVl [N_CONST * 128];
static __device__ bf16     g_hgh [N_CONST * 128];
static __device__ bf16     g_hgl [N_CONST * 128];
static __device__ bf16     g_wh  [262144];                     // all weights, [n][k]
static __device__ bf16     g_wl  [262144];
static __device__ float    g_logit[(size_t)E_CONST * 4];
static __device__ unsigned g_max [N_CONST * 4];
static __device__ float    g_sum [N_CONST * 4];
static __device__ float    g_hagg[N_CONST * 128];
static __device__ double   g_bnacc[32];
static __device__ float    g_bnst[32];

// weight plane offsets (elements)
#define OW_RED 0        // 256 x 320
#define OW_B1  81920    // 128 x 384
#define OW_B2  131072   // 128 x 128
#define OW_V1  147456   // 128 x 256
#define OW_V2  180224   // 128 x 128
#define OW_V3  196608   // 128 x 128
#define OW_O   212992   // 128 x 128
#define W_TOTAL 229376

// ---------------- helpers ----------------
__device__ __forceinline__ uint32_t smem_u32(const void* p) {
    uint32_t a;
    asm("{ .reg .u64 t; cvta.to.shared.u64 t, %1; cvt.u32.u64 %0, t; }" : "=r"(a) : "l"(p));
    return a;
}
__device__ __forceinline__ void cp16(uint32_t dst, const void* src) {
    asm volatile("cp.async.cg.shared.global [%0], [%1], 16;"
        :: "r"(dst), "l"(__cvta_generic_to_global(src)) : "memory");
}
#define CP_COMMIT() asm volatile("cp.async.commit_group;" ::: "memory")
#define CP_WAIT(n)  asm volatile("cp.async.wait_group %0;" :: "n"(n) : "memory")

__device__ __forceinline__ void ldsm4(uint32_t* r, uint32_t addr) {
    asm volatile("ldmatrix.sync.aligned.m8n8.x4.shared.b16 {%0,%1,%2,%3}, [%4];"
        : "=r"(r[0]), "=r"(r[1]), "=r"(r[2]), "=r"(r[3]) : "r"(addr));
}
__device__ __forceinline__ void mma16816(float* d, const uint32_t* a, const uint32_t* b) {
    asm volatile(
        "mma.sync.aligned.m16n8k16.row.col.f32.bf16.bf16.f32 "
        "{%0,%1,%2,%3}, {%4,%5,%6,%7}, {%8,%9}, {%0,%1,%2,%3};"
        : "+f"(d[0]), "+f"(d[1]), "+f"(d[2]), "+f"(d[3])
        : "r"(a[0]), "r"(a[1]), "r"(a[2]), "r"(a[3]), "r"(b[0]), "r"(b[1]));
}
__device__ __forceinline__ unsigned fenc(float f) {
    unsigned u = __float_as_uint(f);
    return (u & 0x80000000u) ? ~u : (u | 0x80000000u);
}
__device__ __forceinline__ float fdec(unsigned u) {
    return (u & 0x80000000u) ? __uint_as_float(u & 0x7FFFFFFFu) : __uint_as_float(~u);
}
__device__ __forceinline__ float gelu_f(float x) {
    return 0.5f * x * (1.f + erff(x * 0.70710678118654752f));
}

// ---------------- init ----------------
__global__ void init_kernel(unsigned* gmax, float* gsum, float* hagg, double* bnacc, int N)
{
    int i = blockIdx.x * 256 + threadIdx.x;
    if (i < N * 128) hagg[i] = 0.f;
    if (i < N * 4) { gmax[i] = 0x007FFFFFu; gsum[i] = 0.f; }
    if (i < 32) bnacc[i] = 0.0;
}

// ---------------- geometry + BN stats ----------------
__global__ __launch_bounds__(256)
void geom_kernel(const int* __restrict__ eidx, const float* __restrict__ hvv,
                 const float* __restrict__ frame, const float* __restrict__ Wvec,
                 float* __restrict__ vff, double* __restrict__ bnacc, int E)
{
    __shared__ float Ws[512];
    __shared__ float bsum[16], bsq[16];
    int tid = threadIdx.x;
    for (int i = tid; i < 512; i += 256) Ws[i] = Wvec[i];
    if (tid < 16) { bsum[tid] = 0.f; bsq[tid] = 0.f; }
    __syncthreads();

    int e = blockIdx.x * 256 + tid;
    float dloc[16];
#pragma unroll
    for (int o = 0; o < 16; o++) dloc[o] = 0.f;

    if (e < E) {
        int c = eidx[e];
        int d = eidx[E + e];
        float F[9];
#pragma unroll
        for (int i = 0; i < 9; i++) F[i] = frame[e * 9 + i];
        float vdt[48], vsrc[48];
#pragma unroll
        for (int v = 0; v < 16; v++) {
            float x = hvv[d * 48 + v * 3 + 0];
            float y = hvv[d * 48 + v * 3 + 1];
            float z = hvv[d * 48 + v * 3 + 2];
            vdt[v * 3 + 0] = F[0] * x + F[1] * y + F[2] * z;
            vdt[v * 3 + 1] = F[3] * x + F[4] * y + F[5] * z;
            vdt[v * 3 + 2] = F[6] * x + F[7] * y + F[8] * z;
        }
#pragma unroll
        for (int i = 0; i < 48; i++) vsrc[i] = hvv[c * 48 + i];

#pragma unroll
        for (int o = 0; o < 16; o++) {
            float v0 = vdt[o * 3 + 0], v1 = vdt[o * 3 + 1], v2 = vdt[o * 3 + 2];
#pragma unroll
            for (int v = 0; v < 16; v++) {
                float wa = Ws[o * 32 + v], wb = Ws[o * 32 + 16 + v];
                v0 += wa * vdt[v * 3 + 0] + wb * vsrc[v * 3 + 0];
                v1 += wa * vdt[v * 3 + 1] + wb * vsrc[v * 3 + 1];
                v2 += wa * vdt[v * 3 + 2] + wb * vsrc[v * 3 + 2];
            }
            float dist = sqrtf(v0 * v0 + v1 * v1 + v2 * v2) + 1e-6f;
            float inv = 1.f / dist;
            vff[e * 64 + o * 3 + 0] = v0 * inv;
            vff[e * 64 + o * 3 + 1] = v1 * inv;
            vff[e * 64 + o * 3 + 2] = v2 * inv;
            vff[e * 64 + 48 + o] = dist;
            dloc[o] = dist;
        }
    }

#pragma unroll
    for (int o = 0; o < 16; o++) {
        float v = dloc[o], v2 = v * v;
#pragma unroll
        for (int off = 16; off; off >>= 1) {
            v  += __shfl_down_sync(0xffffffffu, v, off);
            v2 += __shfl_down_sync(0xffffffffu, v2, off);
        }
        if ((tid & 31) == 0) { atomicAdd(&bsum[o], v); atomicAdd(&bsq[o], v2); }
    }
    __syncthreads();
    if (tid < 16) {
        atomicAdd(&bnacc[tid], (double)bsum[tid]);
        atomicAdd(&bnacc[16 + tid], (double)bsq[tid]);
    }
}

__global__ void bn_finalize(const double* __restrict__ acc, const float* __restrict__ g,
                            const float* __restrict__ b, float* __restrict__ st, int E)
{
    int i = threadIdx.x;
    if (i >= 16) return;
    double mean = acc[i] / (double)E;
    double var  = acc[16 + i] / (double)E - mean * mean;
    float s = (float)((double)g[i] / sqrt(var + 1e-5));
    st[i] = s;
    st[16 + i] = b[i] - (float)mean * s;
}

// ---------------- conversion passes ----------------
__global__ void wprep_all(const float* __restrict__ W0, const float* __restrict__ W1,
                          const float* __restrict__ W2, const float* __restrict__ W3,
                          const float* __restrict__ W4, const float* __restrict__ W5,
                          const float* __restrict__ W6,
                          bf16* __restrict__ hi, bf16* __restrict__ lo)
{
    int idx = blockIdx.x * 256 + threadIdx.x;
    if (idx >= W_TOTAL) return;
    const float* src; int K, NT, start;
    if      (idx < OW_B1)  { src = W0; K = 320; NT = 256; start = OW_RED; }
    else if (idx < OW_B2)  { src = W1; K = 384; NT = 128; start = OW_B1; }
    else if (idx < OW_V1)  { src = W2; K = 128; NT = 128; start = OW_B2; }
    else if (idx < OW_V2)  { src = W3; K = 256; NT = 128; start = OW_V1; }
    else if (idx < OW_V3)  { src = W4; K = 128; NT = 128; start = OW_V2; }
    else if (idx < OW_O)   { src = W5; K = 128; NT = 128; start = OW_V3; }
    else                   { src = W6; K = 128; NT = 128; start = OW_O; }
    int local = idx - start;
    int k = local / NT, n = local % NT;
    float v = src[local];
    bf16 h = __float2bfloat16_rn(v);
    hi[start + (size_t)n * K + k] = h;
    lo[start + (size_t)n * K + k] = __float2bfloat16_rn(v - __bfloat162float(h));
}

__global__ void c2planes(const float* __restrict__ x, bf16* __restrict__ hi,
                         bf16* __restrict__ lo, size_t n)
{
    size_t i = (size_t)blockIdx.x * 256 + threadIdx.x;
    if (i >= n) return;
    float v = x[i];
    bf16 h = __float2bfloat16_rn(v);
    hi[i] = h;
    lo[i] = __float2bfloat16_rn(v - __bfloat162float(h));
}

// ================= GEMM building blocks =================
// Global-pipelined GEMM producing per-warp acc[2][8][4], 128x128 tile, 8 warps (4m x 2n).
// MODE 0: A = (Ahi,Alo) stride K
// MODE 2: k0<128 -> gathered (Ahi,Alo)[gidx[row]] stride 128; else A2 planes stride 256 at k0-128
template<int MODE>
__device__ __forceinline__ void gemm_pipeline(
    float acc[2][8][4], uint32_t sb,
    const bf16* __restrict__ Ahi, const bf16* __restrict__ Alo,
    const bf16* __restrict__ A2hi, const bf16* __restrict__ A2lo,
    const int* __restrict__ gidx,
    const bf16* __restrict__ Bhi, const bf16* __restrict__ Blo,
    int row0, int col0, int M, int K, int tid)
{
    const int lane = tid & 31;
    const int wid = tid >> 5;

    const int lr = tid >> 1;
    const int u0 = (tid & 1) * 4;
    const int arow = (row0 + lr < M) ? (row0 + lr) : (M - 1);
    int gr = 0;
    if (MODE == 2) gr = gidx[arow];
    const int brow = col0 + lr;

    const int nk = K >> 6;

    auto issue = [&](int kc, int st) {
        const int k0 = kc << 6;
        const bf16 *pah, *pal;
        if (MODE == 0) {
            pah = Ahi + (size_t)arow * K + k0;
            pal = Alo + (size_t)arow * K + k0;
        } else {
            if (k0 < 128) { pah = Ahi + (size_t)gr * 128 + k0; pal = Alo + (size_t)gr * 128 + k0; }
            else { pah = A2hi + (size_t)arow * 256 + (k0 - 128); pal = A2lo + (size_t)arow * 256 + (k0 - 128); }
        }
        const bf16* pbh = Bhi + (size_t)brow * K + k0;
        const bf16* pbl = Blo + (size_t)brow * K + k0;

        const uint32_t stbase = sb + st * 65536;
        const uint32_t rowoff = lr * 128;
        const int sw = lr & 7;
#pragma unroll
        for (int i = 0; i < 4; i++) {
            const int u = u0 + i;
            const uint32_t d = rowoff + (uint32_t)((u ^ sw) << 4);
            cp16(stbase +         d, (const char*)pah + u * 16);
            cp16(stbase + 16384 + d, (const char*)pal + u * 16);
            cp16(stbase + 32768 + d, (const char*)pbh + u * 16);
            cp16(stbase + 49152 + d, (const char*)pbl + u * 16);
        }
        CP_COMMIT();
    };

    const int wm = wid >> 1;
    const int wn = wid & 1;
    const int a_row = wm * 32 + (lane & 7) + ((lane & 8) ? 8 : 0);
    const int a_ub  = (lane & 16) ? 1 : 0;
    const int b_rowb = wn * 64 + (lane & 7) + ((lane & 16) ? 8 : 0);
    const int b_ub  = (lane & 8) ? 1 : 0;

    issue(0, 0);
    for (int kc = 0; kc < nk; kc++) {
        if (kc + 1 < nk) { issue(kc + 1, (kc + 1) & 1); CP_WAIT(1); }
        else             { CP_WAIT(0); }
        __syncthreads();

        const uint32_t stbase = sb + (kc & 1) * 65536;
#pragma unroll
        for (int ks = 0; ks < 4; ks++) {
            uint32_t ahi[2][4], alo[2][4];
#pragma unroll
            for (int mt = 0; mt < 2; mt++) {
                const int r = a_row + mt * 16;
                const int u = ks * 2 + a_ub;
                const uint32_t off = r * 128 + (uint32_t)(((u ^ (r & 7))) << 4);
                ldsm4(ahi[mt], stbase + off);
                ldsm4(alo[mt], stbase + 16384 + off);
            }
            uint32_t bhi[4][4], blo[4][4];
#pragma unroll
            for (int g = 0; g < 4; g++) {
                const int n = b_rowb + g * 16;
                const int u = ks * 2 + b_ub;
                const uint32_t off = n * 128 + (uint32_t)(((u ^ (n & 7))) << 4);
                ldsm4(bhi[g], stbase + 32768 + off);
                ldsm4(blo[g], stbase + 49152 + off);
            }
#pragma unroll
            for (int mt = 0; mt < 2; mt++)
#pragma unroll
                for (int nt = 0; nt < 8; nt++) {
                    float* a_ = acc[mt][nt];
                    const uint32_t* bh = &bhi[nt >> 1][(nt & 1) * 2];
                    const uint32_t* bl = &blo[nt >> 1][(nt & 1) * 2];
                    mma16816(a_, ahi[mt], bh);
                    mma16816(a_, ahi[mt], bl);
                    mma16816(a_, alo[mt], bh);
                }
        }
        __syncthreads();
    }
}

// smem-resident GEMM: A planes at aB, B planes at bB (layout: hi c0|hi c1 (16KB ea), lo at +32768)
__device__ __forceinline__ void gemm_smem2(float acc[2][8][4], uint32_t aB, uint32_t bB, int tid)
{
    const int wid = tid >> 5, lane = tid & 31;
    const int wm = wid >> 1, wn = wid & 1;
    const int a_row = wm * 32 + (lane & 7) + ((lane & 8) ? 8 : 0);
    const int a_ub  = (lane & 16) ? 1 : 0;
    const int b_rowb = wn * 64 + (lane & 7) + ((lane & 16) ? 8 : 0);
    const int b_ub  = (lane & 8) ? 1 : 0;
#pragma unroll
    for (int kc = 0; kc < 2; kc++) {
#pragma unroll
        for (int ks = 0; ks < 4; ks++) {
            uint32_t ahi[2][4], alo[2][4];
#pragma unroll
            for (int mt = 0; mt < 2; mt++) {
                const int r = a_row + mt * 16;
                const int u = ks * 2 + a_ub;
                const uint32_t off = kc * 16384 + r * 128 + (uint32_t)(((u ^ (r & 7))) << 4);
                ldsm4(ahi[mt], aB + off);
                ldsm4(alo[mt], aB + 32768 + off);
            }
            uint32_t bhi[4][4], blo[4][4];
#pragma unroll
            for (int g = 0; g < 4; g++) {
                const int n = b_rowb + g * 16;
                const int u = ks * 2 + b_ub;
                const uint32_t off = kc * 16384 + n * 128 + (uint32_t)(((u ^ (n & 7))) << 4);
                ldsm4(bhi[g], bB + off);
                ldsm4(blo[g], bB + 32768 + off);
            }
#pragma unroll
            for (int mt = 0; mt < 2; mt++)
#pragma unroll
                for (int nt = 0; nt < 8; nt++) {
                    float* a_ = acc[mt][nt];
                    const uint32_t* bh = &bhi[nt >> 1][(nt & 1) * 2];
                    const uint32_t* bl = &blo[nt >> 1][(nt & 1) * 2];
                    mma16816(a_, ahi[mt], bh);
                    mma16816(a_, ahi[mt], bl);
                    mma16816(a_, alo[mt], bh);
                }
        }
    }
}

// load 128x128 weight planes into smem chunk layout (hi c0|hi c1|lo c0|lo c1)
__device__ __forceinline__ void load_wplanes(uint32_t dst, const bf16* __restrict__ Whi,
                                             const bf16* __restrict__ Wlo, int tid)
{
    for (int i = tid; i < 2048; i += 256) {
        const int kc = i >> 10;
        const int rem = i & 1023;
        const int row = rem >> 3, u = rem & 7;
        const uint32_t d = kc * 16384 + row * 128 + (uint32_t)(((u ^ (row & 7))) << 4);
        cp16(dst +         d, (const char*)(Whi + (size_t)row * 128 + kc * 64) + u * 16);
        cp16(dst + 32768 + d, (const char*)(Wlo + (size_t)row * 128 + kc * 64) + u * 16);
    }
    CP_COMMIT();
    CP_WAIT(0);
}

// store fragments -> smem bf16 hi/lo planes (with bias + activation)
template<int ACT>
__device__ __forceinline__ void store_planes(const float acc[2][8][4], char* smemp, uint32_t base,
                                             const float* __restrict__ bias, int tid)
{
    const int wid = tid >> 5, lane = tid & 31;
    const int wm = wid >> 1, wn = wid & 1;
#pragma unroll
    for (int mt = 0; mt < 2; mt++)
#pragma unroll
        for (int nt = 0; nt < 8; nt++) {
            const int c = wn * 64 + nt * 8 + (lane & 3) * 2;
            const int kc = c >> 6, kk = c & 63, u = kk >> 3;
            const float b0 = bias[c], b1 = bias[c + 1];
#pragma unroll
            for (int half = 0; half < 2; half++) {
                const int r = wm * 32 + mt * 16 + (lane >> 2) + half * 8;
                float e0 = acc[mt][nt][half * 2] + b0;
                float e1 = acc[mt][nt][half * 2 + 1] + b1;
                if (ACT == 1) { e0 = fmaxf(e0, 0.f); e1 = fmaxf(e1, 0.f); }
                if (ACT == 2) { e0 = gelu_f(e0); e1 = gelu_f(e1); }
                bf16 h0 = __float2bfloat16_rn(e0);
                bf16 h1 = __float2bfloat16_rn(e1);
                __nv_bfloat162 hp; hp.x = h0; hp.y = h1;
                __nv_bfloat162 lp;
                lp.x = __float2bfloat16_rn(e0 - __bfloat162float(h0));
                lp.y = __float2bfloat16_rn(e1 - __bfloat162float(h1));
                const uint32_t ad = base + kc * 16384 + r * 128 +
                                    (uint32_t)(((u ^ (r & 7))) << 4) + (kk & 7) * 2;
                *(__nv_bfloat162*)(smemp + ad) = hp;
                *(__nv_bfloat162*)(smemp + 32768 + ad) = lp;
            }
        }
}

// ---------------- W_red GEMM with in-loader fp32 -> plane conversion ----------------
// A = [ vff(48 sincos | 16 dist, BN applied here) | h_E(256) ] fp32; W planes. K=320.
// smem: stage0 [0,64K): Af32 32K | Bhi 16K | Blo 16K ; stage1 [64K,128K);
//       Aplanes [128K,160K): hi 16K | lo 16K
__global__ __launch_bounds__(256, 1)
void hmma_gemm_cvt(const float* __restrict__ Vff, const float* __restrict__ HE,
                   const float* __restrict__ bn_st,
                   const bf16* __restrict__ Bhi, const bf16* __restrict__ Blo,
                   bf16* __restrict__ Chi, bf16* __restrict__ Clo, int M)
{
    extern __shared__ char smem[];
    const uint32_t sb = smem_u32(smem);
    const int tid = threadIdx.x;
    const int wid = tid >> 5, lane = tid & 31;
    const int row0 = blockIdx.y * 128;
    const int col0 = blockIdx.x * 128;
    constexpr int K = 320;
    constexpr int nk = 5;

    const int lr = tid >> 1;
    const int arow = (row0 + lr < M) ? (row0 + lr) : (M - 1);
    const int brow = col0 + lr;

    auto issue = [&](int kc, int st) {
        const int k0 = kc << 6;
        const float* pa = (k0 == 0) ? (Vff + (size_t)arow * 64)
                                    : (HE + (size_t)arow * 256 + (k0 - 64));
        const bf16* pbh = Bhi + (size_t)brow * K + k0;
        const bf16* pbl = Blo + (size_t)brow * K + k0;
        const uint32_t stb = sb + st * 65536;
        // A fp32: 256B/row, 16 units; this thread does 8
        const int au0 = (tid & 1) * 8;
        const uint32_t aro = lr * 256;
#pragma unroll
        for (int i = 0; i < 8; i++) {
            const int u = au0 + i;
            cp16(stb + aro + (uint32_t)((u ^ (lr & 15)) << 4), (const char*)pa + u * 16);
        }
        const int bu0 = (tid & 1) * 4;
        const uint32_t bro = lr * 128;
        const int sw = lr & 7;
#pragma unroll
        for (int i = 0; i < 4; i++) {
            const int u = bu0 + i;
            const uint32_t d = bro + (uint32_t)((u ^ sw) << 4);
            cp16(stb + 32768 + d, (const char*)pbh + u * 16);
            cp16(stb + 49152 + d, (const char*)pbl + u * 16);
        }
        CP_COMMIT();
    };

    float acc[2][8][4];
#pragma unroll
    for (int i = 0; i < 2; i++)
#pragma unroll
        for (int j = 0; j < 8; j++)
#pragma unroll
            for (int q = 0; q < 4; q++) acc[i][j][q] = 0.f;

    const int wm = wid >> 1;
    const int wn = wid & 1;
    const int a_row = wm * 32 + (lane & 7) + ((lane & 8) ? 8 : 0);
    const int a_ub  = (lane & 16) ? 1 : 0;
    const int b_rowb = wn * 64 + (lane & 7) + ((lane & 16) ? 8 : 0);
    const int b_ub  = (lane & 8) ? 1 : 0;

    issue(0, 0);
    for (int kc = 0; kc < nk; kc++) {
        if (kc + 1 < nk) { issue(kc + 1, (kc + 1) & 1); CP_WAIT(1); }
        else             { CP_WAIT(0); }
        __syncthreads();

        // ---- convert A fp32 -> hi/lo planes ----
        {
            const int crow = tid >> 1;
            const int cu0 = (tid & 1) * 8;
            const char* stg = smem + (kc & 1) * 65536;
#pragma unroll
            for (int jj = 0; jj < 4; jj++) {
                const int ua = cu0 + jj * 2;
                float4 f0 = *(const float4*)(stg + crow * 256 + (uint32_t)((ua ^ (crow & 15)) << 4));
                float4 f1 = *(const float4*)(stg + crow * 256 + (uint32_t)(((ua + 1) ^ (crow & 15)) << 4));
                float v[8] = {f0.x, f0.y, f0.z, f0.w, f1.x, f1.y, f1.z, f1.w};
                if (kc == 0 && ua >= 12) {  // cols >= 48: BN affine
#pragma unroll
                    for (int j = 0; j < 8; j++) {
                        const int col = ua * 4 + j;
                        v[j] = fmaf(v[j], bn_st[col - 48], bn_st[col - 32]);
                    }
                }
                uint32_t ph[4], pl[4];
#pragma unroll
                for (int j = 0; j < 4; j++) {
                    float a = v[2 * j], b = v[2 * j + 1];
                    bf16 ha = __float2bfloat16_rn(a);
                    bf16 hb = __float2bfloat16_rn(b);
                    __nv_bfloat162 hp; hp.x = ha; hp.y = hb;
                    __nv_bfloat162 lp;
                    lp.x = __float2bfloat16_rn(a - __bfloat162float(ha));
                    lp.y = __float2bfloat16_rn(b - __bfloat162float(hb));
                    ph[j] = reinterpret_cast<uint32_t&>(hp);
                    pl[j] = reinterpret_cast<uint32_t&>(lp);
                }
                const int un = ua >> 1;
                const uint32_t ad = crow * 128 + (uint32_t)(((un ^ (crow & 7))) << 4);
                *(uint4*)(smem + 131072 + ad) = make_uint4(ph[0], ph[1], ph[2], ph[3]);
                *(uint4*)(smem + 147456 + ad) = make_uint4(pl[0], pl[1], pl[2], pl[3]);
            }
        }
        __syncthreads();

        const uint32_t stbase = sb + (kc & 1) * 65536;
#pragma unroll
        for (int ks = 0; ks < 4; ks++) {
            uint32_t ahi[2][4], alo[2][4];
#pragma unroll
            for (int mt = 0; mt < 2; mt++) {
                const int r = a_row + mt * 16;
                const int u = ks * 2 + a_ub;
                const uint32_t off = r * 128 + (uint32_t)(((u ^ (r & 7))) << 4);
                ldsm4(ahi[mt], sb + 131072 + off);
                ldsm4(alo[mt], sb + 147456 + off);
            }
            uint32_t bhi[4][4], blo[4][4];
#pragma unroll
            for (int g = 0; g < 4; g++) {
                const int n = b_rowb + g * 16;
                const int u = ks * 2 + b_ub;
                const uint32_t off = n * 128 + (uint32_t)(((u ^ (n & 7))) << 4);
                ldsm4(bhi[g], stbase + 32768 + off);
                ldsm4(blo[g], stbase + 49152 + off);
            }
#pragma unroll
            for (int mt = 0; mt < 2; mt++)
#pragma unroll
                for (int nt = 0; nt < 8; nt++) {
                    float* a_ = acc[mt][nt];
                    const uint32_t* bh = &bhi[nt >> 1][(nt & 1) * 2];
                    const uint32_t* bl = &blo[nt >> 1][(nt & 1) * 2];
                    mma16816(a_, ahi[mt], bh);
                    mma16816(a_, ahi[mt], bl);
                    mma16816(a_, alo[mt], bh);
                }
        }
        __syncthreads();
    }

    // ---- epilogue: write hE planes (NTC=256) ----
#pragma unroll
    for (int mt = 0; mt < 2; mt++) {
        const int r = row0 + wm * 32 + mt * 16 + (lane >> 2);
#pragma unroll
        for (int nt = 0; nt < 8; nt++) {
            const int c = col0 + wn * 64 + nt * 8 + (lane & 3) * 2;
#pragma unroll
            for (int half = 0; half < 2; half++) {
                const int rr = r + half * 8;
                if (rr >= M) continue;
                const float e0 = acc[mt][nt][half * 2];
                const float e1 = acc[mt][nt][half * 2 + 1];
                bf16 h0 = __float2bfloat16_rn(e0);
                bf16 h1 = __float2bfloat16_rn(e1);
                __nv_bfloat162 hp; hp.x = h0; hp.y = h1;
                __nv_bfloat162 lp;
                lp.x = __float2bfloat16_rn(e0 - __bfloat162float(h0));
                lp.y = __float2bfloat16_rn(e1 - __bfloat162float(h1));
                *(__nv_bfloat162*)(Chi + (size_t)rr * 256 + c) = hp;
                *(__nv_bfloat162*)(Clo + (size_t)rr * 256 + c) = lp;
            }
        }
    }
}

// ---------------- standalone GEMM (W_O) ----------------
__global__ __launch_bounds__(256, 1)
void hmma_gemm_o(const bf16* __restrict__ Ahi, const bf16* __restrict__ Alo,
                 const bf16* __restrict__ Bhi, const bf16* __restrict__ Blo,
                 float* __restrict__ Cf, int M)
{
    extern __shared__ char smem[];
    const uint32_t sb = smem_u32(smem);
    const int tid = threadIdx.x;
    const int wid = tid >> 5, lane = tid & 31;
    const int row0 = blockIdx.y * 128;

    float acc[2][8][4];
#pragma unroll
    for (int i = 0; i < 2; i++)
#pragma unroll
        for (int j = 0; j < 8; j++)
#pragma unroll
            for (int q = 0; q < 4; q++) acc[i][j][q] = 0.f;

    gemm_pipeline<0>(acc, sb, Ahi, Alo, nullptr, nullptr, nullptr, Bhi, Blo, row0, 0, M, 128, tid);

    const int wm = wid >> 1, wn = wid & 1;
#pragma unroll
    for (int mt = 0; mt < 2; mt++) {
        const int r = row0 + wm * 32 + mt * 16 + (lane >> 2);
#pragma unroll
        for (int nt = 0; nt < 8; nt++) {
            const int c = wn * 64 + nt * 8 + (lane & 3) * 2;
#pragma unroll
            for (int half = 0; half < 2; half++) {
                const int rr = r + half * 8;
                if (rr >= M) continue;
                *(float2*)(Cf + (size_t)rr * 128 + c) =
                    make_float2(acc[mt][nt][half * 2], acc[mt][nt][half * 2 + 1]);
            }
        }
    }
}

// ---------------- fused A: x1 -> x2 -> logits(+segmax) ----------------
__global__ __launch_bounds__(256, 1)
void fusedA_kernel(const bf16* __restrict__ hVh, const bf16* __restrict__ hVl,
                   const bf16* __restrict__ eh, const bf16* __restrict__ el,
                   const int* __restrict__ eidx,
                   const bf16* __restrict__ wb1h, const bf16* __restrict__ wb1l,
                   const float* __restrict__ bb1,
                   const bf16* __restrict__ wb2h, const bf16* __restrict__ wb2l,
                   const float* __restrict__ bb2,
                   const float* __restrict__ Wb3, const float* __restrict__ bb3,
                   float* __restrict__ logit, unsigned* __restrict__ gmax, int M)
{
    extern __shared__ char smem[];
    const uint32_t sb = smem_u32(smem);
    const int tid = threadIdx.x;
    const int row0 = blockIdx.x * 128;

    float* wb3s = (float*)(smem + 131072);
    if (tid < 128) {
#pragma unroll
        for (int h = 0; h < 4; h++) wb3s[h * 128 + tid] = Wb3[tid * 8 + h];
    }

    float acc[2][8][4];
#pragma unroll
    for (int i = 0; i < 2; i++)
#pragma unroll
        for (int j = 0; j < 8; j++)
#pragma unroll
            for (int q = 0; q < 4; q++) acc[i][j][q] = 0.f;

    gemm_pipeline<2>(acc, sb, hVh, hVl, eh, el, eidx, wb1h, wb1l, row0, 0, M, 384, tid);

    store_planes<1>(acc, smem, 0, bb1, tid);
    load_wplanes(sb + 65536, wb2h, wb2l, tid);
    __syncthreads();

    float acc2[2][8][4];
#pragma unroll
    for (int i = 0; i < 2; i++)
#pragma unroll
        for (int j = 0; j < 8; j++)
#pragma unroll
            for (int q = 0; q < 4; q++) acc2[i][j][q] = 0.f;
    gemm_smem2(acc2, sb, sb + 65536, tid);
    __syncthreads();

    {
        const int wid = tid >> 5, lane = tid & 31;
        const int wm = wid >> 1, wn = wid & 1;
#pragma unroll
        for (int mt = 0; mt < 2; mt++)
#pragma unroll
            for (int nt = 0; nt < 8; nt++) {
                const int c = wn * 64 + nt * 8 + (lane & 3) * 2;
                const float b0 = bb2[c], b1 = bb2[c + 1];
#pragma unroll
                for (int half = 0; half < 2; half++) {
                    const int r = wm * 32 + mt * 16 + (lane >> 2) + half * 8;
                    float e0 = fmaxf(acc2[mt][nt][half * 2] + b0, 0.f);
                    float e1 = fmaxf(acc2[mt][nt][half * 2 + 1] + b1, 0.f);
                    *(float2*)(smem + ((size_t)r * 128 + c) * 4) = make_float2(e0, e1);
                }
            }
    }
    __syncthreads();

    {
        const int wid = tid >> 5, lane = tid & 31;
        const float* x2s = (const float*)smem;
        for (int rr = wid * 16; rr < wid * 16 + 16; rr++) {
            const int e = row0 + rr;
            if (e >= M) break;
            float p0 = 0.f, p1 = 0.f, p2 = 0.f, p3 = 0.f;
#pragma unroll
            for (int j = 0; j < 4; j++) {
                const int c = lane + j * 32;
                const float x = x2s[rr * 128 + c];
                p0 += x * wb3s[c];
                p1 += x * wb3s[128 + c];
                p2 += x * wb3s[256 + c];
                p3 += x * wb3s[384 + c];
            }
#pragma unroll
            for (int off = 16; off; off >>= 1) {
                p0 += __shfl_xor_sync(0xffffffffu, p0, off);
                p1 += __shfl_xor_sync(0xffffffffu, p1, off);
                p2 += __shfl_xor_sync(0xffffffffu, p2, off);
                p3 += __shfl_xor_sync(0xffffffffu, p3, off);
            }
            if (lane < 4) {
                const float p = (lane == 0) ? p0 : (lane == 1) ? p1 : (lane == 2) ? p2 : p3;
                const float l = (p + bb3[lane]) * 0.17677669529663687f;
                logit[(size_t)e * 4 + lane] = l;
                atomicMax(&gmax[eidx[e] * 4 + lane], fenc(l));
            }
        }
    }
}

// ---------------- fused B: v1 -> v2 -> V -> weighted aggregate ----------------
__global__ __launch_bounds__(256, 1)
void fusedB_kernel(const bf16* __restrict__ eh, const bf16* __restrict__ el,
                   const bf16* __restrict__ wv1h, const bf16* __restrict__ wv1l,
                   const float* __restrict__ bv1,
                   const bf16* __restrict__ wv2h, const bf16* __restrict__ wv2l,
                   const float* __restrict__ bv2,
                   const bf16* __restrict__ wv3h, const bf16* __restrict__ wv3l,
                   const float* __restrict__ bv3,
                   const int* __restrict__ eidx,
                   const float* __restrict__ gexp, const float* __restrict__ gsum,
                   float* __restrict__ hagg, int M)
{
    extern __shared__ char smem[];
    const uint32_t sb = smem_u32(smem);
    const int tid = threadIdx.x;
    const int row0 = blockIdx.x * 128;

    float* atts = (float*)(smem + 131072);
    int*   cens = (int*)(smem + 131072 + 2048);
    if (tid < 128) {
        const int e = row0 + tid;
        if (e < M) {
            const int c = eidx[e];
            cens[tid] = c;
#pragma unroll
            for (int h = 0; h < 4; h++)
                atts[tid * 4 + h] = gexp[(size_t)e * 4 + h] / gsum[c * 4 + h];
        }
    }

    float acc[2][8][4];
#pragma unroll
    for (int i = 0; i < 2; i++)
#pragma unroll
        for (int j = 0; j < 8; j++)
#pragma unroll
            for (int q = 0; q < 4; q++) acc[i][j][q] = 0.f;

    gemm_pipeline<0>(acc, sb, eh, el, nullptr, nullptr, nullptr, wv1h, wv1l, row0, 0, M, 256, tid);

    store_planes<2>(acc, smem, 0, bv1, tid);
    load_wplanes(sb + 65536, wv2h, wv2l, tid);
    __syncthreads();

    float acc2[2][8][4];
#pragma unroll
    for (int i = 0; i < 2; i++)
#pragma unroll
        for (int j = 0; j < 8; j++)
#pragma unroll
            for (int q = 0; q < 4; q++) acc2[i][j][q] = 0.f;
    gemm_smem2(acc2, sb, sb + 65536, tid);
    __syncthreads();

    store_planes<2>(acc2, smem, 0, bv2, tid);
    load_wplanes(sb + 65536, wv3h, wv3l, tid);
    __syncthreads();

    float acc3[2][8][4];
#pragma unroll
    for (int i = 0; i < 2; i++)
#pragma unroll
        for (int j = 0; j < 8; j++)
#pragma unroll
            for (int q = 0; q < 4; q++) acc3[i][j][q] = 0.f;
    gemm_smem2(acc3, sb, sb + 65536, tid);

    {
        const int wid = tid >> 5, lane = tid & 31;
        const int wm = wid >> 1, wn = wid & 1;
#pragma unroll
        for (int mt = 0; mt < 2; mt++)
#pragma unroll
            for (int nt = 0; nt < 8; nt++) {
                const int c = wn * 64 + nt * 8 + (lane & 3) * 2;
                const int h = c >> 5;
                const float b0 = bv3[c], b1 = bv3[c + 1];
#pragma unroll
                for (int half = 0; half < 2; half++) {
                    const int rr = wm * 32 + mt * 16 + (lane >> 2) + half * 8;
                    if (row0 + rr < M) {
                        const float a = atts[rr * 4 + h];
                        float* dst = hagg + (size_t)cens[rr] * 128 + c;
                        atomicAdd(dst,     (acc3[mt][nt][half * 2] + b0) * a);
                        atomicAdd(dst + 1, (acc3[mt][nt][half * 2 + 1] + b1) * a);
                    }
                }
            }
    }
}

// ---------------- exp + segment sum ----------------
__global__ void expsum_kernel(float* __restrict__ logit, const int* __restrict__ center,
                              const unsigned* __restrict__ gmax, float* __restrict__ gsum, int E)
{
    int idx = blockIdx.x * 256 + threadIdx.x;
    if (idx >= E * 4) return;
    int e = idx >> 2, h = idx & 3;
    int c = center[e];
    float m = fdec(gmax[c * 4 + h]);
    float ex = expf(logit[idx] - m);
    logit[idx] = ex;
    atomicAdd(&gsum[c * 4 + h], ex);
}

// ---------------- host launch ----------------
extern "C" void kernel_launch(void* const* d_in, const int* in_sizes, int n_in,
                              void* d_out, int out_size)
{
    const float* h_V   = (const float*)d_in[0];
    const float* h_E   = (const float*)d_in[1];
    const int*   eidx  = (const int*)  d_in[2];
    const float* hvv   = (const float*)d_in[3];
    const float* frame = (const float*)d_in[4];
    const float* W_vec = (const float*)d_in[5];
    const float* W_red = (const float*)d_in[6];
    const float* Wb1   = (const float*)d_in[7];
    const float* bb1   = (const float*)d_in[8];
    const float* Wb2   = (const float*)d_in[9];
    const float* bb2   = (const float*)d_in[10];
    const float* Wb3   = (const float*)d_in[11];
    const float* bb3   = (const float*)d_in[12];
    const float* Wv1   = (const float*)d_in[13];
    const float* bv1   = (const float*)d_in[14];
    const float* Wv2   = (const float*)d_in[15];
    const float* bv2   = (const float*)d_in[16];
    const float* Wv3   = (const float*)d_in[17];
    const float* bv3   = (const float*)d_in[18];
    const float* W_O   = (const float*)d_in[19];
    const float* bn_g  = (const float*)d_in[20];
    const float* bn_b  = (const float*)d_in[21];

    int E = in_sizes[2] / 2;
    int N = in_sizes[0] / 128;
    float* out = (float*)d_out;

    float *vff, *logit, *gsum, *hagg, *bnst;
    bf16 *eh, *el, *hVh, *hVl, *hgh, *hgl, *wh, *wl;
    unsigned* gmax;
    double* bnacc;
    cudaGetSymbolAddress((void**)&vff,   g_vff);
    cudaGetSymbolAddress((void**)&eh,    g_eh);
    cudaGetSymbolAddress((void**)&el,    g_el);
    cudaGetSymbolAddress((void**)&hVh,   g_hVh);
    cudaGetSymbolAddress((void**)&hVl,   g_hVl);
    cudaGetSymbolAddress((void**)&hgh,   g_hgh);
    cudaGetSymbolAddress((void**)&hgl,   g_hgl);
    cudaGetSymbolAddress((void**)&wh,    g_wh);
    cudaGetSymbolAddress((void**)&wl,    g_wl);
    cudaGetSymbolAddress((void**)&logit, g_logit);
    cudaGetSymbolAddress((void**)&gmax,  g_max);
    cudaGetSymbolAddress((void**)&gsum,  g_sum);
    cudaGetSymbolAddress((void**)&hagg,  g_hagg);
    cudaGetSymbolAddress((void**)&bnacc, g_bnacc);
    cudaGetSymbolAddress((void**)&bnst,  g_bnst);

    const int SMEM   = 131072;
    const int SMEM_C = 163840;          // cvt GEMM: 2 stages (64K) + A planes (32K)
    const int SMEM_A = 131072 + 2048;
    const int SMEM_B = 131072 + 2048 + 512;
    cudaFuncSetAttribute(hmma_gemm_cvt, cudaFuncAttributeMaxDynamicSharedMemorySize, SMEM_C);
    cudaFuncSetAttribute(hmma_gemm_o,   cudaFuncAttributeMaxDynamicSharedMemorySize, SMEM);
    cudaFuncSetAttribute(fusedA_kernel, cudaFuncAttributeMaxDynamicSharedMemorySize, SMEM_A);
    cudaFuncSetAttribute(fusedB_kernel, cudaFuncAttributeMaxDynamicSharedMemorySize, SMEM_B);

    int Mt = (E + 127) / 128;
    int Mo = (N + 127) / 128;

    init_kernel<<<(N * 128 + 255) / 256, 256>>>(gmax, gsum, hagg, bnacc, N);
    geom_kernel<<<(E + 255) / 256, 256>>>(eidx, hvv, frame, W_vec, vff, bnacc, E);
    bn_finalize<<<1, 32>>>(bnacc, bn_g, bn_b, bnst, E);

    // conversions (weights + tiny h_V only)
    wprep_all<<<(W_TOTAL + 255) / 256, 256>>>(W_red, Wb1, Wb2, Wv1, Wv2, Wv3, W_O, wh, wl);
    c2planes<<<(N * 128 + 255) / 256, 256>>>(h_V, hVh, hVl, (size_t)N * 128);

    // hE = [vff_bn | h_E] @ W_red  (fp32 inputs converted in-loader) -> planes
    hmma_gemm_cvt<<<dim3(2, Mt), 256, SMEM_C>>>(
        vff, h_E, bnst, wh + OW_RED, wl + OW_RED, eh, el, E);
    // fused A: x1 -> x2 -> logits + segment max
    fusedA_kernel<<<Mt, 256, SMEM_A>>>(
        hVh, hVl, eh, el, eidx,
        wh + OW_B1, wl + OW_B1, bb1,
        wh + OW_B2, wl + OW_B2, bb2,
        Wb3, bb3, logit, gmax, E);
    // exp + segment sum
    expsum_kernel<<<(E * 4 + 255) / 256, 256>>>(logit, eidx, gmax, gsum, E);
    // fused B: v1 -> v2 -> V -> weighted aggregate
    fusedB_kernel<<<Mt, 256, SMEM_B>>>(
        eh, el,
        wh + OW_V1, wl + OW_V1, bv1,
        wh + OW_V2, wl + OW_V2, bv2,
        wh + OW_V3, wl + OW_V3, bv3,
        eidx, logit, gsum, hagg, E);
    // hagg -> planes, then out = hagg @ W_O
    c2planes<<<(N * 128 + 255) / 256, 256>>>(hagg, hgh, hgl, (size_t)N * 128);
    hmma_gemm_o<<<dim3(1, Mo), 256, SMEM>>>(
        hgh, hgl, wh + OW_O, wl + OW_O, out, N);
}

// round 6
// speedup vs baseline: 2.7614x; 1.0090x over previous
#include <cuda_runtime.h>
#include <cuda_bf16.h>
#include <math.h>
#include <stdint.h>

#define E_CONST 320000
#define N_CONST 10000
typedef __nv_bfloat16 bf16;

// ---------------- scratch (no allocations allowed) ----------------
static __device__ float    g_vff [(size_t)E_CONST * 64];   // fp32 [sincos48|dist16]
static __device__ float    g_V   [(size_t)E_CONST * 128];  // V (pre-attend) fp32
static __device__ bf16     g_hVh [N_CONST * 128];
static __device__ bf16     g_hVl [N_CONST * 128];
static __device__ bf16     g_hgh [N_CONST * 128];
static __device__ bf16     g_hgl [N_CONST * 128];
static __device__ bf16     g_wh  [262144];                 // all weights, [n][k]
static __device__ bf16     g_wl  [262144];
static __device__ float    g_logit[(size_t)E_CONST * 4];
static __device__ unsigned g_max [N_CONST * 4];
static __device__ float    g_sum [N_CONST * 4];
static __device__ float    g_hagg[N_CONST * 128];
static __device__ double   g_bnacc[32];
static __device__ float    g_bnst[32];

// weight plane offsets (elements)
#define OW_RED 0        // 256 x 320
#define OW_B1  81920    // 128 x 384
#define OW_B2  131072   // 128 x 128
#define OW_V1  147456   // 128 x 256
#define OW_V2  180224   // 128 x 128
#define OW_V3  196608   // 128 x 128
#define OW_O   212992   // 128 x 128
#define W_TOTAL 229376

// ---------------- helpers ----------------
__device__ __forceinline__ uint32_t smem_u32(const void* p) {
    uint32_t a;
    asm("{ .reg .u64 t; cvta.to.shared.u64 t, %1; cvt.u32.u64 %0, t; }" : "=r"(a) : "l"(p));
    return a;
}
__device__ __forceinline__ void cp16(uint32_t dst, const void* src) {
    asm volatile("cp.async.cg.shared.global [%0], [%1], 16;"
        :: "r"(dst), "l"(__cvta_generic_to_global(src)) : "memory");
}
#define CP_COMMIT() asm volatile("cp.async.commit_group;" ::: "memory")
#define CP_WAIT(n)  asm volatile("cp.async.wait_group %0;" :: "n"(n) : "memory")

__device__ __forceinline__ void ldsm4(uint32_t* r, uint32_t addr) {
    asm volatile("ldmatrix.sync.aligned.m8n8.x4.shared.b16 {%0,%1,%2,%3}, [%4];"
        : "=r"(r[0]), "=r"(r[1]), "=r"(r[2]), "=r"(r[3]) : "r"(addr));
}
__device__ __forceinline__ void mma16816(float* d, const uint32_t* a, const uint32_t* b) {
    asm volatile(
        "mma.sync.aligned.m16n8k16.row.col.f32.bf16.bf16.f32 "
        "{%0,%1,%2,%3}, {%4,%5,%6,%7}, {%8,%9}, {%0,%1,%2,%3};"
        : "+f"(d[0]), "+f"(d[1]), "+f"(d[2]), "+f"(d[3])
        : "r"(a[0]), "r"(a[1]), "r"(a[2]), "r"(a[3]), "r"(b[0]), "r"(b[1]));
}
__device__ __forceinline__ unsigned fenc(float f) {
    unsigned u = __float_as_uint(f);
    return (u & 0x80000000u) ? ~u : (u | 0x80000000u);
}
__device__ __forceinline__ float fdec(unsigned u) {
    return (u & 0x80000000u) ? __uint_as_float(u & 0x7FFFFFFFu) : __uint_as_float(~u);
}
__device__ __forceinline__ float gelu_f(float x) {
    return 0.5f * x * (1.f + erff(x * 0.70710678118654752f));
}

// ---------------- init ----------------
__global__ void init_kernel(unsigned* gmax, float* gsum, float* hagg, double* bnacc, int N)
{
    int i = blockIdx.x * 256 + threadIdx.x;
    if (i < N * 128) hagg[i] = 0.f;
    if (i < N * 4) { gmax[i] = 0x007FFFFFu; gsum[i] = 0.f; }
    if (i < 32) bnacc[i] = 0.0;
}

// ---------------- geometry + BN stats ----------------
__global__ __launch_bounds__(256)
void geom_kernel(const int* __restrict__ eidx, const float* __restrict__ hvv,
                 const float* __restrict__ frame, const float* __restrict__ Wvec,
                 float* __restrict__ vff, double* __restrict__ bnacc, int E)
{
    __shared__ float Ws[512];
    __shared__ float bsum[16], bsq[16];
    int tid = threadIdx.x;
    for (int i = tid; i < 512; i += 256) Ws[i] = Wvec[i];
    if (tid < 16) { bsum[tid] = 0.f; bsq[tid] = 0.f; }
    __syncthreads();

    int e = blockIdx.x * 256 + tid;
    float dloc[16];
#pragma unroll
    for (int o = 0; o < 16; o++) dloc[o] = 0.f;

    if (e < E) {
        int c = eidx[e];
        int d = eidx[E + e];
        float F[9];
#pragma unroll
        for (int i = 0; i < 9; i++) F[i] = frame[e * 9 + i];
        float vdt[48], vsrc[48];
#pragma unroll
        for (int v = 0; v < 16; v++) {
            float x = hvv[d * 48 + v * 3 + 0];
            float y = hvv[d * 48 + v * 3 + 1];
            float z = hvv[d * 48 + v * 3 + 2];
            vdt[v * 3 + 0] = F[0] * x + F[1] * y + F[2] * z;
            vdt[v * 3 + 1] = F[3] * x + F[4] * y + F[5] * z;
            vdt[v * 3 + 2] = F[6] * x + F[7] * y + F[8] * z;
        }
#pragma unroll
        for (int i = 0; i < 48; i++) vsrc[i] = hvv[c * 48 + i];

#pragma unroll
        for (int o = 0; o < 16; o++) {
            float v0 = vdt[o * 3 + 0], v1 = vdt[o * 3 + 1], v2 = vdt[o * 3 + 2];
#pragma unroll
            for (int v = 0; v < 16; v++) {
                float wa = Ws[o * 32 + v], wb = Ws[o * 32 + 16 + v];
                v0 += wa * vdt[v * 3 + 0] + wb * vsrc[v * 3 + 0];
                v1 += wa * vdt[v * 3 + 1] + wb * vsrc[v * 3 + 1];
                v2 += wa * vdt[v * 3 + 2] + wb * vsrc[v * 3 + 2];
            }
            float dist = sqrtf(v0 * v0 + v1 * v1 + v2 * v2) + 1e-6f;
            float inv = 1.f / dist;
            vff[e * 64 + o * 3 + 0] = v0 * inv;
            vff[e * 64 + o * 3 + 1] = v1 * inv;
            vff[e * 64 + o * 3 + 2] = v2 * inv;
            vff[e * 64 + 48 + o] = dist;
            dloc[o] = dist;
        }
    }

#pragma unroll
    for (int o = 0; o < 16; o++) {
        float v = dloc[o], v2 = v * v;
#pragma unroll
        for (int off = 16; off; off >>= 1) {
            v  += __shfl_down_sync(0xffffffffu, v, off);
            v2 += __shfl_down_sync(0xffffffffu, v2, off);
        }
        if ((tid & 31) == 0) { atomicAdd(&bsum[o], v); atomicAdd(&bsq[o], v2); }
    }
    __syncthreads();
    if (tid < 16) {
        atomicAdd(&bnacc[tid], (double)bsum[tid]);
        atomicAdd(&bnacc[16 + tid], (double)bsq[tid]);
    }
}

__global__ void bn_finalize(const double* __restrict__ acc, const float* __restrict__ g,
                            const float* __restrict__ b, float* __restrict__ st, int E)
{
    int i = threadIdx.x;
    if (i >= 16) return;
    double mean = acc[i] / (double)E;
    double var  = acc[16 + i] / (double)E - mean * mean;
    float s = (float)((double)g[i] / sqrt(var + 1e-5));
    st[i] = s;
    st[16 + i] = b[i] - (float)mean * s;
}

// ---------------- conversion passes ----------------
__global__ void wprep_all(const float* __restrict__ W0, const float* __restrict__ W1,
                          const float* __restrict__ W2, const float* __restrict__ W3,
                          const float* __restrict__ W4, const float* __restrict__ W5,
                          const float* __restrict__ W6,
                          bf16* __restrict__ hi, bf16* __restrict__ lo)
{
    int idx = blockIdx.x * 256 + threadIdx.x;
    if (idx >= W_TOTAL) return;
    const float* src; int K, NT, start;
    if      (idx < OW_B1)  { src = W0; K = 320; NT = 256; start = OW_RED; }
    else if (idx < OW_B2)  { src = W1; K = 384; NT = 128; start = OW_B1; }
    else if (idx < OW_V1)  { src = W2; K = 128; NT = 128; start = OW_B2; }
    else if (idx < OW_V2)  { src = W3; K = 256; NT = 128; start = OW_V1; }
    else if (idx < OW_V3)  { src = W4; K = 128; NT = 128; start = OW_V2; }
    else if (idx < OW_O)   { src = W5; K = 128; NT = 128; start = OW_V3; }
    else                   { src = W6; K = 128; NT = 128; start = OW_O; }
    int local = idx - start;
    int k = local / NT, n = local % NT;
    float v = src[local];
    bf16 h = __float2bfloat16_rn(v);
    hi[start + (size_t)n * K + k] = h;
    lo[start + (size_t)n * K + k] = __float2bfloat16_rn(v - __bfloat162float(h));
}

__global__ void c2planes(const float* __restrict__ x, bf16* __restrict__ hi,
                         bf16* __restrict__ lo, size_t n)
{
    size_t i = (size_t)blockIdx.x * 256 + threadIdx.x;
    if (i >= n) return;
    float v = x[i];
    bf16 h = __float2bfloat16_rn(v);
    hi[i] = h;
    lo[i] = __float2bfloat16_rn(v - __bfloat162float(h));
}

// ================= GEMM building blocks =================
// One 64-K chunk of bf16x3 HMMA from smem planes. NTILES n-tiles (8 or 16) per warp.
template<int NTILES>
__device__ __forceinline__ void mma_chunk(
    float (&acc)[2][NTILES][4], uint32_t aHi, uint32_t aLo,
    uint32_t bHi, uint32_t bLo, int tid)
{
    const int wid = tid >> 5, lane = tid & 31;
    const int wm = wid >> 1, wn = wid & 1;
    const int a_row = wm * 32 + (lane & 7) + ((lane & 8) ? 8 : 0);
    const int a_ub  = (lane & 16) ? 1 : 0;
    const int b_row0 = wn * (NTILES * 8) + (lane & 7) + ((lane & 16) ? 8 : 0);
    const int b_ub  = (lane & 8) ? 1 : 0;
#pragma unroll
    for (int ks = 0; ks < 4; ks++) {
        uint32_t ahi[2][4], alo[2][4];
#pragma unroll
        for (int mt = 0; mt < 2; mt++) {
            const int r = a_row + mt * 16;
            const int u = ks * 2 + a_ub;
            const uint32_t off = r * 128 + (uint32_t)(((u ^ (r & 7))) << 4);
            ldsm4(ahi[mt], aHi + off);
            ldsm4(alo[mt], aLo + off);
        }
#pragma unroll
        for (int gh = 0; gh < NTILES / 8; gh++) {
            uint32_t bhi[4][4], blo[4][4];
#pragma unroll
            for (int g = 0; g < 4; g++) {
                const int n = b_row0 + (gh * 4 + g) * 16;
                const int u = ks * 2 + b_ub;
                const uint32_t off = n * 128 + (uint32_t)(((u ^ (n & 7))) << 4);
                ldsm4(bhi[g], bHi + off);
                ldsm4(blo[g], bLo + off);
            }
#pragma unroll
            for (int mt = 0; mt < 2; mt++)
#pragma unroll
                for (int ntl = 0; ntl < 8; ntl++) {
                    float* a_ = acc[mt][gh * 8 + ntl];
                    const uint32_t* bh = &bhi[ntl >> 1][(ntl & 1) * 2];
                    const uint32_t* bl = &blo[ntl >> 1][(ntl & 1) * 2];
                    mma16816(a_, ahi[mt], bh);
                    mma16816(a_, ahi[mt], bl);
                    mma16816(a_, alo[mt], bh);
                }
        }
    }
}

// stage one 64-K chunk of weight planes [rows x 64] into swizzled smem
__device__ __forceinline__ void stage_b(uint32_t dstHi, uint32_t dstLo,
                                        const bf16* __restrict__ Whi,
                                        const bf16* __restrict__ Wlo,
                                        int K, int k0, int rows, int tid)
{
    for (int i = tid; i < rows * 8; i += 256) {
        const int r = i >> 3, u = i & 7;
        const uint32_t d = r * 128 + (uint32_t)(((u ^ (r & 7))) << 4);
        cp16(dstHi + d, (const char*)(Whi + (size_t)r * K + k0) + u * 16);
        cp16(dstLo + d, (const char*)(Wlo + (size_t)r * K + k0) + u * 16);
    }
}

// store fragments -> smem bf16 hi/lo planes (chunked layout), bias+activation
template<int NTILES, int ACT>
__device__ __forceinline__ void store_planes_n(const float (&acc)[2][NTILES][4],
                                               char* smemp, uint32_t baseHi, uint32_t baseLo,
                                               const float* __restrict__ bias, int tid)
{
    const int wid = tid >> 5, lane = tid & 31;
    const int wm = wid >> 1, wn = wid & 1;
#pragma unroll
    for (int mt = 0; mt < 2; mt++)
#pragma unroll
        for (int nt = 0; nt < NTILES; nt++) {
            const int c = wn * (NTILES * 8) + nt * 8 + (lane & 3) * 2;
            const int kc = c >> 6, kk = c & 63, u = kk >> 3;
            const float b0 = bias ? bias[c] : 0.f;
            const float b1 = bias ? bias[c + 1] : 0.f;
#pragma unroll
            for (int half = 0; half < 2; half++) {
                const int r = wm * 32 + mt * 16 + (lane >> 2) + half * 8;
                float e0 = acc[mt][nt][half * 2] + b0;
                float e1 = acc[mt][nt][half * 2 + 1] + b1;
                if (ACT == 1) { e0 = fmaxf(e0, 0.f); e1 = fmaxf(e1, 0.f); }
                if (ACT == 2) { e0 = gelu_f(e0); e1 = gelu_f(e1); }
                bf16 h0 = __float2bfloat16_rn(e0);
                bf16 h1 = __float2bfloat16_rn(e1);
                __nv_bfloat162 hp; hp.x = h0; hp.y = h1;
                __nv_bfloat162 lp;
                lp.x = __float2bfloat16_rn(e0 - __bfloat162float(h0));
                lp.y = __float2bfloat16_rn(e1 - __bfloat162float(h1));
                const uint32_t ad = kc * 16384 + r * 128 +
                                    (uint32_t)(((u ^ (r & 7))) << 4) + (kk & 7) * 2;
                *(__nv_bfloat162*)(smemp + baseHi + ad) = hp;
                *(__nv_bfloat162*)(smemp + baseLo + ad) = lp;
            }
        }
}

// ---------------- MEGA kernel: W_red -> x-chain -> logits ; v-chain -> V ----------------
// smem (224 KB): [0,64K) heHi (4 chunks), [64K,128K) heLo, [128K,192K) xv, [192K,224K) stg
__global__ __launch_bounds__(256, 1)
void mega_kernel(const float* __restrict__ Vff, const float* __restrict__ HE,
                 const float* __restrict__ bn_st,
                 const bf16* __restrict__ hVh, const bf16* __restrict__ hVl,
                 const int* __restrict__ eidx,
                 const bf16* __restrict__ wredh, const bf16* __restrict__ wredl,
                 const bf16* __restrict__ wb1h, const bf16* __restrict__ wb1l,
                 const float* __restrict__ bb1,
                 const bf16* __restrict__ wb2h, const bf16* __restrict__ wb2l,
                 const float* __restrict__ bb2,
                 const float* __restrict__ Wb3, const float* __restrict__ bb3,
                 const bf16* __restrict__ wv1h, const bf16* __restrict__ wv1l,
                 const float* __restrict__ bv1,
                 const bf16* __restrict__ wv2h, const bf16* __restrict__ wv2l,
                 const float* __restrict__ bv2,
                 const bf16* __restrict__ wv3h, const bf16* __restrict__ wv3l,
                 const float* __restrict__ bv3,
                 float* __restrict__ logit, unsigned* __restrict__ gmax,
                 float* __restrict__ Vout, int M)
{
    extern __shared__ char smem[];
    const uint32_t sb = smem_u32(smem);
    const uint32_t heHi = sb;
    const uint32_t heLo = sb + 65536;
    const uint32_t xv   = sb + 131072;
    const uint32_t stg  = sb + 196608;
    const int tid = threadIdx.x;
    const int wid = tid >> 5, lane = tid & 31;
    const int row0 = blockIdx.x * 128;

    const int lr = tid >> 1;
    const int arow = (row0 + lr < M) ? (row0 + lr) : (M - 1);

    // ================= P0: hE = [vff_bn | h_E] @ W_red (K=320, N=256) =================
    {
        float acc0[2][16][4];
#pragma unroll
        for (int i = 0; i < 2; i++)
#pragma unroll
            for (int j = 0; j < 16; j++)
#pragma unroll
                for (int q = 0; q < 4; q++) acc0[i][j][q] = 0.f;

        for (int kc = 0; kc < 5; kc++) {
            const int k0 = kc << 6;
            // stage A fp32 (128 x 64 fp32 = 32 KB) into xv[0,32K)
            {
                const float* pa = (k0 == 0) ? (Vff + (size_t)arow * 64)
                                            : (HE + (size_t)arow * 256 + (k0 - 64));
                const int au0 = (tid & 1) * 8;
#pragma unroll
                for (int i = 0; i < 8; i++) {
                    const int u = au0 + i;
                    cp16(xv + lr * 256 + (uint32_t)((u ^ (lr & 15)) << 4),
                         (const char*)pa + u * 16);
                }
            }
            // stage B (256 rows) : Bhi -> xv+32K, Blo -> stg
            stage_b(xv + 32768, stg, wredh, wredl, 320, k0, 256, tid);
            CP_COMMIT();
            CP_WAIT(0);
            __syncthreads();

            // convert A fp32 -> planes in place over xv[0,32K)
            {
                const int crow = tid >> 1;
                const int cu0 = (tid & 1) * 8;
                float4 f[8];
#pragma unroll
                for (int jj = 0; jj < 8; jj++)
                    f[jj] = *(const float4*)(smem + 131072 + crow * 256 +
                                             (uint32_t)(((cu0 + jj) ^ (crow & 15)) << 4));
                if (kc == 0 && cu0 >= 8) {
#pragma unroll
                    for (int jj = 0; jj < 8; jj++) {
                        const int u = cu0 + jj;
                        if (u >= 12) {
                            const int col = u * 4;
                            f[jj].x = fmaf(f[jj].x, bn_st[col - 48], bn_st[col - 32]);
                            f[jj].y = fmaf(f[jj].y, bn_st[col - 47], bn_st[col - 31]);
                            f[jj].z = fmaf(f[jj].z, bn_st[col - 46], bn_st[col - 30]);
                            f[jj].w = fmaf(f[jj].w, bn_st[col - 45], bn_st[col - 29]);
                        }
                    }
                }
                __syncthreads();
#pragma unroll
                for (int jj = 0; jj < 4; jj++) {
                    float v[8] = {f[2 * jj].x, f[2 * jj].y, f[2 * jj].z, f[2 * jj].w,
                                  f[2 * jj + 1].x, f[2 * jj + 1].y, f[2 * jj + 1].z, f[2 * jj + 1].w};
                    uint32_t ph[4], pl[4];
#pragma unroll
                    for (int j = 0; j < 4; j++) {
                        float a = v[2 * j], b = v[2 * j + 1];
                        bf16 ha = __float2bfloat16_rn(a);
                        bf16 hb = __float2bfloat16_rn(b);
                        __nv_bfloat162 hp; hp.x = ha; hp.y = hb;
                        __nv_bfloat162 lp;
                        lp.x = __float2bfloat16_rn(a - __bfloat162float(ha));
                        lp.y = __float2bfloat16_rn(b - __bfloat162float(hb));
                        ph[j] = reinterpret_cast<uint32_t&>(hp);
                        pl[j] = reinterpret_cast<uint32_t&>(lp);
                    }
                    const int un = (cu0 >> 1) + jj;
                    const uint32_t ad = crow * 128 + (uint32_t)(((un ^ (crow & 7))) << 4);
                    *(uint4*)(smem + 131072 + ad)         = make_uint4(ph[0], ph[1], ph[2], ph[3]);
                    *(uint4*)(smem + 131072 + 16384 + ad) = make_uint4(pl[0], pl[1], pl[2], pl[3]);
                }
            }
            __syncthreads();

            mma_chunk<16>(acc0, xv, xv + 16384, xv + 32768, stg, tid);
            __syncthreads();
        }

        // epilogue: hE planes -> [0,128K)
        store_planes_n<16, 0>(acc0, smem, 0, 65536, nullptr, tid);
    }
    __syncthreads();

    // ================= P1: x1 = relu([hV[center] | hE] @ Wb1 + bb1) =================
    float acc1[2][8][4];
#pragma unroll
    for (int i = 0; i < 2; i++)
#pragma unroll
        for (int j = 0; j < 8; j++)
#pragma unroll
            for (int q = 0; q < 4; q++) acc1[i][j][q] = 0.f;
    {
        const int gr = eidx[arow];
        // stage gathered hV planes (2 chunks) into xv
#pragma unroll
        for (int kc = 0; kc < 2; kc++) {
#pragma unroll
            for (int i = 0; i < 4; i++) {
                const int u = (tid & 1) * 4 + i;
                const uint32_t d = lr * 128 + (uint32_t)(((u ^ (lr & 7))) << 4);
                cp16(xv + kc * 16384 + d,         (const char*)(hVh + (size_t)gr * 128 + kc * 64) + u * 16);
                cp16(xv + 32768 + kc * 16384 + d, (const char*)(hVl + (size_t)gr * 128 + kc * 64) + u * 16);
            }
        }
        for (int kc = 0; kc < 6; kc++) {
            stage_b(stg, stg + 16384, wb1h, wb1l, 384, kc * 64, 128, tid);
            CP_COMMIT();
            CP_WAIT(0);
            __syncthreads();
            uint32_t aHi, aLo;
            if (kc < 2) { aHi = xv + kc * 16384;          aLo = xv + 32768 + kc * 16384; }
            else        { aHi = heHi + (kc - 2) * 16384;  aLo = heLo + (kc - 2) * 16384; }
            mma_chunk<8>(acc1, aHi, aLo, stg, stg + 16384, tid);
            __syncthreads();
        }
        // x1 planes -> xv (hV staging dead)
        store_planes_n<8, 1>(acc1, smem, 131072, 131072 + 32768, bb1, tid);
    }
    __syncthreads();

    // ================= P2: x2 = relu(x1 @ Wb2 + bb2) =================
    float acc2[2][8][4];
#pragma unroll
    for (int i = 0; i < 2; i++)
#pragma unroll
        for (int j = 0; j < 8; j++)
#pragma unroll
            for (int q = 0; q < 4; q++) acc2[i][j][q] = 0.f;
    for (int kc = 0; kc < 2; kc++) {
        stage_b(stg, stg + 16384, wb2h, wb2l, 128, kc * 64, 128, tid);
        CP_COMMIT();
        CP_WAIT(0);
        __syncthreads();
        mma_chunk<8>(acc2, xv + kc * 16384, xv + 32768 + kc * 16384, stg, stg + 16384, tid);
        __syncthreads();
    }
    // x2 fp32 -> xv (x1 dead)
    {
        const int wm = wid >> 1, wn = wid & 1;
#pragma unroll
        for (int mt = 0; mt < 2; mt++)
#pragma unroll
            for (int nt = 0; nt < 8; nt++) {
                const int c = wn * 64 + nt * 8 + (lane & 3) * 2;
                const float b0 = bb2[c], b1 = bb2[c + 1];
#pragma unroll
                for (int half = 0; half < 2; half++) {
                    const int r = wm * 32 + mt * 16 + (lane >> 2) + half * 8;
                    float e0 = fmaxf(acc2[mt][nt][half * 2] + b0, 0.f);
                    float e1 = fmaxf(acc2[mt][nt][half * 2 + 1] + b1, 0.f);
                    *(float2*)(smem + 131072 + ((size_t)r * 128 + c) * 4) = make_float2(e0, e1);
                }
            }
    }
    // Wb3 transposed into stg
    {
        float* wb3s = (float*)(smem + 196608);
        if (tid < 128) {
#pragma unroll
            for (int h = 0; h < 4; h++) wb3s[h * 128 + tid] = Wb3[tid * 8 + h];
        }
    }
    __syncthreads();

    // ================= P3: logits + segment max =================
    {
        const float* x2s = (const float*)(smem + 131072);
        const float* wb3s = (const float*)(smem + 196608);
        for (int rr = wid * 16; rr < wid * 16 + 16; rr++) {
            const int e = row0 + rr;
            if (e >= M) break;
            float p0 = 0.f, p1 = 0.f, p2 = 0.f, p3 = 0.f;
#pragma unroll
            for (int j = 0; j < 4; j++) {
                const int c = lane + j * 32;
                const float x = x2s[rr * 128 + c];
                p0 += x * wb3s[c];
                p1 += x * wb3s[128 + c];
                p2 += x * wb3s[256 + c];
                p3 += x * wb3s[384 + c];
            }
#pragma unroll
            for (int off = 16; off; off >>= 1) {
                p0 += __shfl_xor_sync(0xffffffffu, p0, off);
                p1 += __shfl_xor_sync(0xffffffffu, p1, off);
                p2 += __shfl_xor_sync(0xffffffffu, p2, off);
                p3 += __shfl_xor_sync(0xffffffffu, p3, off);
            }
            if (lane < 4) {
                const float p = (lane == 0) ? p0 : (lane == 1) ? p1 : (lane == 2) ? p2 : p3;
                const float l = (p + bb3[lane]) * 0.17677669529663687f;
                logit[(size_t)e * 4 + lane] = l;
                atomicMax(&gmax[eidx[e] * 4 + lane], fenc(l));
            }
        }
    }
    __syncthreads();

    // ================= P4: v1 = gelu(hE @ Wv1 + bv1) =================
    float acc3[2][8][4];
#pragma unroll
    for (int i = 0; i < 2; i++)
#pragma unroll
        for (int j = 0; j < 8; j++)
#pragma unroll
            for (int q = 0; q < 4; q++) acc3[i][j][q] = 0.f;
    for (int kc = 0; kc < 4; kc++) {
        stage_b(stg, stg + 16384, wv1h, wv1l, 256, kc * 64, 128, tid);
        CP_COMMIT();
        CP_WAIT(0);
        __syncthreads();
        mma_chunk<8>(acc3, heHi + kc * 16384, heLo + kc * 16384, stg, stg + 16384, tid);
        __syncthreads();
    }
    store_planes_n<8, 2>(acc3, smem, 131072, 131072 + 32768, bv1, tid);  // v1 -> xv (x2 dead)
    __syncthreads();

    // ================= P5: v2 = gelu(v1 @ Wv2 + bv2) =================
    float acc4[2][8][4];
#pragma unroll
    for (int i = 0; i < 2; i++)
#pragma unroll
        for (int j = 0; j < 8; j++)
#pragma unroll
            for (int q = 0; q < 4; q++) acc4[i][j][q] = 0.f;
    for (int kc = 0; kc < 2; kc++) {
        stage_b(stg, stg + 16384, wv2h, wv2l, 128, kc * 64, 128, tid);
        CP_COMMIT();
        CP_WAIT(0);
        __syncthreads();
        mma_chunk<8>(acc4, xv + kc * 16384, xv + 32768 + kc * 16384, stg, stg + 16384, tid);
        __syncthreads();
    }
    store_planes_n<8, 2>(acc4, smem, 0, 32768, bv2, tid);  // v2 -> hE region (dead)
    __syncthreads();

    // ================= P6: V = v2 @ Wv3 + bv3 -> global fp32 =================
    float acc5[2][8][4];
#pragma unroll
    for (int i = 0; i < 2; i++)
#pragma unroll
        for (int j = 0; j < 8; j++)
#pragma unroll
            for (int q = 0; q < 4; q++) acc5[i][j][q] = 0.f;
    for (int kc = 0; kc < 2; kc++) {
        stage_b(stg, stg + 16384, wv3h, wv3l, 128, kc * 64, 128, tid);
        CP_COMMIT();
        CP_WAIT(0);
        __syncthreads();
        mma_chunk<8>(acc5, heHi + kc * 16384, heHi + 32768 + kc * 16384, stg, stg + 16384, tid);
        __syncthreads();
    }
    {
        const int wm = wid >> 1, wn = wid & 1;
#pragma unroll
        for (int mt = 0; mt < 2; mt++) {
            const int r = row0 + wm * 32 + mt * 16 + (lane >> 2);
#pragma unroll
            for (int nt = 0; nt < 8; nt++) {
                const int c = wn * 64 + nt * 8 + (lane & 3) * 2;
                const float b0 = bv3[c], b1 = bv3[c + 1];
#pragma unroll
                for (int half = 0; half < 2; half++) {
                    const int rr = r + half * 8;
                    if (rr >= M) continue;
                    *(float2*)(Vout + (size_t)rr * 128 + c) =
                        make_float2(acc5[mt][nt][half * 2] + b0,
                                    acc5[mt][nt][half * 2 + 1] + b1);
                }
            }
        }
    }
}

// ---------------- exp + segment sum ----------------
__global__ void expsum_kernel(float* __restrict__ logit, const int* __restrict__ center,
                              const unsigned* __restrict__ gmax, float* __restrict__ gsum, int E)
{
    int idx = blockIdx.x * 256 + threadIdx.x;
    if (idx >= E * 4) return;
    int e = idx >> 2, h = idx & 3;
    int c = center[e];
    float m = fdec(gmax[c * 4 + h]);
    float ex = expf(logit[idx] - m);
    logit[idx] = ex;
    atomicAdd(&gsum[c * 4 + h], ex);
}

// ---------------- weighted segment aggregation ----------------
__global__ void agg_kernel(const float* __restrict__ gexp, const float* __restrict__ gsum,
                           const float* __restrict__ V, const int* __restrict__ center,
                           float* __restrict__ hagg, int E)
{
    int idx = blockIdx.x * 256 + threadIdx.x;
    if (idx >= E * 128) return;
    int e = idx >> 7, t = idx & 127, h = t >> 5;
    int c = center[e];
    float att = gexp[e * 4 + h] / gsum[c * 4 + h];
    atomicAdd(&hagg[c * 128 + t], att * V[idx]);
}

// ---------------- standalone GEMM (W_O) ----------------
__global__ __launch_bounds__(256, 1)
void hmma_gemm_o(const bf16* __restrict__ Ahi, const bf16* __restrict__ Alo,
                 const bf16* __restrict__ Bhi, const bf16* __restrict__ Blo,
                 float* __restrict__ Cf, int M)
{
    extern __shared__ char smem[];
    const uint32_t sb = smem_u32(smem);
    const int tid = threadIdx.x;
    const int wid = tid >> 5, lane = tid & 31;
    const int row0 = blockIdx.x * 128;

    const int lr = tid >> 1;
    const int arow = (row0 + lr < M) ? (row0 + lr) : (M - 1);

    float acc[2][8][4];
#pragma unroll
    for (int i = 0; i < 2; i++)
#pragma unroll
        for (int j = 0; j < 8; j++)
#pragma unroll
            for (int q = 0; q < 4; q++) acc[i][j][q] = 0.f;

    for (int kc = 0; kc < 2; kc++) {
        // stage A + B chunk (single-buffered; small kernel)
        const int k0 = kc * 64;
#pragma unroll
        for (int i = 0; i < 4; i++) {
            const int u = (tid & 1) * 4 + i;
            const uint32_t d = lr * 128 + (uint32_t)(((u ^ (lr & 7))) << 4);
            cp16(sb + d,         (const char*)(Ahi + (size_t)arow * 128 + k0) + u * 16);
            cp16(sb + 16384 + d, (const char*)(Alo + (size_t)arow * 128 + k0) + u * 16);
        }
        stage_b(sb + 32768, sb + 49152, Bhi, Blo, 128, k0, 128, tid);
        CP_COMMIT();
        CP_WAIT(0);
        __syncthreads();
        mma_chunk<8>(acc, sb, sb + 16384, sb + 32768, sb + 49152, tid);
        __syncthreads();
    }

    const int wm = wid >> 1, wn = wid & 1;
#pragma unroll
    for (int mt = 0; mt < 2; mt++) {
        const int r = row0 + wm * 32 + mt * 16 + (lane >> 2);
#pragma unroll
        for (int nt = 0; nt < 8; nt++) {
            const int c = wn * 64 + nt * 8 + (lane & 3) * 2;
#pragma unroll
            for (int half = 0; half < 2; half++) {
                const int rr = r + half * 8;
                if (rr >= M) continue;
                *(float2*)(Cf + (size_t)rr * 128 + c) =
                    make_float2(acc[mt][nt][half * 2], acc[mt][nt][half * 2 + 1]);
            }
        }
    }
}

// ---------------- host launch ----------------
extern "C" void kernel_launch(void* const* d_in, const int* in_sizes, int n_in,
                              void* d_out, int out_size)
{
    const float* h_V   = (const float*)d_in[0];
    const float* h_E   = (const float*)d_in[1];
    const int*   eidx  = (const int*)  d_in[2];
    const float* hvv   = (const float*)d_in[3];
    const float* frame = (const float*)d_in[4];
    const float* W_vec = (const float*)d_in[5];
    const float* W_red = (const float*)d_in[6];
    const float* Wb1   = (const float*)d_in[7];
    const float* bb1   = (const float*)d_in[8];
    const float* Wb2   = (const float*)d_in[9];
    const float* bb2   = (const float*)d_in[10];
    const float* Wb3   = (const float*)d_in[11];
    const float* bb3   = (const float*)d_in[12];
    const float* Wv1   = (const float*)d_in[13];
    const float* bv1   = (const float*)d_in[14];
    const float* Wv2   = (const float*)d_in[15];
    const float* bv2   = (const float*)d_in[16];
    const float* Wv3   = (const float*)d_in[17];
    const float* bv3   = (const float*)d_in[18];
    const float* W_O   = (const float*)d_in[19];
    const float* bn_g  = (const float*)d_in[20];
    const float* bn_b  = (const float*)d_in[21];

    int E = in_sizes[2] / 2;
    int N = in_sizes[0] / 128;
    float* out = (float*)d_out;

    float *vff, *Vbuf, *logit, *gsum, *hagg, *bnst;
    bf16 *hVh, *hVl, *hgh, *hgl, *wh, *wl;
    unsigned* gmax;
    double* bnacc;
    cudaGetSymbolAddress((void**)&vff,   g_vff);
    cudaGetSymbolAddress((void**)&Vbuf,  g_V);
    cudaGetSymbolAddress((void**)&hVh,   g_hVh);
    cudaGetSymbolAddress((void**)&hVl,   g_hVl);
    cudaGetSymbolAddress((void**)&hgh,   g_hgh);
    cudaGetSymbolAddress((void**)&hgl,   g_hgl);
    cudaGetSymbolAddress((void**)&wh,    g_wh);
    cudaGetSymbolAddress((void**)&wl,    g_wl);
    cudaGetSymbolAddress((void**)&logit, g_logit);
    cudaGetSymbolAddress((void**)&gmax,  g_max);
    cudaGetSymbolAddress((void**)&gsum,  g_sum);
    cudaGetSymbolAddress((void**)&hagg,  g_hagg);
    cudaGetSymbolAddress((void**)&bnacc, g_bnacc);
    cudaGetSymbolAddress((void**)&bnst,  g_bnst);

    const int SMEM_M = 229376;   // 224 KB
    const int SMEM_O = 65536;
    cudaFuncSetAttribute(mega_kernel, cudaFuncAttributeMaxDynamicSharedMemorySize, SMEM_M);
    cudaFuncSetAttribute(hmma_gemm_o, cudaFuncAttributeMaxDynamicSharedMemorySize, SMEM_O);

    int Mt = (E + 127) / 128;
    int Mo = (N + 127) / 128;

    init_kernel<<<(N * 128 + 255) / 256, 256>>>(gmax, gsum, hagg, bnacc, N);
    geom_kernel<<<(E + 255) / 256, 256>>>(eidx, hvv, frame, W_vec, vff, bnacc, E);
    bn_finalize<<<1, 32>>>(bnacc, bn_g, bn_b, bnst, E);

    wprep_all<<<(W_TOTAL + 255) / 256, 256>>>(W_red, Wb1, Wb2, Wv1, Wv2, Wv3, W_O, wh, wl);
    c2planes<<<(N * 128 + 255) / 256, 256>>>(h_V, hVh, hVl, (size_t)N * 128);

    mega_kernel<<<Mt, 256, SMEM_M>>>(
        vff, h_E, bnst, hVh, hVl, eidx,
        wh + OW_RED, wl + OW_RED,
        wh + OW_B1, wl + OW_B1, bb1,
        wh + OW_B2, wl + OW_B2, bb2,
        Wb3, bb3,
        wh + OW_V1, wl + OW_V1, bv1,
        wh + OW_V2, wl + OW_V2, bv2,
        wh + OW_V3, wl + OW_V3, bv3,
        logit, gmax, Vbuf, E);

    expsum_kernel<<<(E * 4 + 255) / 256, 256>>>(logit, eidx, gmax, gsum, E);
    agg_kernel<<<(int)(((size_t)E * 128 + 255) / 256), 256>>>(logit, gsum, Vbuf, eidx, hagg, E);

    c2planes<<<(N * 128 + 255) / 256, 256>>>(hagg, hgh, hgl, (size_t)N * 128);
    hmma_gemm_o<<<Mo, 256, SMEM_O>>>(hgh, hgl, wh + OW_O, wl + OW_O, out, N);
}

// round 7
// speedup vs baseline: 3.0042x; 1.0879x over previous
#include <cuda_runtime.h>
#include <cuda_bf16.h>
#include <math.h>
#include <stdint.h>

#define E_CONST 320000
#define N_CONST 10000
typedef __nv_bfloat16 bf16;

// ---------------- scratch (no allocations allowed) ----------------
static __device__ float    g_vff [(size_t)E_CONST * 64];   // fp32 [sincos48|dist16]
static __device__ float    g_V   [(size_t)E_CONST * 128];  // V (pre-attend) fp32
static __device__ bf16     g_hVh [N_CONST * 128];
static __device__ bf16     g_hVl [N_CONST * 128];
static __device__ bf16     g_hgh [N_CONST * 128];
static __device__ bf16     g_hgl [N_CONST * 128];
static __device__ bf16     g_wh  [262144];                 // all weights, [n][k]
static __device__ bf16     g_wl  [262144];
static __device__ float    g_logit[(size_t)E_CONST * 4];
static __device__ unsigned g_max [N_CONST * 4];
static __device__ float    g_sum [N_CONST * 4];
static __device__ float    g_hagg[N_CONST * 128];
static __device__ double   g_bnacc[32];
static __device__ float    g_bnst[32];

// weight plane offsets (elements)
#define OW_RED 0        // 256 x 320
#define OW_B1  81920    // 128 x 384
#define OW_B2  131072   // 128 x 128
#define OW_V1  147456   // 128 x 256
#define OW_V2  180224   // 128 x 128
#define OW_V3  196608   // 128 x 128
#define OW_O   212992   // 128 x 128
#define W_TOTAL 229376

// ---------------- helpers ----------------
__device__ __forceinline__ uint32_t smem_u32(const void* p) {
    uint32_t a;
    asm("{ .reg .u64 t; cvta.to.shared.u64 t, %1; cvt.u32.u64 %0, t; }" : "=r"(a) : "l"(p));
    return a;
}
__device__ __forceinline__ void cp16(uint32_t dst, const void* src) {
    asm volatile("cp.async.cg.shared.global [%0], [%1], 16;"
        :: "r"(dst), "l"(__cvta_generic_to_global(src)) : "memory");
}
#define CP_COMMIT() asm volatile("cp.async.commit_group;" ::: "memory")
#define CP_WAIT(n)  asm volatile("cp.async.wait_group %0;" :: "n"(n) : "memory")

__device__ __forceinline__ void ldsm4(uint32_t* r, uint32_t addr) {
    asm volatile("ldmatrix.sync.aligned.m8n8.x4.shared.b16 {%0,%1,%2,%3}, [%4];"
        : "=r"(r[0]), "=r"(r[1]), "=r"(r[2]), "=r"(r[3]) : "r"(addr));
}
__device__ __forceinline__ void mma16816(float* d, const uint32_t* a, const uint32_t* b) {
    asm volatile(
        "mma.sync.aligned.m16n8k16.row.col.f32.bf16.bf16.f32 "
        "{%0,%1,%2,%3}, {%4,%5,%6,%7}, {%8,%9}, {%0,%1,%2,%3};"
        : "+f"(d[0]), "+f"(d[1]), "+f"(d[2]), "+f"(d[3])
        : "r"(a[0]), "r"(a[1]), "r"(a[2]), "r"(a[3]), "r"(b[0]), "r"(b[1]));
}
__device__ __forceinline__ unsigned fenc(float f) {
    unsigned u = __float_as_uint(f);
    return (u & 0x80000000u) ? ~u : (u | 0x80000000u);
}
__device__ __forceinline__ float fdec(unsigned u) {
    return (u & 0x80000000u) ? __uint_as_float(u & 0x7FFFFFFFu) : __uint_as_float(~u);
}
__device__ __forceinline__ float gelu_f(float x) {
    return 0.5f * x * (1.f + erff(x * 0.70710678118654752f));
}

// ---------------- init ----------------
__global__ void init_kernel(unsigned* gmax, float* gsum, float* hagg, double* bnacc, int N)
{
    int i = blockIdx.x * 256 + threadIdx.x;
    if (i < N * 128) hagg[i] = 0.f;
    if (i < N * 4) { gmax[i] = 0x007FFFFFu; gsum[i] = 0.f; }
    if (i < 32) bnacc[i] = 0.0;
}

// ---------------- geometry + BN stats ----------------
__global__ __launch_bounds__(256)
void geom_kernel(const int* __restrict__ eidx, const float* __restrict__ hvv,
                 const float* __restrict__ frame, const float* __restrict__ Wvec,
                 float* __restrict__ vff, double* __restrict__ bnacc, int E)
{
    __shared__ float Ws[512];
    __shared__ float bsum[16], bsq[16];
    int tid = threadIdx.x;
    for (int i = tid; i < 512; i += 256) Ws[i] = Wvec[i];
    if (tid < 16) { bsum[tid] = 0.f; bsq[tid] = 0.f; }
    __syncthreads();

    int e = blockIdx.x * 256 + tid;
    float dloc[16];
#pragma unroll
    for (int o = 0; o < 16; o++) dloc[o] = 0.f;

    if (e < E) {
        int c = eidx[e];
        int d = eidx[E + e];
        float F[9];
#pragma unroll
        for (int i = 0; i < 9; i++) F[i] = frame[e * 9 + i];
        float vdt[48], vsrc[48];
#pragma unroll
        for (int v = 0; v < 16; v++) {
            float x = hvv[d * 48 + v * 3 + 0];
            float y = hvv[d * 48 + v * 3 + 1];
            float z = hvv[d * 48 + v * 3 + 2];
            vdt[v * 3 + 0] = F[0] * x + F[1] * y + F[2] * z;
            vdt[v * 3 + 1] = F[3] * x + F[4] * y + F[5] * z;
            vdt[v * 3 + 2] = F[6] * x + F[7] * y + F[8] * z;
        }
#pragma unroll
        for (int i = 0; i < 48; i++) vsrc[i] = hvv[c * 48 + i];

#pragma unroll
        for (int o = 0; o < 16; o++) {
            float v0 = vdt[o * 3 + 0], v1 = vdt[o * 3 + 1], v2 = vdt[o * 3 + 2];
#pragma unroll
            for (int v = 0; v < 16; v++) {
                float wa = Ws[o * 32 + v], wb = Ws[o * 32 + 16 + v];
                v0 += wa * vdt[v * 3 + 0] + wb * vsrc[v * 3 + 0];
                v1 += wa * vdt[v * 3 + 1] + wb * vsrc[v * 3 + 1];
                v2 += wa * vdt[v * 3 + 2] + wb * vsrc[v * 3 + 2];
            }
            float dist = sqrtf(v0 * v0 + v1 * v1 + v2 * v2) + 1e-6f;
            float inv = 1.f / dist;
            vff[e * 64 + o * 3 + 0] = v0 * inv;
            vff[e * 64 + o * 3 + 1] = v1 * inv;
            vff[e * 64 + o * 3 + 2] = v2 * inv;
            vff[e * 64 + 48 + o] = dist;
            dloc[o] = dist;
        }
    }

#pragma unroll
    for (int o = 0; o < 16; o++) {
        float v = dloc[o], v2 = v * v;
#pragma unroll
        for (int off = 16; off; off >>= 1) {
            v  += __shfl_down_sync(0xffffffffu, v, off);
            v2 += __shfl_down_sync(0xffffffffu, v2, off);
        }
        if ((tid & 31) == 0) { atomicAdd(&bsum[o], v); atomicAdd(&bsq[o], v2); }
    }
    __syncthreads();
    if (tid < 16) {
        atomicAdd(&bnacc[tid], (double)bsum[tid]);
        atomicAdd(&bnacc[16 + tid], (double)bsq[tid]);
    }
}

__global__ void bn_finalize(const double* __restrict__ acc, const float* __restrict__ g,
                            const float* __restrict__ b, float* __restrict__ st, int E)
{
    int i = threadIdx.x;
    if (i >= 16) return;
    double mean = acc[i] / (double)E;
    double var  = acc[16 + i] / (double)E - mean * mean;
    float s = (float)((double)g[i] / sqrt(var + 1e-5));
    st[i] = s;
    st[16 + i] = b[i] - (float)mean * s;
}

// ---------------- conversion passes ----------------
__global__ void wprep_all(const float* __restrict__ W0, const float* __restrict__ W1,
                          const float* __restrict__ W2, const float* __restrict__ W3,
                          const float* __restrict__ W4, const float* __restrict__ W5,
                          const float* __restrict__ W6,
                          bf16* __restrict__ hi, bf16* __restrict__ lo)
{
    int idx = blockIdx.x * 256 + threadIdx.x;
    if (idx >= W_TOTAL) return;
    const float* src; int K, NT, start;
    if      (idx < OW_B1)  { src = W0; K = 320; NT = 256; start = OW_RED; }
    else if (idx < OW_B2)  { src = W1; K = 384; NT = 128; start = OW_B1; }
    else if (idx < OW_V1)  { src = W2; K = 128; NT = 128; start = OW_B2; }
    else if (idx < OW_V2)  { src = W3; K = 256; NT = 128; start = OW_V1; }
    else if (idx < OW_V3)  { src = W4; K = 128; NT = 128; start = OW_V2; }
    else if (idx < OW_O)   { src = W5; K = 128; NT = 128; start = OW_V3; }
    else                   { src = W6; K = 128; NT = 128; start = OW_O; }
    int local = idx - start;
    int k = local / NT, n = local % NT;
    float v = src[local];
    bf16 h = __float2bfloat16_rn(v);
    hi[start + (size_t)n * K + k] = h;
    lo[start + (size_t)n * K + k] = __float2bfloat16_rn(v - __bfloat162float(h));
}

__global__ void c2planes(const float* __restrict__ x, bf16* __restrict__ hi,
                         bf16* __restrict__ lo, size_t n)
{
    size_t i = (size_t)blockIdx.x * 256 + threadIdx.x;
    if (i >= n) return;
    float v = x[i];
    bf16 h = __float2bfloat16_rn(v);
    hi[i] = h;
    lo[i] = __float2bfloat16_rn(v - __bfloat162float(h));
}

// ================= GEMM building blocks (512 threads, 16 warps = 4m x 4n) =================
// One 64-K chunk of bf16x3 HMMA from smem planes; NT n-tiles (of 8 cols) per warp.
template<int NT>
__device__ __forceinline__ void mma_chunk512(
    float (&acc)[2][NT][4], uint32_t aHi, uint32_t aLo,
    uint32_t bHi, uint32_t bLo, int tid)
{
    const int wid = tid >> 5, lane = tid & 31;
    const int wm = wid >> 2, wn = wid & 3;
    const int a_row = wm * 32 + (lane & 7) + ((lane & 8) ? 8 : 0);
    const int a_ub  = (lane & 16) ? 1 : 0;
    const int b_row0 = wn * (NT * 8) + (lane & 7) + ((lane & 16) ? 8 : 0);
    const int b_ub  = (lane & 8) ? 1 : 0;
#pragma unroll
    for (int ks = 0; ks < 4; ks++) {
        uint32_t ahi[2][4], alo[2][4];
#pragma unroll
        for (int mt = 0; mt < 2; mt++) {
            const int r = a_row + mt * 16;
            const int u = ks * 2 + a_ub;
            const uint32_t off = r * 128 + (uint32_t)(((u ^ (r & 7))) << 4);
            ldsm4(ahi[mt], aHi + off);
            ldsm4(alo[mt], aLo + off);
        }
        uint32_t bhi[NT / 2][4], blo[NT / 2][4];
#pragma unroll
        for (int g = 0; g < NT / 2; g++) {
            const int n = b_row0 + g * 16;
            const int u = ks * 2 + b_ub;
            const uint32_t off = n * 128 + (uint32_t)(((u ^ (n & 7))) << 4);
            ldsm4(bhi[g], bHi + off);
            ldsm4(blo[g], bLo + off);
        }
#pragma unroll
        for (int mt = 0; mt < 2; mt++)
#pragma unroll
            for (int ntl = 0; ntl < NT; ntl++) {
                float* a_ = acc[mt][ntl];
                const uint32_t* bh = &bhi[ntl >> 1][(ntl & 1) * 2];
                const uint32_t* bl = &blo[ntl >> 1][(ntl & 1) * 2];
                mma16816(a_, ahi[mt], bh);
                mma16816(a_, ahi[mt], bl);
                mma16816(a_, alo[mt], bh);
            }
    }
}

// stage one 64-K chunk of weight planes [rows x 64] into swizzled smem (512 threads)
__device__ __forceinline__ void stage_b(uint32_t dstHi, uint32_t dstLo,
                                        const bf16* __restrict__ Whi,
                                        const bf16* __restrict__ Wlo,
                                        int K, int k0, int rows, int tid)
{
    for (int i = tid; i < rows * 8; i += 512) {
        const int r = i >> 3, u = i & 7;
        const uint32_t d = r * 128 + (uint32_t)(((u ^ (r & 7))) << 4);
        cp16(dstHi + d, (const char*)(Whi + (size_t)r * K + k0) + u * 16);
        cp16(dstLo + d, (const char*)(Wlo + (size_t)r * K + k0) + u * 16);
    }
}

// store fragments -> smem bf16 hi/lo planes (chunked layout), bias+activation
template<int NT, int ACT>
__device__ __forceinline__ void store_planes512(const float (&acc)[2][NT][4],
                                                char* smemp, uint32_t baseHi, uint32_t baseLo,
                                                const float* __restrict__ bias, int tid)
{
    const int wid = tid >> 5, lane = tid & 31;
    const int wm = wid >> 2, wn = wid & 3;
#pragma unroll
    for (int mt = 0; mt < 2; mt++)
#pragma unroll
        for (int nt = 0; nt < NT; nt++) {
            const int c = wn * (NT * 8) + nt * 8 + (lane & 3) * 2;
            const int kc = c >> 6, kk = c & 63, u = kk >> 3;
            const float b0 = bias ? bias[c] : 0.f;
            const float b1 = bias ? bias[c + 1] : 0.f;
#pragma unroll
            for (int half = 0; half < 2; half++) {
                const int r = wm * 32 + mt * 16 + (lane >> 2) + half * 8;
                float e0 = acc[mt][nt][half * 2] + b0;
                float e1 = acc[mt][nt][half * 2 + 1] + b1;
                if (ACT == 1) { e0 = fmaxf(e0, 0.f); e1 = fmaxf(e1, 0.f); }
                if (ACT == 2) { e0 = gelu_f(e0); e1 = gelu_f(e1); }
                bf16 h0 = __float2bfloat16_rn(e0);
                bf16 h1 = __float2bfloat16_rn(e1);
                __nv_bfloat162 hp; hp.x = h0; hp.y = h1;
                __nv_bfloat162 lp;
                lp.x = __float2bfloat16_rn(e0 - __bfloat162float(h0));
                lp.y = __float2bfloat16_rn(e1 - __bfloat162float(h1));
                const uint32_t ad = kc * 16384 + r * 128 +
                                    (uint32_t)(((u ^ (r & 7))) << 4) + (kk & 7) * 2;
                *(__nv_bfloat162*)(smemp + baseHi + ad) = hp;
                *(__nv_bfloat162*)(smemp + baseLo + ad) = lp;
            }
        }
}

// ---------------- MEGA kernel (512 threads): W_red -> x-chain -> logits ; v-chain -> V ----------------
// smem (224 KB): [0,64K) heHi (4 chunks), [64K,128K) heLo, [128K,192K) xv, [192K,224K) stg
__global__ __launch_bounds__(512, 1)
void mega_kernel(const float* __restrict__ Vff, const float* __restrict__ HE,
                 const float* __restrict__ bn_st,
                 const bf16* __restrict__ hVh, const bf16* __restrict__ hVl,
                 const int* __restrict__ eidx,
                 const bf16* __restrict__ wredh, const bf16* __restrict__ wredl,
                 const bf16* __restrict__ wb1h, const bf16* __restrict__ wb1l,
                 const float* __restrict__ bb1,
                 const bf16* __restrict__ wb2h, const bf16* __restrict__ wb2l,
                 const float* __restrict__ bb2,
                 const float* __restrict__ Wb3, const float* __restrict__ bb3,
                 const bf16* __restrict__ wv1h, const bf16* __restrict__ wv1l,
                 const float* __restrict__ bv1,
                 const bf16* __restrict__ wv2h, const bf16* __restrict__ wv2l,
                 const float* __restrict__ bv2,
                 const bf16* __restrict__ wv3h, const bf16* __restrict__ wv3l,
                 const float* __restrict__ bv3,
                 float* __restrict__ logit, unsigned* __restrict__ gmax,
                 float* __restrict__ Vout, int M)
{
    extern __shared__ char smem[];
    const uint32_t sb = smem_u32(smem);
    const uint32_t heHi = sb;
    const uint32_t heLo = sb + 65536;
    const uint32_t xv   = sb + 131072;
    const uint32_t stg  = sb + 196608;
    const int tid = threadIdx.x;
    const int wid = tid >> 5, lane = tid & 31;
    const int row0 = blockIdx.x * 128;

    const int lr = tid >> 2;              // 4 threads per row
    const int arow = (row0 + lr < M) ? (row0 + lr) : (M - 1);

    // ================= P0: hE = [vff_bn | h_E] @ W_red (K=320, N=256) =================
    {
        float acc0[2][8][4];
#pragma unroll
        for (int i = 0; i < 2; i++)
#pragma unroll
            for (int j = 0; j < 8; j++)
#pragma unroll
                for (int q = 0; q < 4; q++) acc0[i][j][q] = 0.f;

        for (int kc = 0; kc < 5; kc++) {
            const int k0 = kc << 6;
            // stage A fp32 (128 x 64 fp32 = 32 KB) into xv[0,32K)
            {
                const float* pa = (k0 == 0) ? (Vff + (size_t)arow * 64)
                                            : (HE + (size_t)arow * 256 + (k0 - 64));
                const int au0 = (tid & 3) * 4;
#pragma unroll
                for (int i = 0; i < 4; i++) {
                    const int u = au0 + i;
                    cp16(xv + lr * 256 + (uint32_t)((u ^ (lr & 15)) << 4),
                         (const char*)pa + u * 16);
                }
            }
            // stage B (256 rows) : Bhi -> xv+32K, Blo -> stg
            stage_b(xv + 32768, stg, wredh, wredl, 320, k0, 256, tid);
            CP_COMMIT();
            CP_WAIT(0);
            __syncthreads();

            // convert A fp32 -> planes in place over xv[0,32K)
            {
                const int crow = tid >> 2;
                const int cu0 = (tid & 3) * 4;
                float4 f[4];
#pragma unroll
                for (int jj = 0; jj < 4; jj++)
                    f[jj] = *(const float4*)(smem + 131072 + crow * 256 +
                                             (uint32_t)(((cu0 + jj) ^ (crow & 15)) << 4));
                if (kc == 0 && cu0 >= 12) {
#pragma unroll
                    for (int jj = 0; jj < 4; jj++) {
                        const int u = cu0 + jj;
                        if (u >= 12) {
                            const int col = u * 4;
                            f[jj].x = fmaf(f[jj].x, bn_st[col - 48], bn_st[col - 32]);
                            f[jj].y = fmaf(f[jj].y, bn_st[col - 47], bn_st[col - 31]);
                            f[jj].z = fmaf(f[jj].z, bn_st[col - 46], bn_st[col - 30]);
                            f[jj].w = fmaf(f[jj].w, bn_st[col - 45], bn_st[col - 29]);
                        }
                    }
                }
                __syncthreads();
#pragma unroll
                for (int jj = 0; jj < 2; jj++) {
                    float v[8] = {f[2 * jj].x, f[2 * jj].y, f[2 * jj].z, f[2 * jj].w,
                                  f[2 * jj + 1].x, f[2 * jj + 1].y, f[2 * jj + 1].z, f[2 * jj + 1].w};
                    uint32_t ph[4], pl[4];
#pragma unroll
                    for (int j = 0; j < 4; j++) {
                        float a = v[2 * j], b = v[2 * j + 1];
                        bf16 ha = __float2bfloat16_rn(a);
                        bf16 hb = __float2bfloat16_rn(b);
                        __nv_bfloat162 hp; hp.x = ha; hp.y = hb;
                        __nv_bfloat162 lp;
                        lp.x = __float2bfloat16_rn(a - __bfloat162float(ha));
                        lp.y = __float2bfloat16_rn(b - __bfloat162float(hb));
                        ph[j] = reinterpret_cast<uint32_t&>(hp);
                        pl[j] = reinterpret_cast<uint32_t&>(lp);
                    }
                    const int un = (cu0 >> 1) + jj;
                    const uint32_t ad = crow * 128 + (uint32_t)(((un ^ (crow & 7))) << 4);
                    *(uint4*)(smem + 131072 + ad)         = make_uint4(ph[0], ph[1], ph[2], ph[3]);
                    *(uint4*)(smem + 131072 + 16384 + ad) = make_uint4(pl[0], pl[1], pl[2], pl[3]);
                }
            }
            __syncthreads();

            mma_chunk512<8>(acc0, xv, xv + 16384, xv + 32768, stg, tid);
            __syncthreads();
        }

        // epilogue: hE planes -> [0,128K)
        store_planes512<8, 0>(acc0, smem, 0, 65536, nullptr, tid);
    }
    __syncthreads();

    // ================= P1: x1 = relu([hV[center] | hE] @ Wb1 + bb1) =================
    float acc1[2][4][4];
#pragma unroll
    for (int i = 0; i < 2; i++)
#pragma unroll
        for (int j = 0; j < 4; j++)
#pragma unroll
            for (int q = 0; q < 4; q++) acc1[i][j][q] = 0.f;
    {
        const int gr = eidx[arow];
        // stage gathered hV planes (2 chunks) into xv
#pragma unroll
        for (int kc = 0; kc < 2; kc++) {
#pragma unroll
            for (int i = 0; i < 2; i++) {
                const int u = (tid & 3) * 2 + i;
                const uint32_t d = lr * 128 + (uint32_t)(((u ^ (lr & 7))) << 4);
                cp16(xv + kc * 16384 + d,         (const char*)(hVh + (size_t)gr * 128 + kc * 64) + u * 16);
                cp16(xv + 32768 + kc * 16384 + d, (const char*)(hVl + (size_t)gr * 128 + kc * 64) + u * 16);
            }
        }
        for (int kc = 0; kc < 6; kc++) {
            stage_b(stg, stg + 16384, wb1h, wb1l, 384, kc * 64, 128, tid);
            CP_COMMIT();
            CP_WAIT(0);
            __syncthreads();
            uint32_t aHi, aLo;
            if (kc < 2) { aHi = xv + kc * 16384;          aLo = xv + 32768 + kc * 16384; }
            else        { aHi = heHi + (kc - 2) * 16384;  aLo = heLo + (kc - 2) * 16384; }
            mma_chunk512<4>(acc1, aHi, aLo, stg, stg + 16384, tid);
            __syncthreads();
        }
        // x1 planes -> xv (hV staging dead)
        store_planes512<4, 1>(acc1, smem, 131072, 131072 + 32768, bb1, tid);
    }
    __syncthreads();

    // ================= P2: x2 = relu(x1 @ Wb2 + bb2) =================
    float acc2[2][4][4];
#pragma unroll
    for (int i = 0; i < 2; i++)
#pragma unroll
        for (int j = 0; j < 4; j++)
#pragma unroll
            for (int q = 0; q < 4; q++) acc2[i][j][q] = 0.f;
    for (int kc = 0; kc < 2; kc++) {
        stage_b(stg, stg + 16384, wb2h, wb2l, 128, kc * 64, 128, tid);
        CP_COMMIT();
        CP_WAIT(0);
        __syncthreads();
        mma_chunk512<4>(acc2, xv + kc * 16384, xv + 32768 + kc * 16384, stg, stg + 16384, tid);
        __syncthreads();
    }
    // x2 fp32 -> xv (x1 dead)
    {
        const int wm = wid >> 2, wn = wid & 3;
#pragma unroll
        for (int mt = 0; mt < 2; mt++)
#pragma unroll
            for (int nt = 0; nt < 4; nt++) {
                const int c = wn * 32 + nt * 8 + (lane & 3) * 2;
                const float b0 = bb2[c], b1 = bb2[c + 1];
#pragma unroll
                for (int half = 0; half < 2; half++) {
                    const int r = wm * 32 + mt * 16 + (lane >> 2) + half * 8;
                    float e0 = fmaxf(acc2[mt][nt][half * 2] + b0, 0.f);
                    float e1 = fmaxf(acc2[mt][nt][half * 2 + 1] + b1, 0.f);
                    *(float2*)(smem + 131072 + ((size_t)r * 128 + c) * 4) = make_float2(e0, e1);
                }
            }
    }
    // Wb3 transposed into stg
    {
        float* wb3s = (float*)(smem + 196608);
        if (tid < 128) {
#pragma unroll
            for (int h = 0; h < 4; h++) wb3s[h * 128 + tid] = Wb3[tid * 8 + h];
        }
    }
    __syncthreads();

    // ================= P3: logits + segment max =================
    {
        const float* x2s = (const float*)(smem + 131072);
        const float* wb3s = (const float*)(smem + 196608);
        for (int rr = wid * 8; rr < wid * 8 + 8; rr++) {
            const int e = row0 + rr;
            if (e >= M) break;
            float p0 = 0.f, p1 = 0.f, p2 = 0.f, p3 = 0.f;
#pragma unroll
            for (int j = 0; j < 4; j++) {
                const int c = lane + j * 32;
                const float x = x2s[rr * 128 + c];
                p0 += x * wb3s[c];
                p1 += x * wb3s[128 + c];
                p2 += x * wb3s[256 + c];
                p3 += x * wb3s[384 + c];
            }
#pragma unroll
            for (int off = 16; off; off >>= 1) {
                p0 += __shfl_xor_sync(0xffffffffu, p0, off);
                p1 += __shfl_xor_sync(0xffffffffu, p1, off);
                p2 += __shfl_xor_sync(0xffffffffu, p2, off);
                p3 += __shfl_xor_sync(0xffffffffu, p3, off);
            }
            if (lane < 4) {
                const float p = (lane == 0) ? p0 : (lane == 1) ? p1 : (lane == 2) ? p2 : p3;
                const float l = (p + bb3[lane]) * 0.17677669529663687f;
                logit[(size_t)e * 4 + lane] = l;
                atomicMax(&gmax[eidx[e] * 4 + lane], fenc(l));
            }
        }
    }
    __syncthreads();

    // ================= P4: v1 = gelu(hE @ Wv1 + bv1) =================
    float acc3[2][4][4];
#pragma unroll
    for (int i = 0; i < 2; i++)
#pragma unroll
        for (int j = 0; j < 4; j++)
#pragma unroll
            for (int q = 0; q < 4; q++) acc3[i][j][q] = 0.f;
    for (int kc = 0; kc < 4; kc++) {
        stage_b(stg, stg + 16384, wv1h, wv1l, 256, kc * 64, 128, tid);
        CP_COMMIT();
        CP_WAIT(0);
        __syncthreads();
        mma_chunk512<4>(acc3, heHi + kc * 16384, heLo + kc * 16384, stg, stg + 16384, tid);
        __syncthreads();
    }
    store_planes512<4, 2>(acc3, smem, 131072, 131072 + 32768, bv1, tid);  // v1 -> xv (x2 dead)
    __syncthreads();

    // ================= P5: v2 = gelu(v1 @ Wv2 + bv2) =================
    float acc4[2][4][4];
#pragma unroll
    for (int i = 0; i < 2; i++)
#pragma unroll
        for (int j = 0; j < 4; j++)
#pragma unroll
            for (int q = 0; q < 4; q++) acc4[i][j][q] = 0.f;
    for (int kc = 0; kc < 2; kc++) {
        stage_b(stg, stg + 16384, wv2h, wv2l, 128, kc * 64, 128, tid);
        CP_COMMIT();
        CP_WAIT(0);
        __syncthreads();
        mma_chunk512<4>(acc4, xv + kc * 16384, xv + 32768 + kc * 16384, stg, stg + 16384, tid);
        __syncthreads();
    }
    store_planes512<4, 2>(acc4, smem, 0, 32768, bv2, tid);  // v2 -> hE region (dead)
    __syncthreads();

    // ================= P6: V = v2 @ Wv3 + bv3 -> global fp32 =================
    float acc5[2][4][4];
#pragma unroll
    for (int i = 0; i < 2; i++)
#pragma unroll
        for (int j = 0; j < 4; j++)
#pragma unroll
            for (int q = 0; q < 4; q++) acc5[i][j][q] = 0.f;
    for (int kc = 0; kc < 2; kc++) {
        stage_b(stg, stg + 16384, wv3h, wv3l, 128, kc * 64, 128, tid);
        CP_COMMIT();
        CP_WAIT(0);
        __syncthreads();
        mma_chunk512<4>(acc5, heHi + kc * 16384, heHi + 32768 + kc * 16384, stg, stg + 16384, tid);
        __syncthreads();
    }
    {
        const int wm = wid >> 2, wn = wid & 3;
#pragma unroll
        for (int mt = 0; mt < 2; mt++) {
            const int r = row0 + wm * 32 + mt * 16 + (lane >> 2);
#pragma unroll
            for (int nt = 0; nt < 4; nt++) {
                const int c = wn * 32 + nt * 8 + (lane & 3) * 2;
                const float b0 = bv3[c], b1 = bv3[c + 1];
#pragma unroll
                for (int half = 0; half < 2; half++) {
                    const int rr = r + half * 8;
                    if (rr >= M) continue;
                    *(float2*)(Vout + (size_t)rr * 128 + c) =
                        make_float2(acc5[mt][nt][half * 2] + b0,
                                    acc5[mt][nt][half * 2 + 1] + b1);
                }
            }
        }
    }
}

// ---------------- exp + segment sum ----------------
__global__ void expsum_kernel(float* __restrict__ logit, const int* __restrict__ center,
                              const unsigned* __restrict__ gmax, float* __restrict__ gsum, int E)
{
    int idx = blockIdx.x * 256 + threadIdx.x;
    if (idx >= E * 4) return;
    int e = idx >> 2, h = idx & 3;
    int c = center[e];
    float m = fdec(gmax[c * 4 + h]);
    float ex = expf(logit[idx] - m);
    logit[idx] = ex;
    atomicAdd(&gsum[c * 4 + h], ex);
}

// ---------------- weighted segment aggregation ----------------
__global__ void agg_kernel(const float* __restrict__ gexp, const float* __restrict__ gsum,
                           const float* __restrict__ V, const int* __restrict__ center,
                           float* __restrict__ hagg, int E)
{
    int idx = blockIdx.x * 256 + threadIdx.x;
    if (idx >= E * 128) return;
    int e = idx >> 7, t = idx & 127, h = t >> 5;
    int c = center[e];
    float att = gexp[e * 4 + h] / gsum[c * 4 + h];
    atomicAdd(&hagg[c * 128 + t], att * V[idx]);
}

// ---------------- standalone GEMM (W_O), 256 threads (tiny) ----------------
__device__ __forceinline__ void ldsm_mma8(float (&acc)[2][8][4], uint32_t aB, uint32_t bB, int tid)
{
    const int wid = tid >> 5, lane = tid & 31;
    const int wm = wid >> 1, wn = wid & 1;
    const int a_row = wm * 32 + (lane & 7) + ((lane & 8) ? 8 : 0);
    const int a_ub  = (lane & 16) ? 1 : 0;
    const int b_row0 = wn * 64 + (lane & 7) + ((lane & 16) ? 8 : 0);
    const int b_ub  = (lane & 8) ? 1 : 0;
#pragma unroll
    for (int ks = 0; ks < 4; ks++) {
        uint32_t ahi[2][4], alo[2][4];
#pragma unroll
        for (int mt = 0; mt < 2; mt++) {
            const int r = a_row + mt * 16;
            const int u = ks * 2 + a_ub;
            const uint32_t off = r * 128 + (uint32_t)(((u ^ (r & 7))) << 4);
            ldsm4(ahi[mt], aB + off);
            ldsm4(alo[mt], aB + 16384 + off);
        }
        uint32_t bhi[4][4], blo[4][4];
#pragma unroll
        for (int g = 0; g < 4; g++) {
            const int n = b_row0 + g * 16;
            const int u = ks * 2 + b_ub;
            const uint32_t off = n * 128 + (uint32_t)(((u ^ (n & 7))) << 4);
            ldsm4(bhi[g], bB + off);
            ldsm4(blo[g], bB + 16384 + off);
        }
#pragma unroll
        for (int mt = 0; mt < 2; mt++)
#pragma unroll
            for (int ntl = 0; ntl < 8; ntl++) {
                float* a_ = acc[mt][ntl];
                const uint32_t* bh = &bhi[ntl >> 1][(ntl & 1) * 2];
                const uint32_t* bl = &blo[ntl >> 1][(ntl & 1) * 2];
                mma16816(a_, ahi[mt], bh);
                mma16816(a_, ahi[mt], bl);
                mma16816(a_, alo[mt], bh);
            }
    }
}

__global__ __launch_bounds__(256, 1)
void hmma_gemm_o(const bf16* __restrict__ Ahi, const bf16* __restrict__ Alo,
                 const bf16* __restrict__ Bhi, const bf16* __restrict__ Blo,
                 float* __restrict__ Cf, int M)
{
    extern __shared__ char smem[];
    const uint32_t sb = smem_u32(smem);
    const int tid = threadIdx.x;
    const int wid = tid >> 5, lane = tid & 31;
    const int row0 = blockIdx.x * 128;

    const int lr = tid >> 1;
    const int arow = (row0 + lr < M) ? (row0 + lr) : (M - 1);

    float acc[2][8][4];
#pragma unroll
    for (int i = 0; i < 2; i++)
#pragma unroll
        for (int j = 0; j < 8; j++)
#pragma unroll
            for (int q = 0; q < 4; q++) acc[i][j][q] = 0.f;

    for (int kc = 0; kc < 2; kc++) {
        const int k0 = kc * 64;
#pragma unroll
        for (int i = 0; i < 4; i++) {
            const int u = (tid & 1) * 4 + i;
            const uint32_t d = lr * 128 + (uint32_t)(((u ^ (lr & 7))) << 4);
            cp16(sb + d,         (const char*)(Ahi + (size_t)arow * 128 + k0) + u * 16);
            cp16(sb + 16384 + d, (const char*)(Alo + (size_t)arow * 128 + k0) + u * 16);
        }
        for (int i = tid; i < 128 * 8; i += 256) {
            const int r = i >> 3, u = i & 7;
            const uint32_t d = r * 128 + (uint32_t)(((u ^ (r & 7))) << 4);
            cp16(sb + 32768 + d, (const char*)(Bhi + (size_t)r * 128 + k0) + u * 16);
            cp16(sb + 49152 + d, (const char*)(Blo + (size_t)r * 128 + k0) + u * 16);
        }
        CP_COMMIT();
        CP_WAIT(0);
        __syncthreads();
        ldsm_mma8(acc, sb, sb + 32768, tid);
        __syncthreads();
    }

    const int wm = wid >> 1, wn = wid & 1;
#pragma unroll
    for (int mt = 0; mt < 2; mt++) {
        const int r = row0 + wm * 32 + mt * 16 + (lane >> 2);
#pragma unroll
        for (int nt = 0; nt < 8; nt++) {
            const int c = wn * 64 + nt * 8 + (lane & 3) * 2;
#pragma unroll
            for (int half = 0; half < 2; half++) {
                const int rr = r + half * 8;
                if (rr >= M) continue;
                *(float2*)(Cf + (size_t)rr * 128 + c) =
                    make_float2(acc[mt][nt][half * 2], acc[mt][nt][half * 2 + 1]);
            }
        }
    }
}

// ---------------- host launch ----------------
extern "C" void kernel_launch(void* const* d_in, const int* in_sizes, int n_in,
                              void* d_out, int out_size)
{
    const float* h_V   = (const float*)d_in[0];
    const float* h_E   = (const float*)d_in[1];
    const int*   eidx  = (const int*)  d_in[2];
    const float* hvv   = (const float*)d_in[3];
    const float* frame = (const float*)d_in[4];
    const float* W_vec = (const float*)d_in[5];
    const float* W_red = (const float*)d_in[6];
    const float* Wb1   = (const float*)d_in[7];
    const float* bb1   = (const float*)d_in[8];
    const float* Wb2   = (const float*)d_in[9];
    const float* bb2   = (const float*)d_in[10];
    const float* Wb3   = (const float*)d_in[11];
    const float* bb3   = (const float*)d_in[12];
    const float* Wv1   = (const float*)d_in[13];
    const float* bv1   = (const float*)d_in[14];
    const float* Wv2   = (const float*)d_in[15];
    const float* bv2   = (const float*)d_in[16];
    const float* Wv3   = (const float*)d_in[17];
    const float* bv3   = (const float*)d_in[18];
    const float* W_O   = (const float*)d_in[19];
    const float* bn_g  = (const float*)d_in[20];
    const float* bn_b  = (const float*)d_in[21];

    int E = in_sizes[2] / 2;
    int N = in_sizes[0] / 128;
    float* out = (float*)d_out;

    float *vff, *Vbuf, *logit, *gsum, *hagg, *bnst;
    bf16 *hVh, *hVl, *hgh, *hgl, *wh, *wl;
    unsigned* gmax;
    double* bnacc;
    cudaGetSymbolAddress((void**)&vff,   g_vff);
    cudaGetSymbolAddress((void**)&Vbuf,  g_V);
    cudaGetSymbolAddress((void**)&hVh,   g_hVh);
    cudaGetSymbolAddress((void**)&hVl,   g_hVl);
    cudaGetSymbolAddress((void**)&hgh,   g_hgh);
    cudaGetSymbolAddress((void**)&hgl,   g_hgl);
    cudaGetSymbolAddress((void**)&wh,    g_wh);
    cudaGetSymbolAddress((void**)&wl,    g_wl);
    cudaGetSymbolAddress((void**)&logit, g_logit);
    cudaGetSymbolAddress((void**)&gmax,  g_max);
    cudaGetSymbolAddress((void**)&gsum,  g_sum);
    cudaGetSymbolAddress((void**)&hagg,  g_hagg);
    cudaGetSymbolAddress((void**)&bnacc, g_bnacc);
    cudaGetSymbolAddress((void**)&bnst,  g_bnst);

    const int SMEM_M = 229376;   // 224 KB
    const int SMEM_O = 65536;
    cudaFuncSetAttribute(mega_kernel, cudaFuncAttributeMaxDynamicSharedMemorySize, SMEM_M);
    cudaFuncSetAttribute(hmma_gemm_o, cudaFuncAttributeMaxDynamicSharedMemorySize, SMEM_O);

    int Mt = (E + 127) / 128;
    int Mo = (N + 127) / 128;

    init_kernel<<<(N * 128 + 255) / 256, 256>>>(gmax, gsum, hagg, bnacc, N);
    geom_kernel<<<(E + 255) / 256, 256>>>(eidx, hvv, frame, W_vec, vff, bnacc, E);
    bn_finalize<<<1, 32>>>(bnacc, bn_g, bn_b, bnst, E);

    wprep_all<<<(W_TOTAL + 255) / 256, 256>>>(W_red, Wb1, Wb2, Wv1, Wv2, Wv3, W_O, wh, wl);
    c2planes<<<(N * 128 + 255) / 256, 256>>>(h_V, hVh, hVl, (size_t)N * 128);

    mega_kernel<<<Mt, 512, SMEM_M>>>(
        vff, h_E, bnst, hVh, hVl, eidx,
        wh + OW_RED, wl + OW_RED,
        wh + OW_B1, wl + OW_B1, bb1,
        wh + OW_B2, wl + OW_B2, bb2,
        Wb3, bb3,
        wh + OW_V1, wl + OW_V1, bv1,
        wh + OW_V2, wl + OW_V2, bv2,
        wh + OW_V3, wl + OW_V3, bv3,
        logit, gmax, Vbuf, E);

    expsum_kernel<<<(E * 4 + 255) / 256, 256>>>(logit, eidx, gmax, gsum, E);
    agg_kernel<<<(int)(((size_t)E * 128 + 255) / 256), 256>>>(logit, gsum, Vbuf, eidx, hagg, E);

    c2planes<<<(N * 128 + 255) / 256, 256>>>(hagg, hgh, hgl, (size_t)N * 128);
    hmma_gemm_o<<<Mo, 256, SMEM_O>>>(hgh, hgl, wh + OW_O, wl + OW_O, out, N);
}

// round 8
// speedup vs baseline: 3.0624x; 1.0194x over previous
#include <cuda_runtime.h>
#include <cuda_bf16.h>
#include <math.h>
#include <stdint.h>

#define E_CONST 320000
#define N_CONST 10000
typedef __nv_bfloat16 bf16;

// ---------------- scratch (no allocations allowed) ----------------
static __device__ float    g_vff [(size_t)E_CONST * 64];   // fp32 [sincos48|dist16]
static __device__ float    g_V   [(size_t)E_CONST * 128];  // V (pre-attend) fp32
static __device__ bf16     g_hVh [N_CONST * 128];
static __device__ bf16     g_hVl [N_CONST * 128];
static __device__ bf16     g_hgh [N_CONST * 128];
static __device__ bf16     g_hgl [N_CONST * 128];
static __device__ bf16     g_wh  [262144];                 // all weights, [n][k]
static __device__ bf16     g_wl  [262144];
static __device__ float    g_logit[(size_t)E_CONST * 4];
static __device__ unsigned g_max [N_CONST * 4];
static __device__ float    g_sum [N_CONST * 4];
static __device__ float    g_hagg[N_CONST * 128];
static __device__ double   g_bnacc[32];
static __device__ float    g_bnst[32];

// weight plane offsets (elements)
#define OW_RED 0        // 256 x 320
#define OW_B1  81920    // 128 x 384
#define OW_B2  131072   // 128 x 128
#define OW_V1  147456   // 128 x 256
#define OW_V2  180224   // 128 x 128
#define OW_V3  196608   // 128 x 128
#define OW_O   212992   // 128 x 128
#define W_TOTAL 229376

// ---------------- helpers ----------------
__device__ __forceinline__ uint32_t smem_u32(const void* p) {
    uint32_t a;
    asm("{ .reg .u64 t; cvta.to.shared.u64 t, %1; cvt.u32.u64 %0, t; }" : "=r"(a) : "l"(p));
    return a;
}
__device__ __forceinline__ void cp16(uint32_t dst, const void* src) {
    asm volatile("cp.async.cg.shared.global [%0], [%1], 16;"
        :: "r"(dst), "l"(__cvta_generic_to_global(src)) : "memory");
}
#define CP_COMMIT() asm volatile("cp.async.commit_group;" ::: "memory")
#define CP_WAIT(n)  asm volatile("cp.async.wait_group %0;" :: "n"(n) : "memory")

__device__ __forceinline__ void ldsm4(uint32_t* r, uint32_t addr) {
    asm volatile("ldmatrix.sync.aligned.m8n8.x4.shared.b16 {%0,%1,%2,%3}, [%4];"
        : "=r"(r[0]), "=r"(r[1]), "=r"(r[2]), "=r"(r[3]) : "r"(addr));
}
__device__ __forceinline__ void mma16816(float* d, const uint32_t* a, const uint32_t* b) {
    asm volatile(
        "mma.sync.aligned.m16n8k16.row.col.f32.bf16.bf16.f32 "
        "{%0,%1,%2,%3}, {%4,%5,%6,%7}, {%8,%9}, {%0,%1,%2,%3};"
        : "+f"(d[0]), "+f"(d[1]), "+f"(d[2]), "+f"(d[3])
        : "r"(a[0]), "r"(a[1]), "r"(a[2]), "r"(a[3]), "r"(b[0]), "r"(b[1]));
}
__device__ __forceinline__ unsigned fenc(float f) {
    unsigned u = __float_as_uint(f);
    return (u & 0x80000000u) ? ~u : (u | 0x80000000u);
}
__device__ __forceinline__ float fdec(unsigned u) {
    return (u & 0x80000000u) ? __uint_as_float(u & 0x7FFFFFFFu) : __uint_as_float(~u);
}
__device__ __forceinline__ float gelu_f(float x) {
    return 0.5f * x * (1.f + erff(x * 0.70710678118654752f));
}

// ---------------- init ----------------
__global__ void init_kernel(unsigned* gmax, float* gsum, float* hagg, double* bnacc, int N)
{
    int i = blockIdx.x * 256 + threadIdx.x;
    if (i < N * 128) hagg[i] = 0.f;
    if (i < N * 4) { gmax[i] = 0x007FFFFFu; gsum[i] = 0.f; }
    if (i < 32) bnacc[i] = 0.0;
}

// ---------------- geometry + BN stats ----------------
__global__ __launch_bounds__(256)
void geom_kernel(const int* __restrict__ eidx, const float* __restrict__ hvv,
                 const float* __restrict__ frame, const float* __restrict__ Wvec,
                 float* __restrict__ vff, double* __restrict__ bnacc, int E)
{
    __shared__ float Ws[512];
    __shared__ float bsum[16], bsq[16];
    int tid = threadIdx.x;
    for (int i = tid; i < 512; i += 256) Ws[i] = Wvec[i];
    if (tid < 16) { bsum[tid] = 0.f; bsq[tid] = 0.f; }
    __syncthreads();

    int e = blockIdx.x * 256 + tid;
    float dloc[16];
#pragma unroll
    for (int o = 0; o < 16; o++) dloc[o] = 0.f;

    if (e < E) {
        int c = eidx[e];
        int d = eidx[E + e];
        float F[9];
#pragma unroll
        for (int i = 0; i < 9; i++) F[i] = frame[e * 9 + i];
        float vdt[48], vsrc[48];
#pragma unroll
        for (int v = 0; v < 16; v++) {
            float x = hvv[d * 48 + v * 3 + 0];
            float y = hvv[d * 48 + v * 3 + 1];
            float z = hvv[d * 48 + v * 3 + 2];
            vdt[v * 3 + 0] = F[0] * x + F[1] * y + F[2] * z;
            vdt[v * 3 + 1] = F[3] * x + F[4] * y + F[5] * z;
            vdt[v * 3 + 2] = F[6] * x + F[7] * y + F[8] * z;
        }
#pragma unroll
        for (int i = 0; i < 48; i++) vsrc[i] = hvv[c * 48 + i];

#pragma unroll
        for (int o = 0; o < 16; o++) {
            float v0 = vdt[o * 3 + 0], v1 = vdt[o * 3 + 1], v2 = vdt[o * 3 + 2];
#pragma unroll
            for (int v = 0; v < 16; v++) {
                float wa = Ws[o * 32 + v], wb = Ws[o * 32 + 16 + v];
                v0 += wa * vdt[v * 3 + 0] + wb * vsrc[v * 3 + 0];
                v1 += wa * vdt[v * 3 + 1] + wb * vsrc[v * 3 + 1];
                v2 += wa * vdt[v * 3 + 2] + wb * vsrc[v * 3 + 2];
            }
            float dist = sqrtf(v0 * v0 + v1 * v1 + v2 * v2) + 1e-6f;
            float inv = 1.f / dist;
            vff[e * 64 + o * 3 + 0] = v0 * inv;
            vff[e * 64 + o * 3 + 1] = v1 * inv;
            vff[e * 64 + o * 3 + 2] = v2 * inv;
            vff[e * 64 + 48 + o] = dist;
            dloc[o] = dist;
        }
    }

#pragma unroll
    for (int o = 0; o < 16; o++) {
        float v = dloc[o], v2 = v * v;
#pragma unroll
        for (int off = 16; off; off >>= 1) {
            v  += __shfl_down_sync(0xffffffffu, v, off);
            v2 += __shfl_down_sync(0xffffffffu, v2, off);
        }
        if ((tid & 31) == 0) { atomicAdd(&bsum[o], v); atomicAdd(&bsq[o], v2); }
    }
    __syncthreads();
    if (tid < 16) {
        atomicAdd(&bnacc[tid], (double)bsum[tid]);
        atomicAdd(&bnacc[16 + tid], (double)bsq[tid]);
    }
}

__global__ void bn_finalize(const double* __restrict__ acc, const float* __restrict__ g,
                            const float* __restrict__ b, float* __restrict__ st, int E)
{
    int i = threadIdx.x;
    if (i >= 16) return;
    double mean = acc[i] / (double)E;
    double var  = acc[16 + i] / (double)E - mean * mean;
    float s = (float)((double)g[i] / sqrt(var + 1e-5));
    st[i] = s;
    st[16 + i] = b[i] - (float)mean * s;
}

// ---------------- conversion passes ----------------
__global__ void wprep_all(const float* __restrict__ W0, const float* __restrict__ W1,
                          const float* __restrict__ W2, const float* __restrict__ W3,
                          const float* __restrict__ W4, const float* __restrict__ W5,
                          const float* __restrict__ W6,
                          bf16* __restrict__ hi, bf16* __restrict__ lo)
{
    int idx = blockIdx.x * 256 + threadIdx.x;
    if (idx >= W_TOTAL) return;
    const float* src; int K, NT, start;
    if      (idx < OW_B1)  { src = W0; K = 320; NT = 256; start = OW_RED; }
    else if (idx < OW_B2)  { src = W1; K = 384; NT = 128; start = OW_B1; }
    else if (idx < OW_V1)  { src = W2; K = 128; NT = 128; start = OW_B2; }
    else if (idx < OW_V2)  { src = W3; K = 256; NT = 128; start = OW_V1; }
    else if (idx < OW_V3)  { src = W4; K = 128; NT = 128; start = OW_V2; }
    else if (idx < OW_O)   { src = W5; K = 128; NT = 128; start = OW_V3; }
    else                   { src = W6; K = 128; NT = 128; start = OW_O; }
    int local = idx - start;
    int k = local / NT, n = local % NT;
    float v = src[local];
    bf16 h = __float2bfloat16_rn(v);
    hi[start + (size_t)n * K + k] = h;
    lo[start + (size_t)n * K + k] = __float2bfloat16_rn(v - __bfloat162float(h));
}

__global__ void c2planes(const float* __restrict__ x, bf16* __restrict__ hi,
                         bf16* __restrict__ lo, size_t n)
{
    size_t i = (size_t)blockIdx.x * 256 + threadIdx.x;
    if (i >= n) return;
    float v = x[i];
    bf16 h = __float2bfloat16_rn(v);
    hi[i] = h;
    lo[i] = __float2bfloat16_rn(v - __bfloat162float(h));
}

// ================= GEMM building blocks (512 threads, 16 warps = 4m x 4n) =================
// Half-chunk mma (K=32, ks0 = 0 or 2) of bf16x3 HMMA from smem planes.
template<int NT>
__device__ __forceinline__ void mma_half512(
    float (&acc)[2][NT][4], uint32_t aHi, uint32_t aLo,
    uint32_t bHi, uint32_t bLo, int ks0, int tid)
{
    const int wid = tid >> 5, lane = tid & 31;
    const int wm = wid >> 2, wn = wid & 3;
    const int a_row = wm * 32 + (lane & 7) + ((lane & 8) ? 8 : 0);
    const int a_ub  = (lane & 16) ? 1 : 0;
    const int b_row0 = wn * (NT * 8) + (lane & 7) + ((lane & 16) ? 8 : 0);
    const int b_ub  = (lane & 8) ? 1 : 0;
#pragma unroll
    for (int kss = 0; kss < 2; kss++) {
        const int ks = ks0 + kss;
        uint32_t ahi[2][4], alo[2][4];
#pragma unroll
        for (int mt = 0; mt < 2; mt++) {
            const int r = a_row + mt * 16;
            const int u = ks * 2 + a_ub;
            const uint32_t off = r * 128 + (uint32_t)(((u ^ (r & 7))) << 4);
            ldsm4(ahi[mt], aHi + off);
            ldsm4(alo[mt], aLo + off);
        }
        uint32_t bhi[NT / 2][4], blo[NT / 2][4];
#pragma unroll
        for (int g = 0; g < NT / 2; g++) {
            const int n = b_row0 + g * 16;
            const int u = ks * 2 + b_ub;
            const uint32_t off = n * 128 + (uint32_t)(((u ^ (n & 7))) << 4);
            ldsm4(bhi[g], bHi + off);
            ldsm4(blo[g], bLo + off);
        }
#pragma unroll
        for (int mt = 0; mt < 2; mt++)
#pragma unroll
            for (int ntl = 0; ntl < NT; ntl++) {
                float* a_ = acc[mt][ntl];
                const uint32_t* bh = &bhi[ntl >> 1][(ntl & 1) * 2];
                const uint32_t* bl = &blo[ntl >> 1][(ntl & 1) * 2];
                mma16816(a_, ahi[mt], bh);
                mma16816(a_, ahi[mt], bl);
                mma16816(a_, alo[mt], bh);
            }
    }
}

// stage HALF of a 64-K weight chunk (units half*4..half*4+3 of each 128B row) + commit
__device__ __forceinline__ void stage_half(uint32_t dstHi, uint32_t dstLo,
                                           const bf16* __restrict__ Whi,
                                           const bf16* __restrict__ Wlo,
                                           int K, int k0, int half, int rows, int tid)
{
    for (int i = tid; i < rows * 4; i += 512) {
        const int r = i >> 2, u = (i & 3) + half * 4;
        const uint32_t d = r * 128 + (uint32_t)(((u ^ (r & 7))) << 4);
        cp16(dstHi + d, (const char*)(Whi + (size_t)r * K + k0) + u * 16);
        cp16(dstLo + d, (const char*)(Wlo + (size_t)r * K + k0) + u * 16);
    }
    CP_COMMIT();
}

// pipelined weight-streaming phase: single 32KB buffer, half-chunk ping-pong
template<int NT, typename FA>
__device__ __forceinline__ void run_phase(float (&acc)[2][NT][4], FA addrA,
                                          const bf16* __restrict__ Wh, const bf16* __restrict__ Wl,
                                          int K, int nch, uint32_t bHi, uint32_t bLo, int tid)
{
    stage_half(bHi, bLo, Wh, Wl, K, 0, 0, 128, tid);
    const int H = nch * 2;
    for (int h = 0; h < H; h++) {
        if (h + 1 < H) {
            stage_half(bHi, bLo, Wh, Wl, K, ((h + 1) >> 1) * 64, (h + 1) & 1, 128, tid);
            CP_WAIT(1);
        } else {
            CP_WAIT(0);
        }
        __syncthreads();
        uint32_t aHi, aLo;
        addrA(h >> 1, aHi, aLo);
        mma_half512<NT>(acc, aHi, aLo, bHi, bLo, (h & 1) * 2, tid);
        __syncthreads();
    }
}

// store fragments -> smem bf16 hi/lo planes (chunked layout), bias+activation
template<int NT, int ACT>
__device__ __forceinline__ void store_planes512(const float (&acc)[2][NT][4],
                                                char* smemp, uint32_t baseHi, uint32_t baseLo,
                                                const float* __restrict__ bias, int tid)
{
    const int wid = tid >> 5, lane = tid & 31;
    const int wm = wid >> 2, wn = wid & 3;
#pragma unroll
    for (int mt = 0; mt < 2; mt++)
#pragma unroll
        for (int nt = 0; nt < NT; nt++) {
            const int c = wn * (NT * 8) + nt * 8 + (lane & 3) * 2;
            const int kc = c >> 6, kk = c & 63, u = kk >> 3;
            const float b0 = bias ? bias[c] : 0.f;
            const float b1 = bias ? bias[c + 1] : 0.f;
#pragma unroll
            for (int half = 0; half < 2; half++) {
                const int r = wm * 32 + mt * 16 + (lane >> 2) + half * 8;
                float e0 = acc[mt][nt][half * 2] + b0;
                float e1 = acc[mt][nt][half * 2 + 1] + b1;
                if (ACT == 1) { e0 = fmaxf(e0, 0.f); e1 = fmaxf(e1, 0.f); }
                if (ACT == 2) { e0 = gelu_f(e0); e1 = gelu_f(e1); }
                bf16 h0 = __float2bfloat16_rn(e0);
                bf16 h1 = __float2bfloat16_rn(e1);
                __nv_bfloat162 hp; hp.x = h0; hp.y = h1;
                __nv_bfloat162 lp;
                lp.x = __float2bfloat16_rn(e0 - __bfloat162float(h0));
                lp.y = __float2bfloat16_rn(e1 - __bfloat162float(h1));
                const uint32_t ad = kc * 16384 + r * 128 +
                                    (uint32_t)(((u ^ (r & 7))) << 4) + (kk & 7) * 2;
                *(__nv_bfloat162*)(smemp + baseHi + ad) = hp;
                *(__nv_bfloat162*)(smemp + baseLo + ad) = lp;
            }
        }
}

// ---------------- MEGA kernel (512 threads): W_red -> x-chain -> logits ; v-chain -> V ----------------
// smem (224 KB): [0,64K) heHi (4 chunks), [64K,128K) heLo, [128K,192K) xv, [192K,224K) stg
__global__ __launch_bounds__(512, 1)
void mega_kernel(const float* __restrict__ Vff, const float* __restrict__ HE,
                 const float* __restrict__ bn_st,
                 const bf16* __restrict__ hVh, const bf16* __restrict__ hVl,
                 const int* __restrict__ eidx,
                 const bf16* __restrict__ wredh, const bf16* __restrict__ wredl,
                 const bf16* __restrict__ wb1h, const bf16* __restrict__ wb1l,
                 const float* __restrict__ bb1,
                 const bf16* __restrict__ wb2h, const bf16* __restrict__ wb2l,
                 const float* __restrict__ bb2,
                 const float* __restrict__ Wb3, const float* __restrict__ bb3,
                 const bf16* __restrict__ wv1h, const bf16* __restrict__ wv1l,
                 const float* __restrict__ bv1,
                 const bf16* __restrict__ wv2h, const bf16* __restrict__ wv2l,
                 const float* __restrict__ bv2,
                 const bf16* __restrict__ wv3h, const bf16* __restrict__ wv3l,
                 const float* __restrict__ bv3,
                 float* __restrict__ logit, unsigned* __restrict__ gmax,
                 float* __restrict__ Vout, int M)
{
    extern __shared__ char smem[];
    const uint32_t sb = smem_u32(smem);
    const uint32_t heHi = sb;
    const uint32_t heLo = sb + 65536;
    const uint32_t xv   = sb + 131072;
    const uint32_t stg  = sb + 196608;
    const int tid = threadIdx.x;
    const int wid = tid >> 5, lane = tid & 31;
    const int row0 = blockIdx.x * 128;

    const int lr = tid >> 2;              // 4 threads per row
    const int arow = (row0 + lr < M) ? (row0 + lr) : (M - 1);
    const int cu0 = (tid & 3) * 4;        // fp32 16B-unit base for A convert

    // ================= P0: hE = [vff_bn | h_E] @ W_red (K=320, N=256) =================
    // A: register-prefetched fp32 -> converted to planes in xv[0,32K)
    // B: Bhi in xv[32K,64K), Blo in stg; half-chunk ping-pong pipeline (10 halves)
    {
        float acc0[2][8][4];
#pragma unroll
        for (int i = 0; i < 2; i++)
#pragma unroll
            for (int j = 0; j < 8; j++)
#pragma unroll
                for (int q = 0; q < 4; q++) acc0[i][j][q] = 0.f;

        // preload A(kc=0) into registers
        float4 areg[4];
        {
            const float4* pa = (const float4*)(Vff + (size_t)arow * 64);
#pragma unroll
            for (int jj = 0; jj < 4; jj++) areg[jj] = pa[cu0 + jj];
        }
        stage_half(xv + 32768, stg, wredh, wredl, 320, 0, 0, 256, tid);

        for (int kc = 0; kc < 5; kc++) {
            // convert A regs -> hi/lo planes in xv[0,32K)
            {
                float4 f[4];
#pragma unroll
                for (int jj = 0; jj < 4; jj++) f[jj] = areg[jj];
                if (kc == 0 && cu0 >= 12) {
#pragma unroll
                    for (int jj = 0; jj < 4; jj++) {
                        const int u = cu0 + jj;
                        if (u >= 12) {
                            const int col = u * 4;
                            f[jj].x = fmaf(f[jj].x, bn_st[col - 48], bn_st[col - 32]);
                            f[jj].y = fmaf(f[jj].y, bn_st[col - 47], bn_st[col - 31]);
                            f[jj].z = fmaf(f[jj].z, bn_st[col - 46], bn_st[col - 30]);
                            f[jj].w = fmaf(f[jj].w, bn_st[col - 45], bn_st[col - 29]);
                        }
                    }
                }
#pragma unroll
                for (int jj = 0; jj < 2; jj++) {
                    float v[8] = {f[2 * jj].x, f[2 * jj].y, f[2 * jj].z, f[2 * jj].w,
                                  f[2 * jj + 1].x, f[2 * jj + 1].y, f[2 * jj + 1].z, f[2 * jj + 1].w};
                    uint32_t ph[4], pl[4];
#pragma unroll
                    for (int j = 0; j < 4; j++) {
                        float a = v[2 * j], b = v[2 * j + 1];
                        bf16 ha = __float2bfloat16_rn(a);
                        bf16 hb = __float2bfloat16_rn(b);
                        __nv_bfloat162 hp; hp.x = ha; hp.y = hb;
                        __nv_bfloat162 lp;
                        lp.x = __float2bfloat16_rn(a - __bfloat162float(ha));
                        lp.y = __float2bfloat16_rn(b - __bfloat162float(hb));
                        ph[j] = reinterpret_cast<uint32_t&>(hp);
                        pl[j] = reinterpret_cast<uint32_t&>(lp);
                    }
                    const int un = (cu0 >> 1) + jj;
                    const uint32_t ad = lr * 128 + (uint32_t)(((un ^ (lr & 7))) << 4);
                    *(uint4*)(smem + 131072 + ad)         = make_uint4(ph[0], ph[1], ph[2], ph[3]);
                    *(uint4*)(smem + 131072 + 16384 + ad) = make_uint4(pl[0], pl[1], pl[2], pl[3]);
                }
            }
            // prefetch A(kc+1) into registers (latency hidden by the 2 mma halves)
            if (kc < 4) {
                const float4* pa = (const float4*)(HE + (size_t)arow * 256 + kc * 64);
#pragma unroll
                for (int jj = 0; jj < 4; jj++) areg[jj] = pa[cu0 + jj];
            }
            // two B halves, pipelined
#pragma unroll
            for (int hh = 0; hh < 2; hh++) {
                const int h = kc * 2 + hh;
                if (h + 1 < 10) {
                    stage_half(xv + 32768, stg, wredh, wredl, 320,
                               ((h + 1) >> 1) * 64, (h + 1) & 1, 256, tid);
                    CP_WAIT(1);
                } else {
                    CP_WAIT(0);
                }
                __syncthreads();
                mma_half512<8>(acc0, xv, xv + 16384, xv + 32768, stg, hh * 2, tid);
                __syncthreads();
            }
        }

        // epilogue: hE planes -> [0,128K)
        store_planes512<8, 0>(acc0, smem, 0, 65536, nullptr, tid);
    }
    __syncthreads();

    // ================= P1: x1 = relu([hV[center] | hE] @ Wb1 + bb1) =================
    float acc1[2][4][4];
#pragma unroll
    for (int i = 0; i < 2; i++)
#pragma unroll
        for (int j = 0; j < 4; j++)
#pragma unroll
            for (int q = 0; q < 4; q++) acc1[i][j][q] = 0.f;
    {
        const int gr = eidx[arow];
        // stage gathered hV planes (2 chunks) into xv -> one commit group
#pragma unroll
        for (int kc = 0; kc < 2; kc++) {
#pragma unroll
            for (int i = 0; i < 2; i++) {
                const int u = (tid & 3) * 2 + i;
                const uint32_t d = lr * 128 + (uint32_t)(((u ^ (lr & 7))) << 4);
                cp16(xv + kc * 16384 + d,         (const char*)(hVh + (size_t)gr * 128 + kc * 64) + u * 16);
                cp16(xv + 32768 + kc * 16384 + d, (const char*)(hVl + (size_t)gr * 128 + kc * 64) + u * 16);
            }
        }
        CP_COMMIT();

        run_phase<4>(acc1,
            [&](int kc, uint32_t& aHi, uint32_t& aLo) {
                if (kc < 2) { aHi = xv + kc * 16384;         aLo = xv + 32768 + kc * 16384; }
                else        { aHi = heHi + (kc - 2) * 16384; aLo = heLo + (kc - 2) * 16384; }
            },
            wb1h, wb1l, 384, 6, stg, stg + 16384, tid);

        // x1 planes -> xv (hV staging dead)
        store_planes512<4, 1>(acc1, smem, 131072, 131072 + 32768, bb1, tid);
    }
    __syncthreads();

    // ================= P2: x2 = relu(x1 @ Wb2 + bb2) =================
    float acc2[2][4][4];
#pragma unroll
    for (int i = 0; i < 2; i++)
#pragma unroll
        for (int j = 0; j < 4; j++)
#pragma unroll
            for (int q = 0; q < 4; q++) acc2[i][j][q] = 0.f;
    run_phase<4>(acc2,
        [&](int kc, uint32_t& aHi, uint32_t& aLo) {
            aHi = xv + kc * 16384; aLo = xv + 32768 + kc * 16384;
        },
        wb2h, wb2l, 128, 2, stg, stg + 16384, tid);

    // x2 fp32 -> xv (x1 dead)
    {
        const int wm = wid >> 2, wn = wid & 3;
#pragma unroll
        for (int mt = 0; mt < 2; mt++)
#pragma unroll
            for (int nt = 0; nt < 4; nt++) {
                const int c = wn * 32 + nt * 8 + (lane & 3) * 2;
                const float b0 = bb2[c], b1 = bb2[c + 1];
#pragma unroll
                for (int half = 0; half < 2; half++) {
                    const int r = wm * 32 + mt * 16 + (lane >> 2) + half * 8;
                    float e0 = fmaxf(acc2[mt][nt][half * 2] + b0, 0.f);
                    float e1 = fmaxf(acc2[mt][nt][half * 2 + 1] + b1, 0.f);
                    *(float2*)(smem + 131072 + ((size_t)r * 128 + c) * 4) = make_float2(e0, e1);
                }
            }
    }
    // Wb3 transposed into stg
    {
        float* wb3s = (float*)(smem + 196608);
        if (tid < 128) {
#pragma unroll
            for (int h = 0; h < 4; h++) wb3s[h * 128 + tid] = Wb3[tid * 8 + h];
        }
    }
    __syncthreads();

    // ================= P3: logits + segment max =================
    {
        const float* x2s = (const float*)(smem + 131072);
        const float* wb3s = (const float*)(smem + 196608);
        for (int rr = wid * 8; rr < wid * 8 + 8; rr++) {
            const int e = row0 + rr;
            if (e >= M) break;
            float p0 = 0.f, p1 = 0.f, p2 = 0.f, p3 = 0.f;
#pragma unroll
            for (int j = 0; j < 4; j++) {
                const int c = lane + j * 32;
                const float x = x2s[rr * 128 + c];
                p0 += x * wb3s[c];
                p1 += x * wb3s[128 + c];
                p2 += x * wb3s[256 + c];
                p3 += x * wb3s[384 + c];
            }
#pragma unroll
            for (int off = 16; off; off >>= 1) {
                p0 += __shfl_xor_sync(0xffffffffu, p0, off);
                p1 += __shfl_xor_sync(0xffffffffu, p1, off);
                p2 += __shfl_xor_sync(0xffffffffu, p2, off);
                p3 += __shfl_xor_sync(0xffffffffu, p3, off);
            }
            if (lane < 4) {
                const float p = (lane == 0) ? p0 : (lane == 1) ? p1 : (lane == 2) ? p2 : p3;
                const float l = (p + bb3[lane]) * 0.17677669529663687f;
                logit[(size_t)e * 4 + lane] = l;
                atomicMax(&gmax[eidx[e] * 4 + lane], fenc(l));
            }
        }
    }
    __syncthreads();

    // ================= P4: v1 = gelu(hE @ Wv1 + bv1) =================
    float acc3[2][4][4];
#pragma unroll
    for (int i = 0; i < 2; i++)
#pragma unroll
        for (int j = 0; j < 4; j++)
#pragma unroll
            for (int q = 0; q < 4; q++) acc3[i][j][q] = 0.f;
    run_phase<4>(acc3,
        [&](int kc, uint32_t& aHi, uint32_t& aLo) {
            aHi = heHi + kc * 16384; aLo = heLo + kc * 16384;
        },
        wv1h, wv1l, 256, 4, stg, stg + 16384, tid);
    store_planes512<4, 2>(acc3, smem, 131072, 131072 + 32768, bv1, tid);  // v1 -> xv (x2 dead)
    __syncthreads();

    // ================= P5: v2 = gelu(v1 @ Wv2 + bv2) =================
    float acc4[2][4][4];
#pragma unroll
    for (int i = 0; i < 2; i++)
#pragma unroll
        for (int j = 0; j < 4; j++)
#pragma unroll
            for (int q = 0; q < 4; q++) acc4[i][j][q] = 0.f;
    run_phase<4>(acc4,
        [&](int kc, uint32_t& aHi, uint32_t& aLo) {
            aHi = xv + kc * 16384; aLo = xv + 32768 + kc * 16384;
        },
        wv2h, wv2l, 128, 2, stg, stg + 16384, tid);
    store_planes512<4, 2>(acc4, smem, 0, 32768, bv2, tid);  // v2 -> hE region (dead)
    __syncthreads();

    // ================= P6: V = v2 @ Wv3 + bv3 -> global fp32 =================
    float acc5[2][4][4];
#pragma unroll
    for (int i = 0; i < 2; i++)
#pragma unroll
        for (int j = 0; j < 4; j++)
#pragma unroll
            for (int q = 0; q < 4; q++) acc5[i][j][q] = 0.f;
    run_phase<4>(acc5,
        [&](int kc, uint32_t& aHi, uint32_t& aLo) {
            aHi = heHi + kc * 16384; aLo = heHi + 32768 + kc * 16384;
        },
        wv3h, wv3l, 128, 2, stg, stg + 16384, tid);
    {
        const int wm = wid >> 2, wn = wid & 3;
#pragma unroll
        for (int mt = 0; mt < 2; mt++) {
            const int r = row0 + wm * 32 + mt * 16 + (lane >> 2);
#pragma unroll
            for (int nt = 0; nt < 4; nt++) {
                const int c = wn * 32 + nt * 8 + (lane & 3) * 2;
                const float b0 = bv3[c], b1 = bv3[c + 1];
#pragma unroll
                for (int half = 0; half < 2; half++) {
                    const int rr = r + half * 8;
                    if (rr >= M) continue;
                    *(float2*)(Vout + (size_t)rr * 128 + c) =
                        make_float2(acc5[mt][nt][half * 2] + b0,
                                    acc5[mt][nt][half * 2 + 1] + b1);
                }
            }
        }
    }
}

// ---------------- exp + segment sum ----------------
__global__ void expsum_kernel(float* __restrict__ logit, const int* __restrict__ center,
                              const unsigned* __restrict__ gmax, float* __restrict__ gsum, int E)
{
    int idx = blockIdx.x * 256 + threadIdx.x;
    if (idx >= E * 4) return;
    int e = idx >> 2, h = idx & 3;
    int c = center[e];
    float m = fdec(gmax[c * 4 + h]);
    float ex = expf(logit[idx] - m);
    logit[idx] = ex;
    atomicAdd(&gsum[c * 4 + h], ex);
}

// ---------------- weighted segment aggregation ----------------
__global__ void agg_kernel(const float* __restrict__ gexp, const float* __restrict__ gsum,
                           const float* __restrict__ V, const int* __restrict__ center,
                           float* __restrict__ hagg, int E)
{
    int idx = blockIdx.x * 256 + threadIdx.x;
    if (idx >= E * 128) return;
    int e = idx >> 7, t = idx & 127, h = t >> 5;
    int c = center[e];
    float att = gexp[e * 4 + h] / gsum[c * 4 + h];
    atomicAdd(&hagg[c * 128 + t], att * V[idx]);
}

// ---------------- standalone GEMM (W_O), 256 threads (tiny) ----------------
__device__ __forceinline__ void ldsm_mma8(float (&acc)[2][8][4], uint32_t aB, uint32_t bB, int tid)
{
    const int wid = tid >> 5, lane = tid & 31;
    const int wm = wid >> 1, wn = wid & 1;
    const int a_row = wm * 32 + (lane & 7) + ((lane & 8) ? 8 : 0);
    const int a_ub  = (lane & 16) ? 1 : 0;
    const int b_row0 = wn * 64 + (lane & 7) + ((lane & 16) ? 8 : 0);
    const int b_ub  = (lane & 8) ? 1 : 0;
#pragma unroll
    for (int ks = 0; ks < 4; ks++) {
        uint32_t ahi[2][4], alo[2][4];
#pragma unroll
        for (int mt = 0; mt < 2; mt++) {
            const int r = a_row + mt * 16;
            const int u = ks * 2 + a_ub;
            const uint32_t off = r * 128 + (uint32_t)(((u ^ (r & 7))) << 4);
            ldsm4(ahi[mt], aB + off);
            ldsm4(alo[mt], aB + 16384 + off);
        }
        uint32_t bhi[4][4], blo[4][4];
#pragma unroll
        for (int g = 0; g < 4; g++) {
            const int n = b_row0 + g * 16;
            const int u = ks * 2 + b_ub;
            const uint32_t off = n * 128 + (uint32_t)(((u ^ (n & 7))) << 4);
            ldsm4(bhi[g], bB + off);
            ldsm4(blo[g], bB + 16384 + off);
        }
#pragma unroll
        for (int mt = 0; mt < 2; mt++)
#pragma unroll
            for (int ntl = 0; ntl < 8; ntl++) {
                float* a_ = acc[mt][ntl];
                const uint32_t* bh = &bhi[ntl >> 1][(ntl & 1) * 2];
                const uint32_t* bl = &blo[ntl >> 1][(ntl & 1) * 2];
                mma16816(a_, ahi[mt], bh);
                mma16816(a_, ahi[mt], bl);
                mma16816(a_, alo[mt], bh);
            }
    }
}

__global__ __launch_bounds__(256, 1)
void hmma_gemm_o(const bf16* __restrict__ Ahi, const bf16* __restrict__ Alo,
                 const bf16* __restrict__ Bhi, const bf16* __restrict__ Blo,
                 float* __restrict__ Cf, int M)
{
    extern __shared__ char smem[];
    const uint32_t sb = smem_u32(smem);
    const int tid = threadIdx.x;
    const int wid = tid >> 5, lane = tid & 31;
    const int row0 = blockIdx.x * 128;

    const int lr = tid >> 1;
    const int arow = (row0 + lr < M) ? (row0 + lr) : (M - 1);

    float acc[2][8][4];
#pragma unroll
    for (int i = 0; i < 2; i++)
#pragma unroll
        for (int j = 0; j < 8; j++)
#pragma unroll
            for (int q = 0; q < 4; q++) acc[i][j][q] = 0.f;

    for (int kc = 0; kc < 2; kc++) {
        const int k0 = kc * 64;
#pragma unroll
        for (int i = 0; i < 4; i++) {
            const int u = (tid & 1) * 4 + i;
            const uint32_t d = lr * 128 + (uint32_t)(((u ^ (lr & 7))) << 4);
            cp16(sb + d,         (const char*)(Ahi + (size_t)arow * 128 + k0) + u * 16);
            cp16(sb + 16384 + d, (const char*)(Alo + (size_t)arow * 128 + k0) + u * 16);
        }
        for (int i = tid; i < 128 * 8; i += 256) {
            const int r = i >> 3, u = i & 7;
            const uint32_t d = r * 128 + (uint32_t)(((u ^ (r & 7))) << 4);
            cp16(sb + 32768 + d, (const char*)(Bhi + (size_t)r * 128 + k0) + u * 16);
            cp16(sb + 49152 + d, (const char*)(Blo + (size_t)r * 128 + k0) + u * 16);
        }
        CP_COMMIT();
        CP_WAIT(0);
        __syncthreads();
        ldsm_mma8(acc, sb, sb + 32768, tid);
        __syncthreads();
    }

    const int wm = wid >> 1, wn = wid & 1;
#pragma unroll
    for (int mt = 0; mt < 2; mt++) {
        const int r = row0 + wm * 32 + mt * 16 + (lane >> 2);
#pragma unroll
        for (int nt = 0; nt < 8; nt++) {
            const int c = wn * 64 + nt * 8 + (lane & 3) * 2;
#pragma unroll
            for (int half = 0; half < 2; half++) {
                const int rr = r + half * 8;
                if (rr >= M) continue;
                *(float2*)(Cf + (size_t)rr * 128 + c) =
                    make_float2(acc[mt][nt][half * 2], acc[mt][nt][half * 2 + 1]);
            }
        }
    }
}

// ---------------- host launch ----------------
extern "C" void kernel_launch(void* const* d_in, const int* in_sizes, int n_in,
                              void* d_out, int out_size)
{
    const float* h_V   = (const float*)d_in[0];
    const float* h_E   = (const float*)d_in[1];
    const int*   eidx  = (const int*)  d_in[2];
    const float* hvv   = (const float*)d_in[3];
    const float* frame = (const float*)d_in[4];
    const float* W_vec = (const float*)d_in[5];
    const float* W_red = (const float*)d_in[6];
    const float* Wb1   = (const float*)d_in[7];
    const float* bb1   = (const float*)d_in[8];
    const float* Wb2   = (const float*)d_in[9];
    const float* bb2   = (const float*)d_in[10];
    const float* Wb3   = (const float*)d_in[11];
    const float* bb3   = (const float*)d_in[12];
    const float* Wv1   = (const float*)d_in[13];
    const float* bv1   = (const float*)d_in[14];
    const float* Wv2   = (const float*)d_in[15];
    const float* bv2   = (const float*)d_in[16];
    const float* Wv3   = (const float*)d_in[17];
    const float* bv3   = (const float*)d_in[18];
    const float* W_O   = (const float*)d_in[19];
    const float* bn_g  = (const float*)d_in[20];
    const float* bn_b  = (const float*)d_in[21];

    int E = in_sizes[2] / 2;
    int N = in_sizes[0] / 128;
    float* out = (float*)d_out;

    float *vff, *Vbuf, *logit, *gsum, *hagg, *bnst;
    bf16 *hVh, *hVl, *hgh, *hgl, *wh, *wl;
    unsigned* gmax;
    double* bnacc;
    cudaGetSymbolAddress((void**)&vff,   g_vff);
    cudaGetSymbolAddress((void**)&Vbuf,  g_V);
    cudaGetSymbolAddress((void**)&hVh,   g_hVh);
    cudaGetSymbolAddress((void**)&hVl,   g_hVl);
    cudaGetSymbolAddress((void**)&hgh,   g_hgh);
    cudaGetSymbolAddress((void**)&hgl,   g_hgl);
    cudaGetSymbolAddress((void**)&wh,    g_wh);
    cudaGetSymbolAddress((void**)&wl,    g_wl);
    cudaGetSymbolAddress((void**)&logit, g_logit);
    cudaGetSymbolAddress((void**)&gmax,  g_max);
    cudaGetSymbolAddress((void**)&gsum,  g_sum);
    cudaGetSymbolAddress((void**)&hagg,  g_hagg);
    cudaGetSymbolAddress((void**)&bnacc, g_bnacc);
    cudaGetSymbolAddress((void**)&bnst,  g_bnst);

    const int SMEM_M = 229376;   // 224 KB
    const int SMEM_O = 65536;
    cudaFuncSetAttribute(mega_kernel, cudaFuncAttributeMaxDynamicSharedMemorySize, SMEM_M);
    cudaFuncSetAttribute(hmma_gemm_o, cudaFuncAttributeMaxDynamicSharedMemorySize, SMEM_O);

    int Mt = (E + 127) / 128;
    int Mo = (N + 127) / 128;

    init_kernel<<<(N * 128 + 255) / 256, 256>>>(gmax, gsum, hagg, bnacc, N);
    geom_kernel<<<(E + 255) / 256, 256>>>(eidx, hvv, frame, W_vec, vff, bnacc, E);
    bn_finalize<<<1, 32>>>(bnacc, bn_g, bn_b, bnst, E);

    wprep_all<<<(W_TOTAL + 255) / 256, 256>>>(W_red, Wb1, Wb2, Wv1, Wv2, Wv3, W_O, wh, wl);
    c2planes<<<(N * 128 + 255) / 256, 256>>>(h_V, hVh, hVl, (size_t)N * 128);

    mega_kernel<<<Mt, 512, SMEM_M>>>(
        vff, h_E, bnst, hVh, hVl, eidx,
        wh + OW_RED, wl + OW_RED,
        wh + OW_B1, wl + OW_B1, bb1,
        wh + OW_B2, wl + OW_B2, bb2,
        Wb3, bb3,
        wh + OW_V1, wl + OW_V1, bv1,
        wh + OW_V2, wl + OW_V2, bv2,
        wh + OW_V3, wl + OW_V3, bv3,
        logit, gmax, Vbuf, E);

    expsum_kernel<<<(E * 4 + 255) / 256, 256>>>(logit, eidx, gmax, gsum, E);
    agg_kernel<<<(int)(((size_t)E * 128 + 255) / 256), 256>>>(logit, gsum, Vbuf, eidx, hagg, E);

    c2planes<<<(N * 128 + 255) / 256, 256>>>(hagg, hgh, hgl, (size_t)N * 128);
    hmma_gemm_o<<<Mo, 256, SMEM_O>>>(hgh, hgl, wh + OW_O, wl + OW_O, out, N);
}

// round 9
// speedup vs baseline: 3.4105x; 1.1137x over previous
#include <cuda_runtime.h>
#include <cuda_bf16.h>
#include <math.h>
#include <stdint.h>

#define E_CONST 320000
#define N_CONST 10000
typedef __nv_bfloat16 bf16;

// ---------------- scratch (no allocations allowed) ----------------
static __device__ float    g_vff [(size_t)E_CONST * 64];   // fp32 [sincos48|dist16]
static __device__ bf16     g_hVh [N_CONST * 128];
static __device__ bf16     g_hVl [N_CONST * 128];
static __device__ bf16     g_hgh [N_CONST * 128];
static __device__ bf16     g_hgl [N_CONST * 128];
static __device__ bf16     g_wh  [262144];                 // all weights, [n][k]
static __device__ bf16     g_wl  [262144];
static __device__ float    g_sum [N_CONST * 4];
static __device__ float    g_hagg[N_CONST * 128];
static __device__ double   g_bnacc[32];
static __device__ float    g_bnst[32];

// weight plane offsets (elements)
#define OW_RED 0        // 256 x 320
#define OW_B1  81920    // 128 x 384
#define OW_B2  131072   // 128 x 128
#define OW_V1  147456   // 128 x 256
#define OW_V2  180224   // 128 x 128
#define OW_V3  196608   // 128 x 128
#define OW_O   212992   // 128 x 128
#define W_TOTAL 229376

// mega smem tail (beyond the 224KB working set)
#define ATT_OFF 229376
#define CEN_OFF 231424
#define SMEM_MEGA 231936

// ---------------- helpers ----------------
__device__ __forceinline__ uint32_t smem_u32(const void* p) {
    uint32_t a;
    asm("{ .reg .u64 t; cvta.to.shared.u64 t, %1; cvt.u32.u64 %0, t; }" : "=r"(a) : "l"(p));
    return a;
}
__device__ __forceinline__ void cp16(uint32_t dst, const void* src) {
    asm volatile("cp.async.cg.shared.global [%0], [%1], 16;"
        :: "r"(dst), "l"(__cvta_generic_to_global(src)) : "memory");
}
#define CP_COMMIT() asm volatile("cp.async.commit_group;" ::: "memory")
#define CP_WAIT(n)  asm volatile("cp.async.wait_group %0;" :: "n"(n) : "memory")

__device__ __forceinline__ void ldsm4(uint32_t* r, uint32_t addr) {
    asm volatile("ldmatrix.sync.aligned.m8n8.x4.shared.b16 {%0,%1,%2,%3}, [%4];"
        : "=r"(r[0]), "=r"(r[1]), "=r"(r[2]), "=r"(r[3]) : "r"(addr));
}
__device__ __forceinline__ void mma16816(float* d, const uint32_t* a, const uint32_t* b) {
    asm volatile(
        "mma.sync.aligned.m16n8k16.row.col.f32.bf16.bf16.f32 "
        "{%0,%1,%2,%3}, {%4,%5,%6,%7}, {%8,%9}, {%0,%1,%2,%3};"
        : "+f"(d[0]), "+f"(d[1]), "+f"(d[2]), "+f"(d[3])
        : "r"(a[0]), "r"(a[1]), "r"(a[2]), "r"(a[3]), "r"(b[0]), "r"(b[1]));
}
__device__ __forceinline__ void red2(float* addr, float x, float y) {
    asm volatile("red.global.v2.f32.add [%0], {%1, %2};"
        :: "l"(__cvta_generic_to_global(addr)), "f"(x), "f"(y) : "memory");
}
__device__ __forceinline__ float gelu_f(float x) {
    return 0.5f * x * (1.f + erff(x * 0.70710678118654752f));
}

// ---------------- init ----------------
__global__ void init_kernel(float* gsum, float* hagg, double* bnacc, int N)
{
    int i = blockIdx.x * 256 + threadIdx.x;
    if (i < N * 128) hagg[i] = 0.f;
    if (i < N * 4) gsum[i] = 0.f;
    if (i < 32) bnacc[i] = 0.0;
}

// ---------------- geometry + BN stats ----------------
__global__ __launch_bounds__(256)
void geom_kernel(const int* __restrict__ eidx, const float* __restrict__ hvv,
                 const float* __restrict__ frame, const float* __restrict__ Wvec,
                 float* __restrict__ vff, double* __restrict__ bnacc, int E)
{
    __shared__ float Ws[512];
    __shared__ float bsum[16], bsq[16];
    int tid = threadIdx.x;
    for (int i = tid; i < 512; i += 256) Ws[i] = Wvec[i];
    if (tid < 16) { bsum[tid] = 0.f; bsq[tid] = 0.f; }
    __syncthreads();

    int e = blockIdx.x * 256 + tid;
    float dloc[16];
#pragma unroll
    for (int o = 0; o < 16; o++) dloc[o] = 0.f;

    if (e < E) {
        int c = eidx[e];
        int d = eidx[E + e];
        float F[9];
#pragma unroll
        for (int i = 0; i < 9; i++) F[i] = frame[e * 9 + i];
        float vdt[48], vsrc[48];
#pragma unroll
        for (int v = 0; v < 16; v++) {
            float x = hvv[d * 48 + v * 3 + 0];
            float y = hvv[d * 48 + v * 3 + 1];
            float z = hvv[d * 48 + v * 3 + 2];
            vdt[v * 3 + 0] = F[0] * x + F[1] * y + F[2] * z;
            vdt[v * 3 + 1] = F[3] * x + F[4] * y + F[5] * z;
            vdt[v * 3 + 2] = F[6] * x + F[7] * y + F[8] * z;
        }
#pragma unroll
        for (int i = 0; i < 48; i++) vsrc[i] = hvv[c * 48 + i];

#pragma unroll
        for (int o = 0; o < 16; o++) {
            float v0 = vdt[o * 3 + 0], v1 = vdt[o * 3 + 1], v2 = vdt[o * 3 + 2];
#pragma unroll
            for (int v = 0; v < 16; v++) {
                float wa = Ws[o * 32 + v], wb = Ws[o * 32 + 16 + v];
                v0 += wa * vdt[v * 3 + 0] + wb * vsrc[v * 3 + 0];
                v1 += wa * vdt[v * 3 + 1] + wb * vsrc[v * 3 + 1];
                v2 += wa * vdt[v * 3 + 2] + wb * vsrc[v * 3 + 2];
            }
            float dist = sqrtf(v0 * v0 + v1 * v1 + v2 * v2) + 1e-6f;
            float inv = 1.f / dist;
            vff[e * 64 + o * 3 + 0] = v0 * inv;
            vff[e * 64 + o * 3 + 1] = v1 * inv;
            vff[e * 64 + o * 3 + 2] = v2 * inv;
            vff[e * 64 + 48 + o] = dist;
            dloc[o] = dist;
        }
    }

#pragma unroll
    for (int o = 0; o < 16; o++) {
        float v = dloc[o], v2 = v * v;
#pragma unroll
        for (int off = 16; off; off >>= 1) {
            v  += __shfl_down_sync(0xffffffffu, v, off);
            v2 += __shfl_down_sync(0xffffffffu, v2, off);
        }
        if ((tid & 31) == 0) { atomicAdd(&bsum[o], v); atomicAdd(&bsq[o], v2); }
    }
    __syncthreads();
    if (tid < 16) {
        atomicAdd(&bnacc[tid], (double)bsum[tid]);
        atomicAdd(&bnacc[16 + tid], (double)bsq[tid]);
    }
}

__global__ void bn_finalize(const double* __restrict__ acc, const float* __restrict__ g,
                            const float* __restrict__ b, float* __restrict__ st, int E)
{
    int i = threadIdx.x;
    if (i >= 16) return;
    double mean = acc[i] / (double)E;
    double var  = acc[16 + i] / (double)E - mean * mean;
    float s = (float)((double)g[i] / sqrt(var + 1e-5));
    st[i] = s;
    st[16 + i] = b[i] - (float)mean * s;
}

// ---------------- conversion passes ----------------
__global__ void wprep_all(const float* __restrict__ W0, const float* __restrict__ W1,
                          const float* __restrict__ W2, const float* __restrict__ W3,
                          const float* __restrict__ W4, const float* __restrict__ W5,
                          const float* __restrict__ W6,
                          bf16* __restrict__ hi, bf16* __restrict__ lo)
{
    int idx = blockIdx.x * 256 + threadIdx.x;
    if (idx >= W_TOTAL) return;
    const float* src; int K, NT, start;
    if      (idx < OW_B1)  { src = W0; K = 320; NT = 256; start = OW_RED; }
    else if (idx < OW_B2)  { src = W1; K = 384; NT = 128; start = OW_B1; }
    else if (idx < OW_V1)  { src = W2; K = 128; NT = 128; start = OW_B2; }
    else if (idx < OW_V2)  { src = W3; K = 256; NT = 128; start = OW_V1; }
    else if (idx < OW_V3)  { src = W4; K = 128; NT = 128; start = OW_V2; }
    else if (idx < OW_O)   { src = W5; K = 128; NT = 128; start = OW_V3; }
    else                   { src = W6; K = 128; NT = 128; start = OW_O; }
    int local = idx - start;
    int k = local / NT, n = local % NT;
    float v = src[local];
    bf16 h = __float2bfloat16_rn(v);
    hi[start + (size_t)n * K + k] = h;
    lo[start + (size_t)n * K + k] = __float2bfloat16_rn(v - __bfloat162float(h));
}

__global__ void c2planes(const float* __restrict__ x, bf16* __restrict__ hi,
                         bf16* __restrict__ lo, size_t n)
{
    size_t i = (size_t)blockIdx.x * 256 + threadIdx.x;
    if (i >= n) return;
    float v = x[i];
    bf16 h = __float2bfloat16_rn(v);
    hi[i] = h;
    lo[i] = __float2bfloat16_rn(v - __bfloat162float(h));
}

// hagg -> planes with softmax normalization folded in
__global__ void c2planes_norm(const float* __restrict__ x, const float* __restrict__ gsum,
                              bf16* __restrict__ hi, bf16* __restrict__ lo, int N)
{
    int i = blockIdx.x * 256 + threadIdx.x;
    if (i >= N * 128) return;
    int node = i >> 7, col = i & 127;
    float s = gsum[node * 4 + (col >> 5)];
    float v = x[i] / (s > 0.f ? s : 1.f);
    bf16 h = __float2bfloat16_rn(v);
    hi[i] = h;
    lo[i] = __float2bfloat16_rn(v - __bfloat162float(h));
}

// ================= GEMM building blocks (512 threads, 16 warps = 4m x 4n) =================
template<int NT>
__device__ __forceinline__ void mma_half512(
    float (&acc)[2][NT][4], uint32_t aHi, uint32_t aLo,
    uint32_t bHi, uint32_t bLo, int ks0, int tid)
{
    const int wid = tid >> 5, lane = tid & 31;
    const int wm = wid >> 2, wn = wid & 3;
    const int a_row = wm * 32 + (lane & 7) + ((lane & 8) ? 8 : 0);
    const int a_ub  = (lane & 16) ? 1 : 0;
    const int b_row0 = wn * (NT * 8) + (lane & 7) + ((lane & 16) ? 8 : 0);
    const int b_ub  = (lane & 8) ? 1 : 0;
#pragma unroll
    for (int kss = 0; kss < 2; kss++) {
        const int ks = ks0 + kss;
        uint32_t ahi[2][4], alo[2][4];
#pragma unroll
        for (int mt = 0; mt < 2; mt++) {
            const int r = a_row + mt * 16;
            const int u = ks * 2 + a_ub;
            const uint32_t off = r * 128 + (uint32_t)(((u ^ (r & 7))) << 4);
            ldsm4(ahi[mt], aHi + off);
            ldsm4(alo[mt], aLo + off);
        }
        uint32_t bhi[NT / 2][4], blo[NT / 2][4];
#pragma unroll
        for (int g = 0; g < NT / 2; g++) {
            const int n = b_row0 + g * 16;
            const int u = ks * 2 + b_ub;
            const uint32_t off = n * 128 + (uint32_t)(((u ^ (n & 7))) << 4);
            ldsm4(bhi[g], bHi + off);
            ldsm4(blo[g], bLo + off);
        }
#pragma unroll
        for (int mt = 0; mt < 2; mt++)
#pragma unroll
            for (int ntl = 0; ntl < NT; ntl++) {
                float* a_ = acc[mt][ntl];
                const uint32_t* bh = &bhi[ntl >> 1][(ntl & 1) * 2];
                const uint32_t* bl = &blo[ntl >> 1][(ntl & 1) * 2];
                mma16816(a_, ahi[mt], bh);
                mma16816(a_, ahi[mt], bl);
                mma16816(a_, alo[mt], bh);
            }
    }
}

__device__ __forceinline__ void stage_half(uint32_t dstHi, uint32_t dstLo,
                                           const bf16* __restrict__ Whi,
                                           const bf16* __restrict__ Wlo,
                                           int K, int k0, int half, int rows, int tid)
{
    for (int i = tid; i < rows * 4; i += 512) {
        const int r = i >> 2, u = (i & 3) + half * 4;
        const uint32_t d = r * 128 + (uint32_t)(((u ^ (r & 7))) << 4);
        cp16(dstHi + d, (const char*)(Whi + (size_t)r * K + k0) + u * 16);
        cp16(dstLo + d, (const char*)(Wlo + (size_t)r * K + k0) + u * 16);
    }
    CP_COMMIT();
}

template<int NT, typename FA>
__device__ __forceinline__ void run_phase(float (&acc)[2][NT][4], FA addrA,
                                          const bf16* __restrict__ Wh, const bf16* __restrict__ Wl,
                                          int K, int nch, uint32_t bHi, uint32_t bLo, int tid)
{
    stage_half(bHi, bLo, Wh, Wl, K, 0, 0, 128, tid);
    const int H = nch * 2;
    for (int h = 0; h < H; h++) {
        if (h + 1 < H) {
            stage_half(bHi, bLo, Wh, Wl, K, ((h + 1) >> 1) * 64, (h + 1) & 1, 128, tid);
            CP_WAIT(1);
        } else {
            CP_WAIT(0);
        }
        __syncthreads();
        uint32_t aHi, aLo;
        addrA(h >> 1, aHi, aLo);
        mma_half512<NT>(acc, aHi, aLo, bHi, bLo, (h & 1) * 2, tid);
        __syncthreads();
    }
}

template<int NT, int ACT>
__device__ __forceinline__ void store_planes512(const float (&acc)[2][NT][4],
                                                char* smemp, uint32_t baseHi, uint32_t baseLo,
                                                const float* __restrict__ bias, int tid)
{
    const int wid = tid >> 5, lane = tid & 31;
    const int wm = wid >> 2, wn = wid & 3;
#pragma unroll
    for (int mt = 0; mt < 2; mt++)
#pragma unroll
        for (int nt = 0; nt < NT; nt++) {
            const int c = wn * (NT * 8) + nt * 8 + (lane & 3) * 2;
            const int kc = c >> 6, kk = c & 63, u = kk >> 3;
            const float b0 = bias ? bias[c] : 0.f;
            const float b1 = bias ? bias[c + 1] : 0.f;
#pragma unroll
            for (int half = 0; half < 2; half++) {
                const int r = wm * 32 + mt * 16 + (lane >> 2) + half * 8;
                float e0 = acc[mt][nt][half * 2] + b0;
                float e1 = acc[mt][nt][half * 2 + 1] + b1;
                if (ACT == 1) { e0 = fmaxf(e0, 0.f); e1 = fmaxf(e1, 0.f); }
                if (ACT == 2) { e0 = gelu_f(e0); e1 = gelu_f(e1); }
                bf16 h0 = __float2bfloat16_rn(e0);
                bf16 h1 = __float2bfloat16_rn(e1);
                __nv_bfloat162 hp; hp.x = h0; hp.y = h1;
                __nv_bfloat162 lp;
                lp.x = __float2bfloat16_rn(e0 - __bfloat162float(h0));
                lp.y = __float2bfloat16_rn(e1 - __bfloat162float(h1));
                const uint32_t ad = kc * 16384 + r * 128 +
                                    (uint32_t)(((u ^ (r & 7))) << 4) + (kk & 7) * 2;
                *(__nv_bfloat162*)(smemp + baseHi + ad) = hp;
                *(__nv_bfloat162*)(smemp + baseLo + ad) = lp;
            }
        }
}

// ---------------- MEGA kernel (512 threads) ----------------
// smem: [0,64K) heHi, [64K,128K) heLo, [128K,192K) xv, [192K,224K) stg,
//       [224K,226K) att (e values), [226K,226.5K) cen
__global__ __launch_bounds__(512, 1)
void mega_kernel(const float* __restrict__ Vff, const float* __restrict__ HE,
                 const float* __restrict__ bn_st,
                 const bf16* __restrict__ hVh, const bf16* __restrict__ hVl,
                 const int* __restrict__ eidx,
                 const bf16* __restrict__ wredh, const bf16* __restrict__ wredl,
                 const bf16* __restrict__ wb1h, const bf16* __restrict__ wb1l,
                 const float* __restrict__ bb1,
                 const bf16* __restrict__ wb2h, const bf16* __restrict__ wb2l,
                 const float* __restrict__ bb2,
                 const float* __restrict__ Wb3, const float* __restrict__ bb3,
                 const bf16* __restrict__ wv1h, const bf16* __restrict__ wv1l,
                 const float* __restrict__ bv1,
                 const bf16* __restrict__ wv2h, const bf16* __restrict__ wv2l,
                 const float* __restrict__ bv2,
                 const bf16* __restrict__ wv3h, const bf16* __restrict__ wv3l,
                 const float* __restrict__ bv3,
                 float* __restrict__ gsum, float* __restrict__ hagg, int M)
{
    extern __shared__ char smem[];
    const uint32_t sb = smem_u32(smem);
    const uint32_t heHi = sb;
    const uint32_t heLo = sb + 65536;
    const uint32_t xv   = sb + 131072;
    const uint32_t stg  = sb + 196608;
    const int tid = threadIdx.x;
    const int wid = tid >> 5, lane = tid & 31;
    const int row0 = blockIdx.x * 128;

    const int lr = tid >> 2;              // 4 threads per row
    const int arow = (row0 + lr < M) ? (row0 + lr) : (M - 1);
    const int cu0 = (tid & 3) * 4;        // fp32 16B-unit base for A convert

    // ================= P0: hE = [vff_bn | h_E] @ W_red (K=320, N=256) =================
    {
        float acc0[2][8][4];
#pragma unroll
        for (int i = 0; i < 2; i++)
#pragma unroll
            for (int j = 0; j < 8; j++)
#pragma unroll
                for (int q = 0; q < 4; q++) acc0[i][j][q] = 0.f;

        float4 areg[4];
        {
            const float4* pa = (const float4*)(Vff + (size_t)arow * 64);
#pragma unroll
            for (int jj = 0; jj < 4; jj++) areg[jj] = pa[cu0 + jj];
        }
        stage_half(xv + 32768, stg, wredh, wredl, 320, 0, 0, 256, tid);

        for (int kc = 0; kc < 5; kc++) {
            {
                float4 f[4];
#pragma unroll
                for (int jj = 0; jj < 4; jj++) f[jj] = areg[jj];
                if (kc == 0 && cu0 >= 12) {
#pragma unroll
                    for (int jj = 0; jj < 4; jj++) {
                        const int u = cu0 + jj;
                        if (u >= 12) {
                            const int col = u * 4;
                            f[jj].x = fmaf(f[jj].x, bn_st[col - 48], bn_st[col - 32]);
                            f[jj].y = fmaf(f[jj].y, bn_st[col - 47], bn_st[col - 31]);
                            f[jj].z = fmaf(f[jj].z, bn_st[col - 46], bn_st[col - 30]);
                            f[jj].w = fmaf(f[jj].w, bn_st[col - 45], bn_st[col - 29]);
                        }
                    }
                }
#pragma unroll
                for (int jj = 0; jj < 2; jj++) {
                    float v[8] = {f[2 * jj].x, f[2 * jj].y, f[2 * jj].z, f[2 * jj].w,
                                  f[2 * jj + 1].x, f[2 * jj + 1].y, f[2 * jj + 1].z, f[2 * jj + 1].w};
                    uint32_t ph[4], pl[4];
#pragma unroll
                    for (int j = 0; j < 4; j++) {
                        float a = v[2 * j], b = v[2 * j + 1];
                        bf16 ha = __float2bfloat16_rn(a);
                        bf16 hb = __float2bfloat16_rn(b);
                        __nv_bfloat162 hp; hp.x = ha; hp.y = hb;
                        __nv_bfloat162 lp;
                        lp.x = __float2bfloat16_rn(a - __bfloat162float(ha));
                        lp.y = __float2bfloat16_rn(b - __bfloat162float(hb));
                        ph[j] = reinterpret_cast<uint32_t&>(hp);
                        pl[j] = reinterpret_cast<uint32_t&>(lp);
                    }
                    const int un = (cu0 >> 1) + jj;
                    const uint32_t ad = lr * 128 + (uint32_t)(((un ^ (lr & 7))) << 4);
                    *(uint4*)(smem + 131072 + ad)         = make_uint4(ph[0], ph[1], ph[2], ph[3]);
                    *(uint4*)(smem + 131072 + 16384 + ad) = make_uint4(pl[0], pl[1], pl[2], pl[3]);
                }
            }
            if (kc < 4) {
                const float4* pa = (const float4*)(HE + (size_t)arow * 256 + kc * 64);
#pragma unroll
                for (int jj = 0; jj < 4; jj++) areg[jj] = pa[cu0 + jj];
            }
#pragma unroll
            for (int hh = 0; hh < 2; hh++) {
                const int h = kc * 2 + hh;
                if (h + 1 < 10) {
                    stage_half(xv + 32768, stg, wredh, wredl, 320,
                               ((h + 1) >> 1) * 64, (h + 1) & 1, 256, tid);
                    CP_WAIT(1);
                } else {
                    CP_WAIT(0);
                }
                __syncthreads();
                mma_half512<8>(acc0, xv, xv + 16384, xv + 32768, stg, hh * 2, tid);
                __syncthreads();
            }
        }

        store_planes512<8, 0>(acc0, smem, 0, 65536, nullptr, tid);
    }
    __syncthreads();

    // ================= P1: x1 = relu([hV[center] | hE] @ Wb1 + bb1) =================
    float acc1[2][4][4];
#pragma unroll
    for (int i = 0; i < 2; i++)
#pragma unroll
        for (int j = 0; j < 4; j++)
#pragma unroll
            for (int q = 0; q < 4; q++) acc1[i][j][q] = 0.f;
    {
        const int gr = eidx[arow];
#pragma unroll
        for (int kc = 0; kc < 2; kc++) {
#pragma unroll
            for (int i = 0; i < 2; i++) {
                const int u = (tid & 3) * 2 + i;
                const uint32_t d = lr * 128 + (uint32_t)(((u ^ (lr & 7))) << 4);
                cp16(xv + kc * 16384 + d,         (const char*)(hVh + (size_t)gr * 128 + kc * 64) + u * 16);
                cp16(xv + 32768 + kc * 16384 + d, (const char*)(hVl + (size_t)gr * 128 + kc * 64) + u * 16);
            }
        }
        CP_COMMIT();

        run_phase<4>(acc1,
            [&](int kc, uint32_t& aHi, uint32_t& aLo) {
                if (kc < 2) { aHi = xv + kc * 16384;         aLo = xv + 32768 + kc * 16384; }
                else        { aHi = heHi + (kc - 2) * 16384; aLo = heLo + (kc - 2) * 16384; }
            },
            wb1h, wb1l, 384, 6, stg, stg + 16384, tid);

        store_planes512<4, 1>(acc1, smem, 131072, 131072 + 32768, bb1, tid);
    }
    __syncthreads();

    // ================= P2: x2 = relu(x1 @ Wb2 + bb2) =================
    float acc2[2][4][4];
#pragma unroll
    for (int i = 0; i < 2; i++)
#pragma unroll
        for (int j = 0; j < 4; j++)
#pragma unroll
            for (int q = 0; q < 4; q++) acc2[i][j][q] = 0.f;
    run_phase<4>(acc2,
        [&](int kc, uint32_t& aHi, uint32_t& aLo) {
            aHi = xv + kc * 16384; aLo = xv + 32768 + kc * 16384;
        },
        wb2h, wb2l, 128, 2, stg, stg + 16384, tid);

    // x2 fp32 -> xv (x1 dead)
    {
        const int wm = wid >> 2, wn = wid & 3;
#pragma unroll
        for (int mt = 0; mt < 2; mt++)
#pragma unroll
            for (int nt = 0; nt < 4; nt++) {
                const int c = wn * 32 + nt * 8 + (lane & 3) * 2;
                const float b0 = bb2[c], b1 = bb2[c + 1];
#pragma unroll
                for (int half = 0; half < 2; half++) {
                    const int r = wm * 32 + mt * 16 + (lane >> 2) + half * 8;
                    float e0 = fmaxf(acc2[mt][nt][half * 2] + b0, 0.f);
                    float e1 = fmaxf(acc2[mt][nt][half * 2 + 1] + b1, 0.f);
                    *(float2*)(smem + 131072 + ((size_t)r * 128 + c) * 4) = make_float2(e0, e1);
                }
            }
    }
    // Wb3 transposed into stg
    {
        float* wb3s = (float*)(smem + 196608);
        if (tid < 128) {
#pragma unroll
            for (int h = 0; h < 4; h++) wb3s[h * 128 + tid] = Wb3[tid * 8 + h];
        }
    }
    __syncthreads();

    // ================= P3: e = exp(logits), segment sum (no max needed) =================
    {
        const float* x2s = (const float*)(smem + 131072);
        const float* wb3s = (const float*)(smem + 196608);
        float* atts = (float*)(smem + ATT_OFF);
        int* cens = (int*)(smem + CEN_OFF);
        for (int rr = wid * 8; rr < wid * 8 + 8; rr++) {
            const int e = row0 + rr;
            if (e >= M) break;
            float p0 = 0.f, p1 = 0.f, p2 = 0.f, p3 = 0.f;
#pragma unroll
            for (int j = 0; j < 4; j++) {
                const int c = lane + j * 32;
                const float x = x2s[rr * 128 + c];
                p0 += x * wb3s[c];
                p1 += x * wb3s[128 + c];
                p2 += x * wb3s[256 + c];
                p3 += x * wb3s[384 + c];
            }
#pragma unroll
            for (int off = 16; off; off >>= 1) {
                p0 += __shfl_xor_sync(0xffffffffu, p0, off);
                p1 += __shfl_xor_sync(0xffffffffu, p1, off);
                p2 += __shfl_xor_sync(0xffffffffu, p2, off);
                p3 += __shfl_xor_sync(0xffffffffu, p3, off);
            }
            if (lane < 4) {
                const float p = (lane == 0) ? p0 : (lane == 1) ? p1 : (lane == 2) ? p2 : p3;
                const float l = (p + bb3[lane]) * 0.17677669529663687f;
                const float ex = expf(l);
                atts[rr * 4 + lane] = ex;
                const int c = eidx[e];
                if (lane == 0) cens[rr] = c;
                atomicAdd(&gsum[c * 4 + lane], ex);
            }
        }
    }
    __syncthreads();

    // ================= P4: v1 = gelu(hE @ Wv1 + bv1) =================
    float acc3[2][4][4];
#pragma unroll
    for (int i = 0; i < 2; i++)
#pragma unroll
        for (int j = 0; j < 4; j++)
#pragma unroll
            for (int q = 0; q < 4; q++) acc3[i][j][q] = 0.f;
    run_phase<4>(acc3,
        [&](int kc, uint32_t& aHi, uint32_t& aLo) {
            aHi = heHi + kc * 16384; aLo = heLo + kc * 16384;
        },
        wv1h, wv1l, 256, 4, stg, stg + 16384, tid);
    store_planes512<4, 2>(acc3, smem, 131072, 131072 + 32768, bv1, tid);  // v1 -> xv
    __syncthreads();

    // ================= P5: v2 = gelu(v1 @ Wv2 + bv2) =================
    float acc4[2][4][4];
#pragma unroll
    for (int i = 0; i < 2; i++)
#pragma unroll
        for (int j = 0; j < 4; j++)
#pragma unroll
            for (int q = 0; q < 4; q++) acc4[i][j][q] = 0.f;
    run_phase<4>(acc4,
        [&](int kc, uint32_t& aHi, uint32_t& aLo) {
            aHi = xv + kc * 16384; aLo = xv + 32768 + kc * 16384;
        },
        wv2h, wv2l, 128, 2, stg, stg + 16384, tid);
    store_planes512<4, 2>(acc4, smem, 0, 32768, bv2, tid);  // v2 -> hE region (dead)
    __syncthreads();

    // ================= P6: V = v2 @ Wv3 + bv3; hagg[center] += e * V =================
    float acc5[2][4][4];
#pragma unroll
    for (int i = 0; i < 2; i++)
#pragma unroll
        for (int j = 0; j < 4; j++)
#pragma unroll
            for (int q = 0; q < 4; q++) acc5[i][j][q] = 0.f;
    run_phase<4>(acc5,
        [&](int kc, uint32_t& aHi, uint32_t& aLo) {
            aHi = heHi + kc * 16384; aLo = heHi + 32768 + kc * 16384;
        },
        wv3h, wv3l, 128, 2, stg, stg + 16384, tid);
    {
        const float* atts = (const float*)(smem + ATT_OFF);
        const int* cens = (const int*)(smem + CEN_OFF);
        const int wm = wid >> 2, wn = wid & 3;
#pragma unroll
        for (int mt = 0; mt < 2; mt++) {
#pragma unroll
            for (int nt = 0; nt < 4; nt++) {
                const int c = wn * 32 + nt * 8 + (lane & 3) * 2;
                const int h = c >> 5;
                const float b0 = bv3[c], b1 = bv3[c + 1];
#pragma unroll
                for (int half = 0; half < 2; half++) {
                    const int rl = wm * 32 + mt * 16 + (lane >> 2) + half * 8;
                    if (row0 + rl < M) {
                        const float a = atts[rl * 4 + h];
                        float* dst = hagg + (size_t)cens[rl] * 128 + c;
                        red2(dst, (acc5[mt][nt][half * 2] + b0) * a,
                                  (acc5[mt][nt][half * 2 + 1] + b1) * a);
                    }
                }
            }
        }
    }
}

// ---------------- standalone GEMM (W_O), 256 threads ----------------
__device__ __forceinline__ void ldsm_mma8(float (&acc)[2][8][4], uint32_t aB, uint32_t bB, int tid)
{
    const int wid = tid >> 5, lane = tid & 31;
    const int wm = wid >> 1, wn = wid & 1;
    const int a_row = wm * 32 + (lane & 7) + ((lane & 8) ? 8 : 0);
    const int a_ub  = (lane & 16) ? 1 : 0;
    const int b_row0 = wn * 64 + (lane & 7) + ((lane & 16) ? 8 : 0);
    const int b_ub  = (lane & 8) ? 1 : 0;
#pragma unroll
    for (int ks = 0; ks < 4; ks++) {
        uint32_t ahi[2][4], alo[2][4];
#pragma unroll
        for (int mt = 0; mt < 2; mt++) {
            const int r = a_row + mt * 16;
            const int u = ks * 2 + a_ub;
            const uint32_t off = r * 128 + (uint32_t)(((u ^ (r & 7))) << 4);
            ldsm4(ahi[mt], aB + off);
            ldsm4(alo[mt], aB + 16384 + off);
        }
        uint32_t bhi[4][4], blo[4][4];
#pragma unroll
        for (int g = 0; g < 4; g++) {
            const int n = b_row0 + g * 16;
            const int u = ks * 2 + b_ub;
            const uint32_t off = n * 128 + (uint32_t)(((u ^ (n & 7))) << 4);
            ldsm4(bhi[g], bB + off);
            ldsm4(blo[g], bB + 16384 + off);
        }
#pragma unroll
        for (int mt = 0; mt < 2; mt++)
#pragma unroll
            for (int ntl = 0; ntl < 8; ntl++) {
                float* a_ = acc[mt][ntl];
                const uint32_t* bh = &bhi[ntl >> 1][(ntl & 1) * 2];
                const uint32_t* bl = &blo[ntl >> 1][(ntl & 1) * 2];
                mma16816(a_, ahi[mt], bh);
                mma16816(a_, ahi[mt], bl);
                mma16816(a_, alo[mt], bh);
            }
    }
}

__global__ __launch_bounds__(256, 1)
void hmma_gemm_o(const bf16* __restrict__ Ahi, const bf16* __restrict__ Alo,
                 const bf16* __restrict__ Bhi, const bf16* __restrict__ Blo,
                 float* __restrict__ Cf, int M)
{
    extern __shared__ char smem[];
    const uint32_t sb = smem_u32(smem);
    const int tid = threadIdx.x;
    const int wid = tid >> 5, lane = tid & 31;
    const int row0 = blockIdx.x * 128;

    const int lr = tid >> 1;
    const int arow = (row0 + lr < M) ? (row0 + lr) : (M - 1);

    float acc[2][8][4];
#pragma unroll
    for (int i = 0; i < 2; i++)
#pragma unroll
        for (int j = 0; j < 8; j++)
#pragma unroll
            for (int q = 0; q < 4; q++) acc[i][j][q] = 0.f;

    for (int kc = 0; kc < 2; kc++) {
        const int k0 = kc * 64;
#pragma unroll
        for (int i = 0; i < 4; i++) {
            const int u = (tid & 1) * 4 + i;
            const uint32_t d = lr * 128 + (uint32_t)(((u ^ (lr & 7))) << 4);
            cp16(sb + d,         (const char*)(Ahi + (size_t)arow * 128 + k0) + u * 16);
            cp16(sb + 16384 + d, (const char*)(Alo + (size_t)arow * 128 + k0) + u * 16);
        }
        for (int i = tid; i < 128 * 8; i += 256) {
            const int r = i >> 3, u = i & 7;
            const uint32_t d = r * 128 + (uint32_t)(((u ^ (r & 7))) << 4);
            cp16(sb + 32768 + d, (const char*)(Bhi + (size_t)r * 128 + k0) + u * 16);
            cp16(sb + 49152 + d, (const char*)(Blo + (size_t)r * 128 + k0) + u * 16);
        }
        CP_COMMIT();
        CP_WAIT(0);
        __syncthreads();
        ldsm_mma8(acc, sb, sb + 32768, tid);
        __syncthreads();
    }

    const int wm = wid >> 1, wn = wid & 1;
#pragma unroll
    for (int mt = 0; mt < 2; mt++) {
        const int r = row0 + wm * 32 + mt * 16 + (lane >> 2);
#pragma unroll
        for (int nt = 0; nt < 8; nt++) {
            const int c = wn * 64 + nt * 8 + (lane & 3) * 2;
#pragma unroll
            for (int half = 0; half < 2; half++) {
                const int rr = r + half * 8;
                if (rr >= M) continue;
                *(float2*)(Cf + (size_t)rr * 128 + c) =
                    make_float2(acc[mt][nt][half * 2], acc[mt][nt][half * 2 + 1]);
            }
        }
    }
}

// ---------------- host launch ----------------
extern "C" void kernel_launch(void* const* d_in, const int* in_sizes, int n_in,
                              void* d_out, int out_size)
{
    const float* h_V   = (const float*)d_in[0];
    const float* h_E   = (const float*)d_in[1];
    const int*   eidx  = (const int*)  d_in[2];
    const float* hvv   = (const float*)d_in[3];
    const float* frame = (const float*)d_in[4];
    const float* W_vec = (const float*)d_in[5];
    const float* W_red = (const float*)d_in[6];
    const float* Wb1   = (const float*)d_in[7];
    const float* bb1   = (const float*)d_in[8];
    const float* Wb2   = (const float*)d_in[9];
    const float* bb2   = (const float*)d_in[10];
    const float* Wb3   = (const float*)d_in[11];
    const float* bb3   = (const float*)d_in[12];
    const float* Wv1   = (const float*)d_in[13];
    const float* bv1   = (const float*)d_in[14];
    const float* Wv2   = (const float*)d_in[15];
    const float* bv2   = (const float*)d_in[16];
    const float* Wv3   = (const float*)d_in[17];
    const float* bv3   = (const float*)d_in[18];
    const float* W_O   = (const float*)d_in[19];
    const float* bn_g  = (const float*)d_in[20];
    const float* bn_b  = (const float*)d_in[21];

    int E = in_sizes[2] / 2;
    int N = in_sizes[0] / 128;
    float* out = (float*)d_out;

    float *vff, *gsum, *hagg, *bnst;
    bf16 *hVh, *hVl, *hgh, *hgl, *wh, *wl;
    double* bnacc;
    cudaGetSymbolAddress((void**)&vff,   g_vff);
    cudaGetSymbolAddress((void**)&hVh,   g_hVh);
    cudaGetSymbolAddress((void**)&hVl,   g_hVl);
    cudaGetSymbolAddress((void**)&hgh,   g_hgh);
    cudaGetSymbolAddress((void**)&hgl,   g_hgl);
    cudaGetSymbolAddress((void**)&wh,    g_wh);
    cudaGetSymbolAddress((void**)&wl,    g_wl);
    cudaGetSymbolAddress((void**)&gsum,  g_sum);
    cudaGetSymbolAddress((void**)&hagg,  g_hagg);
    cudaGetSymbolAddress((void**)&bnacc, g_bnacc);
    cudaGetSymbolAddress((void**)&bnst,  g_bnst);

    const int SMEM_O = 65536;
    cudaFuncSetAttribute(mega_kernel, cudaFuncAttributeMaxDynamicSharedMemorySize, SMEM_MEGA);
    cudaFuncSetAttribute(hmma_gemm_o, cudaFuncAttributeMaxDynamicSharedMemorySize, SMEM_O);

    int Mt = (E + 127) / 128;
    int Mo = (N + 127) / 128;

    init_kernel<<<(N * 128 + 255) / 256, 256>>>(gsum, hagg, bnacc, N);
    geom_kernel<<<(E + 255) / 256, 256>>>(eidx, hvv, frame, W_vec, vff, bnacc, E);
    bn_finalize<<<1, 32>>>(bnacc, bn_g, bn_b, bnst, E);

    wprep_all<<<(W_TOTAL + 255) / 256, 256>>>(W_red, Wb1, Wb2, Wv1, Wv2, Wv3, W_O, wh, wl);
    c2planes<<<(N * 128 + 255) / 256, 256>>>(h_V, hVh, hVl, (size_t)N * 128);

    mega_kernel<<<Mt, 512, SMEM_MEGA>>>(
        vff, h_E, bnst, hVh, hVl, eidx,
        wh + OW_RED, wl + OW_RED,
        wh + OW_B1, wl + OW_B1, bb1,
        wh + OW_B2, wl + OW_B2, bb2,
        Wb3, bb3,
        wh + OW_V1, wl + OW_V1, bv1,
        wh + OW_V2, wl + OW_V2, bv2,
        wh + OW_V3, wl + OW_V3, bv3,
        gsum, hagg, E);

    // hagg normalized by segment sums -> planes, then out = hagg @ W_O
    c2planes_norm<<<(N * 128 + 255) / 256, 256>>>(hagg, gsum, hgh, hgl, N);
    hmma_gemm_o<<<Mo, 256, SMEM_O>>>(hgh, hgl, wh + OW_O, wl + OW_O, out, N);
}